// round 5
// baseline (speedup 1.0000x reference)
#include <cuda_runtime.h>
#include <cuda_bf16.h>
#include <math.h>

#define DIMN  1024
#define NH    16
#define HD    64
#define BATCH 2
#define SEQ   2048
#define MROWS (BATCH*SEQ)   // 4096

// ---------------- scratch (device globals; no allocations allowed) ----------
__device__ float g_qlin[MROWS*DIMN];
__device__ float g_klin[MROWS*DIMN];

__device__ __nv_bfloat16 g_xhi[MROWS*DIMN];
__device__ __nv_bfloat16 g_xlo[MROWS*DIMN];
__device__ __nv_bfloat16 g_ohi[MROWS*DIMN];
__device__ __nv_bfloat16 g_olo[MROWS*DIMN];
__device__ __nv_bfloat16 g_whi[4][DIMN*DIMN];
__device__ __nv_bfloat16 g_wlo[4][DIMN*DIMN];

// attention operands, [B,H,S,hd], bf16 hi/lo
__device__ __nv_bfloat16 g_qthi[MROWS*DIMN];
__device__ __nv_bfloat16 g_qtlo[MROWS*DIMN];
__device__ __nv_bfloat16 g_kthi[MROWS*DIMN];
__device__ __nv_bfloat16 g_ktlo[MROWS*DIMN];
__device__ __nv_bfloat16 g_vthi[MROWS*DIMN];
__device__ __nv_bfloat16 g_vtlo[MROWS*DIMN];

// ---------------- helpers ----------------------------------------------------
__device__ __forceinline__ unsigned int smem_u32(const void* p) {
    return (unsigned int)__cvta_generic_to_shared(p);
}
__device__ __forceinline__ void cp16(unsigned int s, const void* g) {
    asm volatile("cp.async.cg.shared.global [%0], [%1], 16;\n" :: "r"(s), "l"(g));
}
__device__ __forceinline__ void cp_commit() {
    asm volatile("cp.async.commit_group;\n");
}
__device__ __forceinline__ void cp_wait1() {
    asm volatile("cp.async.wait_group 1;\n");
}
__device__ __forceinline__ void cp_wait2() {
    asm volatile("cp.async.wait_group 2;\n");
}
__device__ __forceinline__ void cp_wait0() {
    asm volatile("cp.async.wait_group 0;\n");
}
__device__ __forceinline__ void ldmx4(unsigned int addr, unsigned int& r0, unsigned int& r1,
                                      unsigned int& r2, unsigned int& r3) {
    asm volatile("ldmatrix.sync.aligned.m8n8.x4.shared.b16 {%0,%1,%2,%3}, [%4];\n"
                 : "=r"(r0), "=r"(r1), "=r"(r2), "=r"(r3) : "r"(addr));
}
__device__ __forceinline__ void ldmx4t(unsigned int addr, unsigned int& r0, unsigned int& r1,
                                       unsigned int& r2, unsigned int& r3) {
    asm volatile("ldmatrix.sync.aligned.m8n8.x4.trans.shared.b16 {%0,%1,%2,%3}, [%4];\n"
                 : "=r"(r0), "=r"(r1), "=r"(r2), "=r"(r3) : "r"(addr));
}
__device__ __forceinline__ void mma16816(float* c, const unsigned int* a,
                                         unsigned int b0, unsigned int b1) {
    asm volatile("mma.sync.aligned.m16n8k16.row.col.f32.bf16.bf16.f32 "
                 "{%0,%1,%2,%3}, {%4,%5,%6,%7}, {%8,%9}, {%0,%1,%2,%3};\n"
                 : "+f"(c[0]), "+f"(c[1]), "+f"(c[2]), "+f"(c[3])
                 : "r"(a[0]), "r"(a[1]), "r"(a[2]), "r"(a[3]), "r"(b0), "r"(b1));
}
__device__ __forceinline__ unsigned short bfbits(float f) {
    __nv_bfloat16 h = __float2bfloat16(f);
    return *reinterpret_cast<unsigned short*>(&h);
}
__device__ __forceinline__ unsigned int pk2(float a, float b) {
    return (unsigned int)bfbits(a) | ((unsigned int)bfbits(b) << 16);
}
__device__ __forceinline__ float bf2f(unsigned short u) {
    __nv_bfloat16 h = *reinterpret_cast<__nv_bfloat16*>(&u);
    return __bfloat162float(h);
}

// ---------------- fp32 -> bf16 hi/lo split ----------------------------------
__global__ __launch_bounds__(256)
void f32_split(const float* __restrict__ src,
               __nv_bfloat16* __restrict__ hi,
               __nv_bfloat16* __restrict__ lo, int n4)
{
    int i = blockIdx.x * blockDim.x + threadIdx.x;
    if (i >= n4) return;
    float4 v = reinterpret_cast<const float4*>(src)[i];
    float f[4] = {v.x, v.y, v.z, v.w};
    unsigned short ph[4], pl[4];
#pragma unroll
    for (int j = 0; j < 4; j++) {
        ph[j] = bfbits(f[j]);
        pl[j] = bfbits(f[j] - bf2f(ph[j]));
    }
    reinterpret_cast<ushort4*>(hi)[i] = make_ushort4(ph[0], ph[1], ph[2], ph[3]);
    reinterpret_cast<ushort4*>(lo)[i] = make_ushort4(pl[0], pl[1], pl[2], pl[3]);
}

// ---------------- HMMA GEMM: C[M,N] = A[M,K] @ W[N,K]^T ----------------------
// CTA tile 128x256, 256 threads (8 warps, 2x4), warp tile 64x64.
// BK=32 (2 k16 substeps), 3-stage cp.async pipeline, split-bf16 (3 MMA terms).
// smem per stage (48KB): A planes [sub][him] 4x4KB at +0, B planes 4x8KB at +16K.
#define GST   49152
#define GKT   32      // K iterations (1024/32)

__device__ __forceinline__ void gemm_loads(const __nv_bfloat16* __restrict__ Ah,
                                           const __nv_bfloat16* __restrict__ Al,
                                           const __nv_bfloat16* __restrict__ Wh,
                                           const __nv_bfloat16* __restrict__ Wl,
                                           int row0, int col0, int kb,
                                           unsigned int stbase, int tid)
{
#pragma unroll
    for (int i = 0; i < 4; i++) {                 // A: 1024 chunks of 16B
        int id = tid + i * 256;
        int blk = id >> 8;                        // 0..3
        int sub = blk >> 1, him = blk & 1;
        int w = id & 255;
        int r = w >> 1, lch = w & 1;
        int pc = lch ^ ((r >> 2) & 1);
        unsigned int sa = stbase + (unsigned)(blk * 4096 + r * 32 + pc * 16);
        const __nv_bfloat16* src = him ? Al : Ah;
        cp16(sa, src + (size_t)(row0 + r) * DIMN + kb * 32 + sub * 16 + lch * 8);
    }
#pragma unroll
    for (int i = 0; i < 8; i++) {                 // B: 2048 chunks of 16B
        int id = tid + i * 256;
        int blk = id >> 9;                        // 0..3
        int sub = blk >> 1, him = blk & 1;
        int w = id & 511;
        int r = w >> 1, lch = w & 1;
        int pc = lch ^ ((r >> 2) & 1);
        unsigned int sa = stbase + (unsigned)(16384 + blk * 8192 + r * 32 + pc * 16);
        const __nv_bfloat16* src = him ? Wl : Wh;
        cp16(sa, src + (size_t)(col0 + r) * DIMN + kb * 32 + sub * 16 + lch * 8);
    }
}

__device__ __forceinline__ void gemm_body(const __nv_bfloat16* __restrict__ Ah,
                                          const __nv_bfloat16* __restrict__ Al,
                                          const __nv_bfloat16* __restrict__ Wh,
                                          const __nv_bfloat16* __restrict__ Wl,
                                          float* __restrict__ Cout, int vmode)
{
    extern __shared__ __align__(128) unsigned char gsm[];
    const unsigned int sb = smem_u32(gsm);
    const int tid = threadIdx.x, lane = tid & 31, warp = tid >> 5;
    const int wm = warp >> 2, wn = warp & 3;
    const int row0 = blockIdx.y * 128, col0 = blockIdx.x * 256;

    float acc[4][8][4];
#pragma unroll
    for (int i = 0; i < 4; i++)
#pragma unroll
        for (int j = 0; j < 8; j++)
#pragma unroll
            for (int k = 0; k < 4; k++) acc[i][j][k] = 0.0f;

    // ldmatrix base addresses (stage 0, sub 0, him 0)
    unsigned int aBase[4], bBase[4];
#pragma unroll
    for (int mt = 0; mt < 4; mt++) {
        int r  = wm * 64 + mt * 16 + (lane & 15);
        int ch = lane >> 4;
        int pc = ch ^ ((r >> 2) & 1);
        aBase[mt] = sb + r * 32 + pc * 16;
    }
#pragma unroll
    for (int p = 0; p < 4; p++) {
        int grp = lane >> 3;
        int r   = wn * 64 + p * 16 + (grp >> 1) * 8 + (lane & 7);
        int ch  = grp & 1;
        int pc  = ch ^ ((r >> 2) & 1);
        bBase[p] = sb + 16384 + r * 32 + pc * 16;
    }

    // prologue: stages 0,1
    gemm_loads(Ah, Al, Wh, Wl, row0, col0, 0, sb, tid);
    cp_commit();
    gemm_loads(Ah, Al, Wh, Wl, row0, col0, 1, sb + GST, tid);
    cp_commit();

    int s3 = 0;                 // stage of iteration c
    int l3 = 2;                 // stage for load of c+2
    for (int c = 0; c < GKT; c++) {
        __syncthreads();        // all warps done reading buffer l3's old data
        if (c + 2 < GKT)
            gemm_loads(Ah, Al, Wh, Wl, row0, col0, c + 2, sb + l3 * GST, tid);
        cp_commit();
        cp_wait2();
        __syncthreads();

        const unsigned int stoff = (unsigned)(s3 * GST);
#pragma unroll
        for (int sub = 0; sub < 2; sub++) {
            const unsigned int ao = stoff + sub * 8192;
            const unsigned int bo = stoff + sub * 16384;
            unsigned int ah[4][4], al[4][4], bh[4][4], bl[4][4];
#pragma unroll
            for (int mt = 0; mt < 4; mt++) {
                ldmx4(aBase[mt] + ao,        ah[mt][0], ah[mt][1], ah[mt][2], ah[mt][3]);
                ldmx4(aBase[mt] + ao + 4096, al[mt][0], al[mt][1], al[mt][2], al[mt][3]);
            }
#pragma unroll
            for (int p = 0; p < 4; p++) {
                ldmx4(bBase[p] + bo,        bh[p][0], bh[p][1], bh[p][2], bh[p][3]);
                ldmx4(bBase[p] + bo + 8192, bl[p][0], bl[p][1], bl[p][2], bl[p][3]);
            }
#pragma unroll
            for (int mt = 0; mt < 4; mt++) {
#pragma unroll
                for (int nt = 0; nt < 8; nt++) {
                    int p = nt >> 1, s = nt & 1;
                    mma16816(acc[mt][nt], ah[mt], bh[p][2*s], bh[p][2*s+1]);
                    mma16816(acc[mt][nt], ah[mt], bl[p][2*s], bl[p][2*s+1]);
                    mma16816(acc[mt][nt], al[mt], bh[p][2*s], bh[p][2*s+1]);
                }
            }
        }
        s3 = (s3 == 2) ? 0 : s3 + 1;
        l3 = (l3 == 2) ? 0 : l3 + 1;
    }

    // epilogue
    if (!vmode) {
#pragma unroll
        for (int mt = 0; mt < 4; mt++) {
            int r = row0 + wm * 64 + mt * 16 + (lane >> 2);
#pragma unroll
            for (int nt = 0; nt < 8; nt++) {
                int c = col0 + wn * 64 + nt * 8 + (lane & 3) * 2;
                *reinterpret_cast<float2*>(&Cout[(size_t)r * DIMN + c]) =
                    make_float2(acc[mt][nt][0], acc[mt][nt][1]);
                *reinterpret_cast<float2*>(&Cout[(size_t)(r + 8) * DIMN + c]) =
                    make_float2(acc[mt][nt][2], acc[mt][nt][3]);
            }
        }
    } else {
        // V: split to bf16 hi/lo, scatter transposed into [B,H,S,hd]
#pragma unroll
        for (int mt = 0; mt < 4; mt++) {
            int r = row0 + wm * 64 + mt * 16 + (lane >> 2);
#pragma unroll
            for (int nt = 0; nt < 8; nt++) {
                int c = col0 + wn * 64 + nt * 8 + (lane & 3) * 2;
#pragma unroll
                for (int e = 0; e < 4; e++) {
                    int rr = r + (e >> 1) * 8;
                    int cc = c + (e & 1);
                    int b = rr >> 11, s = rr & (SEQ-1);
                    int h = cc >> 6,  d = cc & (HD-1);
                    size_t di = (((size_t)(b*NH + h))*SEQ + s)*HD + d;
                    float v = acc[mt][nt][e];
                    unsigned short hb = bfbits(v);
                    unsigned short lb = bfbits(v - bf2f(hb));
                    reinterpret_cast<unsigned short*>(g_vthi)[di] = hb;
                    reinterpret_cast<unsigned short*>(g_vtlo)[di] = lb;
                }
            }
        }
    }
}

__global__ __launch_bounds__(256)
void qkv_gemm_mma(const __nv_bfloat16* __restrict__ xhi,
                  const __nv_bfloat16* __restrict__ xlo)
{
    int z = blockIdx.z;
    if (z == 0)      gemm_body(xhi, xlo, g_whi[0], g_wlo[0], g_qlin, 0);
    else if (z == 1) gemm_body(xhi, xlo, g_whi[1], g_wlo[1], g_klin, 0);
    else             gemm_body(xhi, xlo, g_whi[2], g_wlo[2], nullptr, 1);
}

__global__ __launch_bounds__(256)
void out_gemm_mma(float* __restrict__ C)
{
    gemm_body(g_ohi, g_olo, g_whi[3], g_wlo[3], C, 0);
}

// ---------------- RoPE + transpose to [B,H,S,hd], emit bf16 hi/lo -----------
__global__ void rope_transpose()
{
    int idx = blockIdx.x * blockDim.x + threadIdx.x;
    if (idx >= BATCH*SEQ*NH*(HD/2)) return;
    int d2 = idx & 31;
    int h  = (idx >> 5) & (NH-1);
    int s  = (idx >> 9) & (SEQ-1);
    int b  = idx >> 20;

    // inv_freq = 10000^(-d2/32) = exp2(-d2 * log2(10000)/32)
    float inv = exp2f(-(float)d2 * (13.287712379549449f / 32.0f));
    float ang = (float)s * inv;
    float c  = cosf(ang);
    float sn = sinf(ang);

    size_t src = ((size_t)(b*SEQ + s))*DIMN + h*HD;
    size_t dst = (((size_t)(b*NH + h))*SEQ + s)*HD;

    float q1 = g_qlin[src + d2], q2 = g_qlin[src + d2 + 32];
    float k1 = g_klin[src + d2], k2 = g_klin[src + d2 + 32];
    float qa = q1*c - q2*sn, qb = q2*c + q1*sn;
    float ka = k1*c - k2*sn, kb = k2*c + k1*sn;

    unsigned short* qh = reinterpret_cast<unsigned short*>(g_qthi);
    unsigned short* qlp = reinterpret_cast<unsigned short*>(g_qtlo);
    unsigned short* kh = reinterpret_cast<unsigned short*>(g_kthi);
    unsigned short* klp = reinterpret_cast<unsigned short*>(g_ktlo);

    unsigned short t;
    t = bfbits(qa); qh[dst+d2] = t;      qlp[dst+d2]    = bfbits(qa - bf2f(t));
    t = bfbits(qb); qh[dst+d2+32] = t;   qlp[dst+d2+32] = bfbits(qb - bf2f(t));
    t = bfbits(ka); kh[dst+d2] = t;      klp[dst+d2]    = bfbits(ka - bf2f(t));
    t = bfbits(kb); kh[dst+d2+32] = t;   klp[dst+d2+32] = bfbits(kb - bf2f(t));
}

// ---------------- Flash attention (causal) on HMMA, split-bf16 --------------
#define FROWP 72

__device__ __forceinline__ int SKI(int st, int hm, int r) {
    return ((st*2 + hm)*64 + r) * FROWP;
}

__global__ __launch_bounds__(128)
void flash_attn_mma()
{
    const int iq = blockIdx.x, h = blockIdx.y, b = blockIdx.z;
    const int q0 = iq * 64;
    const int tid = threadIdx.x, lane = tid & 31, warp = tid >> 5;
    const float LOG2E = 1.4426950408889634f;

    extern __shared__ __align__(16) __nv_bfloat16 fsm[];
    __nv_bfloat16* sK = fsm;
    __nv_bfloat16* sV = fsm + 2*2*64*FROWP;

    const size_t bh = (size_t)(b*NH + h) * SEQ * HD;
    const __nv_bfloat16* Qh = g_qthi + bh + (size_t)q0*HD;
    const __nv_bfloat16* Ql = g_qtlo + bh + (size_t)q0*HD;
    const __nv_bfloat16* Kh = g_kthi + bh;
    const __nv_bfloat16* Kl = g_ktlo + bh;
    const __nv_bfloat16* Vh = g_vthi + bh;
    const __nv_bfloat16* Vl = g_vtlo + bh;

    const int lrow = tid >> 1;
    const int lc0  = (tid & 1) * 4;

#pragma unroll
    for (int cc = 0; cc < 4; cc++) {
        int col = (lc0 + cc) * 8;
        cp16(smem_u32(&sK[SKI(0,0,lrow) + col]), Qh + lrow*HD + col);
        cp16(smem_u32(&sK[SKI(0,1,lrow) + col]), Ql + lrow*HD + col);
    }
    cp_commit(); cp_wait0();
    __syncthreads();

    unsigned int qfh[4][4], qfl[4][4];
    {
        int r  = warp*16 + (lane & 15);
        int ch = (lane >> 4) * 8;
#pragma unroll
        for (int ks = 0; ks < 4; ks++) {
            ldmx4(smem_u32(&sK[SKI(0,0,r) + ch + ks*16]),
                  qfh[ks][0], qfh[ks][1], qfh[ks][2], qfh[ks][3]);
            ldmx4(smem_u32(&sK[SKI(0,1,r) + ch + ks*16]),
                  qfl[ks][0], qfl[ks][1], qfl[ks][2], qfl[ks][3]);
        }
    }
    __syncthreads();

    float oacc[8][4];
#pragma unroll
    for (int i = 0; i < 8; i++)
#pragma unroll
        for (int j = 0; j < 4; j++) oacc[i][j] = 0.0f;
    float m0 = -INFINITY, m1 = -INFINITY, l0 = 0.0f, l1 = 0.0f;

    const int nkv = iq + 1;

#pragma unroll
    for (int cc = 0; cc < 4; cc++) {
        int col = (lc0 + cc) * 8;
        cp16(smem_u32(&sK[SKI(0,0,lrow) + col]), Kh + lrow*HD + col);
        cp16(smem_u32(&sK[SKI(0,1,lrow) + col]), Kl + lrow*HD + col);
        cp16(smem_u32(&sV[SKI(0,0,lrow) + col]), Vh + lrow*HD + col);
        cp16(smem_u32(&sV[SKI(0,1,lrow) + col]), Vl + lrow*HD + col);
    }
    cp_commit();

    for (int t = 0; t < nkv; t++) {
        const int st = t & 1;
        if (t + 1 < nkv) {
            const int ns = (t + 1) & 1;
            const size_t go = (size_t)(t + 1) * 64 * HD;
#pragma unroll
            for (int cc = 0; cc < 4; cc++) {
                int col = (lc0 + cc) * 8;
                cp16(smem_u32(&sK[SKI(ns,0,lrow) + col]), Kh + go + lrow*HD + col);
                cp16(smem_u32(&sK[SKI(ns,1,lrow) + col]), Kl + go + lrow*HD + col);
                cp16(smem_u32(&sV[SKI(ns,0,lrow) + col]), Vh + go + lrow*HD + col);
                cp16(smem_u32(&sV[SKI(ns,1,lrow) + col]), Vl + go + lrow*HD + col);
            }
        }
        cp_commit();
        cp_wait1();
        __syncthreads();

        float sacc[8][4];
#pragma unroll
        for (int i = 0; i < 8; i++)
#pragma unroll
            for (int j = 0; j < 4; j++) sacc[i][j] = 0.0f;

        {
            const int grp = lane >> 3;
            const int rb  = (grp >> 1) * 8 + (lane & 7);
            const int cb  = (grp & 1) * 8;
#pragma unroll
            for (int ks = 0; ks < 4; ks++) {
#pragma unroll
                for (int p = 0; p < 4; p++) {
                    unsigned int kfh[4], kfl[4];
                    ldmx4(smem_u32(&sK[SKI(st,0,p*16+rb) + cb + ks*16]),
                          kfh[0], kfh[1], kfh[2], kfh[3]);
                    ldmx4(smem_u32(&sK[SKI(st,1,p*16+rb) + cb + ks*16]),
                          kfl[0], kfl[1], kfl[2], kfl[3]);
#pragma unroll
                    for (int s = 0; s < 2; s++) {
                        int nt = 2*p + s;
                        mma16816(sacc[nt], qfh[ks], kfh[2*s], kfh[2*s+1]);
                        mma16816(sacc[nt], qfh[ks], kfl[2*s], kfl[2*s+1]);
                        mma16816(sacc[nt], qfl[ks], kfh[2*s], kfh[2*s+1]);
                    }
                }
            }
        }

        const int quad = lane >> 2;
        const int cpair = (lane & 3) * 2;
        if (t == nkv - 1) {
            const int r0 = q0 + warp*16 + quad;
            const int kvb = t*64 + cpair;
#pragma unroll
            for (int nt = 0; nt < 8; nt++) {
#pragma unroll
                for (int j = 0; j < 2; j++) {
                    int kg = kvb + nt*8 + j;
                    sacc[nt][j]   = (kg > r0)     ? -INFINITY : sacc[nt][j]   * 0.125f;
                    sacc[nt][2+j] = (kg > r0 + 8) ? -INFINITY : sacc[nt][2+j] * 0.125f;
                }
            }
        } else {
#pragma unroll
            for (int nt = 0; nt < 8; nt++)
#pragma unroll
                for (int j = 0; j < 4; j++) sacc[nt][j] *= 0.125f;
        }

        float mx0 = -INFINITY, mx1 = -INFINITY;
#pragma unroll
        for (int nt = 0; nt < 8; nt++) {
            mx0 = fmaxf(mx0, fmaxf(sacc[nt][0], sacc[nt][1]));
            mx1 = fmaxf(mx1, fmaxf(sacc[nt][2], sacc[nt][3]));
        }
        mx0 = fmaxf(mx0, __shfl_xor_sync(0xffffffffu, mx0, 1));
        mx0 = fmaxf(mx0, __shfl_xor_sync(0xffffffffu, mx0, 2));
        mx1 = fmaxf(mx1, __shfl_xor_sync(0xffffffffu, mx1, 1));
        mx1 = fmaxf(mx1, __shfl_xor_sync(0xffffffffu, mx1, 2));

        float mn0 = fmaxf(m0, mx0), mn1 = fmaxf(m1, mx1);
        float a0 = exp2f((m0 - mn0) * LOG2E);
        float a1 = exp2f((m1 - mn1) * LOG2E);
        m0 = mn0; m1 = mn1;

        float s0 = 0.0f, s1 = 0.0f;
#pragma unroll
        for (int nt = 0; nt < 8; nt++) {
            float p0 = exp2f((sacc[nt][0] - mn0) * LOG2E);
            float p1 = exp2f((sacc[nt][1] - mn0) * LOG2E);
            float p2 = exp2f((sacc[nt][2] - mn1) * LOG2E);
            float p3 = exp2f((sacc[nt][3] - mn1) * LOG2E);
            sacc[nt][0] = p0; sacc[nt][1] = p1; sacc[nt][2] = p2; sacc[nt][3] = p3;
            s0 += p0 + p1; s1 += p2 + p3;
        }
        s0 += __shfl_xor_sync(0xffffffffu, s0, 1);
        s0 += __shfl_xor_sync(0xffffffffu, s0, 2);
        s1 += __shfl_xor_sync(0xffffffffu, s1, 1);
        s1 += __shfl_xor_sync(0xffffffffu, s1, 2);
        l0 = l0 * a0 + s0;
        l1 = l1 * a1 + s1;

#pragma unroll
        for (int nt = 0; nt < 8; nt++) {
            oacc[nt][0] *= a0; oacc[nt][1] *= a0;
            oacc[nt][2] *= a1; oacc[nt][3] *= a1;
        }

        unsigned int pfh[4][4], pfl[4][4];
#pragma unroll
        for (int ks = 0; ks < 4; ks++) {
#pragma unroll
            for (int half = 0; half < 2; half++) {
                float pa = sacc[2*ks][2*half],  pb = sacc[2*ks][2*half+1];
                float pc = sacc[2*ks+1][2*half], pd = sacc[2*ks+1][2*half+1];
                unsigned short ha = bfbits(pa), hb2 = bfbits(pb);
                unsigned short hc = bfbits(pc), hd2 = bfbits(pd);
                pfh[ks][half]   = (unsigned int)ha | ((unsigned int)hb2 << 16);
                pfh[ks][2+half] = (unsigned int)hc | ((unsigned int)hd2 << 16);
                pfl[ks][half]   = pk2(pa - bf2f(ha), pb - bf2f(hb2));
                pfl[ks][2+half] = pk2(pc - bf2f(hc), pd - bf2f(hd2));
            }
        }

        {
            const int g   = lane >> 3;
            const int kvr = (g & 1) * 8 + (lane & 7);
            const int dcb = (g >> 1) * 8;
#pragma unroll
            for (int dt = 0; dt < 4; dt++) {
#pragma unroll
                for (int ks = 0; ks < 4; ks++) {
                    unsigned int vfh[4], vfl[4];
                    ldmx4t(smem_u32(&sV[SKI(st,0,ks*16+kvr) + dt*16 + dcb]),
                           vfh[0], vfh[1], vfh[2], vfh[3]);
                    ldmx4t(smem_u32(&sV[SKI(st,1,ks*16+kvr) + dt*16 + dcb]),
                           vfl[0], vfl[1], vfl[2], vfl[3]);
#pragma unroll
                    for (int s = 0; s < 2; s++) {
                        int nt = 2*dt + s;
                        mma16816(oacc[nt], pfh[ks], vfh[2*s], vfh[2*s+1]);
                        mma16816(oacc[nt], pfh[ks], vfl[2*s], vfl[2*s+1]);
                        mma16816(oacc[nt], pfl[ks], vfh[2*s], vfh[2*s+1]);
                    }
                }
            }
        }
        __syncthreads();
    }

    {
        const int quad = lane >> 2;
        const int cpair = (lane & 3) * 2;
        float il0 = 1.0f / l0, il1 = 1.0f / l1;
        int r0 = q0 + warp*16 + quad;
        unsigned short* OH = reinterpret_cast<unsigned short*>(g_ohi);
        unsigned short* OL = reinterpret_cast<unsigned short*>(g_olo);
#pragma unroll
        for (int nt = 0; nt < 8; nt++) {
            int d = nt*8 + cpair;
            size_t i0 = ((size_t)(b*SEQ) + r0)     * DIMN + h*HD + d;
            size_t i1 = ((size_t)(b*SEQ) + r0 + 8) * DIMN + h*HD + d;
            float v0 = oacc[nt][0]*il0, v1 = oacc[nt][1]*il0;
            float v2 = oacc[nt][2]*il1, v3 = oacc[nt][3]*il1;
            unsigned short h0 = bfbits(v0), h1 = bfbits(v1);
            unsigned short h2 = bfbits(v2), h3 = bfbits(v3);
            *reinterpret_cast<unsigned int*>(&OH[i0]) = (unsigned)h0 | ((unsigned)h1 << 16);
            *reinterpret_cast<unsigned int*>(&OH[i1]) = (unsigned)h2 | ((unsigned)h3 << 16);
            *reinterpret_cast<unsigned int*>(&OL[i0]) =
                (unsigned)bfbits(v0 - bf2f(h0)) | ((unsigned)bfbits(v1 - bf2f(h1)) << 16);
            *reinterpret_cast<unsigned int*>(&OL[i1]) =
                (unsigned)bfbits(v2 - bf2f(h2)) | ((unsigned)bfbits(v3 - bf2f(h3)) << 16);
        }
    }
}

// ---------------- launch ----------------------------------------------------
extern "C" void kernel_launch(void* const* d_in, const int* in_sizes, int n_in,
                              void* d_out, int out_size)
{
    const float* x  = (const float*)d_in[0];
    const float* Wq = (const float*)d_in[1];
    const float* Wk = (const float*)d_in[2];
    const float* Wv = (const float*)d_in[3];
    const float* Wo = (const float*)d_in[4];
    float* out = (float*)d_out;

    __nv_bfloat16 *xhi, *xlo, *whi, *wlo;
    cudaGetSymbolAddress((void**)&xhi, g_xhi);
    cudaGetSymbolAddress((void**)&xlo, g_xlo);
    cudaGetSymbolAddress((void**)&whi, g_whi);
    cudaGetSymbolAddress((void**)&wlo, g_wlo);

    const int NW = DIMN * DIMN;
    const int NX = MROWS * DIMN;

    f32_split<<<(NX/4 + 255)/256, 256>>>(x,  xhi, xlo, NX/4);
    f32_split<<<(NW/4 + 255)/256, 256>>>(Wq, whi + 0*(size_t)NW, wlo + 0*(size_t)NW, NW/4);
    f32_split<<<(NW/4 + 255)/256, 256>>>(Wk, whi + 1*(size_t)NW, wlo + 1*(size_t)NW, NW/4);
    f32_split<<<(NW/4 + 255)/256, 256>>>(Wv, whi + 2*(size_t)NW, wlo + 2*(size_t)NW, NW/4);
    f32_split<<<(NW/4 + 255)/256, 256>>>(Wo, whi + 3*(size_t)NW, wlo + 3*(size_t)NW, NW/4);

    const int GSM_BYTES = 3 * GST;   // 147456
    cudaFuncSetAttribute(qkv_gemm_mma, cudaFuncAttributeMaxDynamicSharedMemorySize, GSM_BYTES);
    cudaFuncSetAttribute(out_gemm_mma, cudaFuncAttributeMaxDynamicSharedMemorySize, GSM_BYTES);

    dim3 gqkv(DIMN/256, MROWS/128, 3);
    qkv_gemm_mma<<<gqkv, 256, GSM_BYTES>>>(xhi, xlo);

    int nrope = BATCH*SEQ*NH*(HD/2);
    rope_transpose<<<(nrope + 255)/256, 256>>>();

    const int FSM_BYTES = 2 * (2*2*64*FROWP) * (int)sizeof(__nv_bfloat16);
    cudaFuncSetAttribute(flash_attn_mma, cudaFuncAttributeMaxDynamicSharedMemorySize, FSM_BYTES);
    dim3 gfl(SEQ/64, NH, BATCH);
    flash_attn_mma<<<gfl, 128, FSM_BYTES>>>();

    dim3 gout(DIMN/256, MROWS/128);
    out_gemm_mma<<<gout, 256, GSM_BYTES>>>(out);
}

// round 6
// speedup vs baseline: 1.1856x; 1.1856x over previous
#include <cuda_runtime.h>
#include <cuda_bf16.h>
#include <cuda_fp16.h>
#include <math.h>

#define DIMN  1024
#define NH    16
#define HD    64
#define BATCH 2
#define SEQ   2048
#define MROWS (BATCH*SEQ)   // 4096

// ---------------- scratch (device globals; no allocations allowed) ----------
__device__ float g_qlin[MROWS*DIMN];
__device__ float g_klin[MROWS*DIMN];

__device__ __nv_bfloat16 g_xhi[MROWS*DIMN];
__device__ __nv_bfloat16 g_xlo[MROWS*DIMN];
__device__ __nv_bfloat16 g_ohi[MROWS*DIMN];
__device__ __nv_bfloat16 g_olo[MROWS*DIMN];
__device__ __nv_bfloat16 g_whi[4][DIMN*DIMN];
__device__ __nv_bfloat16 g_wlo[4][DIMN*DIMN];

// attention operands, [B,H,S,hd]
__device__ __nv_bfloat16 g_qthi[MROWS*DIMN];
__device__ __nv_bfloat16 g_qtlo[MROWS*DIMN];
__device__ __nv_bfloat16 g_kthi[MROWS*DIMN];
__device__ __nv_bfloat16 g_ktlo[MROWS*DIMN];
__device__ __half        g_v16 [MROWS*DIMN];   // V single fp16 plane

// ---------------- helpers ----------------------------------------------------
__device__ __forceinline__ unsigned int smem_u32(const void* p) {
    return (unsigned int)__cvta_generic_to_shared(p);
}
__device__ __forceinline__ void cp16(unsigned int s, const void* g) {
    asm volatile("cp.async.cg.shared.global [%0], [%1], 16;\n" :: "r"(s), "l"(g));
}
__device__ __forceinline__ void cp_commit() {
    asm volatile("cp.async.commit_group;\n");
}
__device__ __forceinline__ void cp_wait1() {
    asm volatile("cp.async.wait_group 1;\n");
}
__device__ __forceinline__ void cp_wait0() {
    asm volatile("cp.async.wait_group 0;\n");
}
__device__ __forceinline__ void ldmx4(unsigned int addr, unsigned int& r0, unsigned int& r1,
                                      unsigned int& r2, unsigned int& r3) {
    asm volatile("ldmatrix.sync.aligned.m8n8.x4.shared.b16 {%0,%1,%2,%3}, [%4];\n"
                 : "=r"(r0), "=r"(r1), "=r"(r2), "=r"(r3) : "r"(addr));
}
__device__ __forceinline__ void ldmx4t(unsigned int addr, unsigned int& r0, unsigned int& r1,
                                       unsigned int& r2, unsigned int& r3) {
    asm volatile("ldmatrix.sync.aligned.m8n8.x4.trans.shared.b16 {%0,%1,%2,%3}, [%4];\n"
                 : "=r"(r0), "=r"(r1), "=r"(r2), "=r"(r3) : "r"(addr));
}
__device__ __forceinline__ void mma16816(float* c, const unsigned int* a,
                                         unsigned int b0, unsigned int b1) {
    asm volatile("mma.sync.aligned.m16n8k16.row.col.f32.bf16.bf16.f32 "
                 "{%0,%1,%2,%3}, {%4,%5,%6,%7}, {%8,%9}, {%0,%1,%2,%3};\n"
                 : "+f"(c[0]), "+f"(c[1]), "+f"(c[2]), "+f"(c[3])
                 : "r"(a[0]), "r"(a[1]), "r"(a[2]), "r"(a[3]), "r"(b0), "r"(b1));
}
__device__ __forceinline__ void mma16816h(float* c, const unsigned int* a,
                                          unsigned int b0, unsigned int b1) {
    asm volatile("mma.sync.aligned.m16n8k16.row.col.f32.f16.f16.f32 "
                 "{%0,%1,%2,%3}, {%4,%5,%6,%7}, {%8,%9}, {%0,%1,%2,%3};\n"
                 : "+f"(c[0]), "+f"(c[1]), "+f"(c[2]), "+f"(c[3])
                 : "r"(a[0]), "r"(a[1]), "r"(a[2]), "r"(a[3]), "r"(b0), "r"(b1));
}
__device__ __forceinline__ unsigned short bfbits(float f) {
    __nv_bfloat16 h = __float2bfloat16(f);
    return *reinterpret_cast<unsigned short*>(&h);
}
__device__ __forceinline__ unsigned short hfbits(float f) {
    __half h = __float2half_rn(f);
    return *reinterpret_cast<unsigned short*>(&h);
}
__device__ __forceinline__ unsigned int pk2h(float a, float b) {
    return (unsigned int)hfbits(a) | ((unsigned int)hfbits(b) << 16);
}
__device__ __forceinline__ float bf2f(unsigned short u) {
    __nv_bfloat16 h = *reinterpret_cast<__nv_bfloat16*>(&u);
    return __bfloat162float(h);
}

// ---------------- fp32 -> bf16 hi/lo split ----------------------------------
__global__ __launch_bounds__(256)
void f32_split(const float* __restrict__ src,
               __nv_bfloat16* __restrict__ hi,
               __nv_bfloat16* __restrict__ lo, int n4)
{
    int i = blockIdx.x * blockDim.x + threadIdx.x;
    if (i >= n4) return;
    float4 v = reinterpret_cast<const float4*>(src)[i];
    float f[4] = {v.x, v.y, v.z, v.w};
    unsigned short ph[4], pl[4];
#pragma unroll
    for (int j = 0; j < 4; j++) {
        ph[j] = bfbits(f[j]);
        pl[j] = bfbits(f[j] - bf2f(ph[j]));
    }
    reinterpret_cast<ushort4*>(hi)[i] = make_ushort4(ph[0], ph[1], ph[2], ph[3]);
    reinterpret_cast<ushort4*>(lo)[i] = make_ushort4(pl[0], pl[1], pl[2], pl[3]);
}

// ---------------- HMMA GEMM (R3 config): C[M,N] = A[M,K] @ W[N,K]^T ----------
__device__ __forceinline__ void gemm_mma_body(const __nv_bfloat16* __restrict__ Ah,
                                              const __nv_bfloat16* __restrict__ Al,
                                              const __nv_bfloat16* __restrict__ Bh,
                                              const __nv_bfloat16* __restrict__ Bl,
                                              float* __restrict__ C, int vmode)
{
    __shared__ __align__(128) __nv_bfloat16 sA[2][2][128][16];
    __shared__ __align__(128) __nv_bfloat16 sB[2][2][128][16];

    const int tid   = threadIdx.x;
    const int lane  = tid & 31;
    const int warp  = tid >> 5;
    const int wm    = warp >> 2;
    const int wn    = warp & 3;
    const int row0  = blockIdx.y * 128;
    const int col0  = blockIdx.x * 128;

    const int lrow = tid >> 1;
    const int lch  = tid & 1;
    const int lpc  = lch ^ ((lrow >> 2) & 1);
    const size_t aoff = (size_t)(row0 + lrow) * DIMN + lch * 8;
    const size_t boff = (size_t)(col0 + lrow) * DIMN + lch * 8;

    float acc[4][4][4];
#pragma unroll
    for (int i = 0; i < 4; i++)
#pragma unroll
        for (int j = 0; j < 4; j++)
#pragma unroll
            for (int k = 0; k < 4; k++) acc[i][j][k] = 0.0f;

    const unsigned int stg = (unsigned int)(2 * 128 * 16 * sizeof(__nv_bfloat16));

    unsigned int aAddr[4][2], bAddr[2][2];
#pragma unroll
    for (int mt = 0; mt < 4; mt++) {
        int r  = wm * 64 + mt * 16 + (lane & 15);
        int ch = lane >> 4;
        int pc = ch ^ ((r >> 2) & 1);
        aAddr[mt][0] = smem_u32(&sA[0][0][r][pc * 8]);
        aAddr[mt][1] = smem_u32(&sA[0][1][r][pc * 8]);
    }
#pragma unroll
    for (int p = 0; p < 2; p++) {
        int grp = lane >> 3;
        int r   = wn * 32 + p * 16 + (grp >> 1) * 8 + (lane & 7);
        int ch  = grp & 1;
        int pc  = ch ^ ((r >> 2) & 1);
        bAddr[p][0] = smem_u32(&sB[0][0][r][pc * 8]);
        bAddr[p][1] = smem_u32(&sB[0][1][r][pc * 8]);
    }

    {
        unsigned int sa0 = smem_u32(&sA[0][0][lrow][lpc * 8]);
        unsigned int sa1 = smem_u32(&sA[0][1][lrow][lpc * 8]);
        unsigned int sb0 = smem_u32(&sB[0][0][lrow][lpc * 8]);
        unsigned int sb1 = smem_u32(&sB[0][1][lrow][lpc * 8]);
        cp16(sa0, Ah + aoff); cp16(sa1, Al + aoff);
        cp16(sb0, Bh + boff); cp16(sb1, Bl + boff);
        cp_commit();
    }

    const int KT = DIMN / 16;
    for (int kt = 0; kt < KT; kt++) {
        int cur = kt & 1;
        if (kt + 1 < KT) {
            int nxt = (kt + 1) & 1;
            size_t ko = (size_t)(kt + 1) * 16;
            unsigned int sa0 = smem_u32(&sA[nxt][0][lrow][lpc * 8]);
            unsigned int sa1 = smem_u32(&sA[nxt][1][lrow][lpc * 8]);
            unsigned int sb0 = smem_u32(&sB[nxt][0][lrow][lpc * 8]);
            unsigned int sb1 = smem_u32(&sB[nxt][1][lrow][lpc * 8]);
            cp16(sa0, Ah + aoff + ko); cp16(sa1, Al + aoff + ko);
            cp16(sb0, Bh + boff + ko); cp16(sb1, Bl + boff + ko);
        }
        cp_commit();
        cp_wait1();
        __syncthreads();

        unsigned int coff = cur * stg;
        unsigned int ah[4][4], al[4][4], bh[2][4], bl[2][4];
#pragma unroll
        for (int mt = 0; mt < 4; mt++) {
            ldmx4(aAddr[mt][0] + coff, ah[mt][0], ah[mt][1], ah[mt][2], ah[mt][3]);
            ldmx4(aAddr[mt][1] + coff, al[mt][0], al[mt][1], al[mt][2], al[mt][3]);
        }
#pragma unroll
        for (int p = 0; p < 2; p++) {
            ldmx4(bAddr[p][0] + coff, bh[p][0], bh[p][1], bh[p][2], bh[p][3]);
            ldmx4(bAddr[p][1] + coff, bl[p][0], bl[p][1], bl[p][2], bl[p][3]);
        }
#pragma unroll
        for (int mt = 0; mt < 4; mt++) {
#pragma unroll
            for (int nt = 0; nt < 4; nt++) {
                int p = nt >> 1, s = nt & 1;
                mma16816(acc[mt][nt], ah[mt], bh[p][2*s], bh[p][2*s+1]);
                mma16816(acc[mt][nt], ah[mt], bl[p][2*s], bl[p][2*s+1]);
                mma16816(acc[mt][nt], al[mt], bh[p][2*s], bh[p][2*s+1]);
            }
        }
        __syncthreads();
    }

    if (!vmode) {
#pragma unroll
        for (int mt = 0; mt < 4; mt++) {
            int r = row0 + wm * 64 + mt * 16 + (lane >> 2);
#pragma unroll
            for (int nt = 0; nt < 4; nt++) {
                int c = col0 + wn * 32 + nt * 8 + (lane & 3) * 2;
                *reinterpret_cast<float2*>(&C[(size_t)r * DIMN + c]) =
                    make_float2(acc[mt][nt][0], acc[mt][nt][1]);
                *reinterpret_cast<float2*>(&C[(size_t)(r + 8) * DIMN + c]) =
                    make_float2(acc[mt][nt][2], acc[mt][nt][3]);
            }
        }
    } else {
        // V: convert to fp16 single plane, scatter transposed into [B,H,S,hd]
#pragma unroll
        for (int mt = 0; mt < 4; mt++) {
            int r = row0 + wm * 64 + mt * 16 + (lane >> 2);
#pragma unroll
            for (int nt = 0; nt < 4; nt++) {
                int c = col0 + wn * 32 + nt * 8 + (lane & 3) * 2;
#pragma unroll
                for (int e = 0; e < 4; e++) {
                    int rr = r + (e >> 1) * 8;
                    int cc = c + (e & 1);
                    int b = rr >> 11, s = rr & (SEQ-1);
                    int h = cc >> 6,  d = cc & (HD-1);
                    size_t di = (((size_t)(b*NH + h))*SEQ + s)*HD + d;
                    reinterpret_cast<unsigned short*>(g_v16)[di] = hfbits(acc[mt][nt][e]);
                }
            }
        }
    }
}

__global__ __launch_bounds__(256)
void qkv_gemm_mma(const __nv_bfloat16* __restrict__ xhi,
                  const __nv_bfloat16* __restrict__ xlo)
{
    int z = blockIdx.z;
    if (z == 0)      gemm_mma_body(xhi, xlo, g_whi[0], g_wlo[0], g_qlin, 0);
    else if (z == 1) gemm_mma_body(xhi, xlo, g_whi[1], g_wlo[1], g_klin, 0);
    else             gemm_mma_body(xhi, xlo, g_whi[2], g_wlo[2], nullptr, 1);
}

__global__ __launch_bounds__(256)
void out_gemm_mma(float* __restrict__ C)
{
    gemm_mma_body(g_ohi, g_olo, g_whi[3], g_wlo[3], C, 0);
}

// ---------------- RoPE + transpose to [B,H,S,hd], emit bf16 hi/lo -----------
__global__ void rope_transpose()
{
    int idx = blockIdx.x * blockDim.x + threadIdx.x;
    if (idx >= BATCH*SEQ*NH*(HD/2)) return;
    int d2 = idx & 31;
    int h  = (idx >> 5) & (NH-1);
    int s  = (idx >> 9) & (SEQ-1);
    int b  = idx >> 20;

    float inv = exp2f(-(float)d2 * (13.287712379549449f / 32.0f));
    float ang = (float)s * inv;
    float c  = cosf(ang);
    float sn = sinf(ang);

    size_t src = ((size_t)(b*SEQ + s))*DIMN + h*HD;
    size_t dst = (((size_t)(b*NH + h))*SEQ + s)*HD;

    float q1 = g_qlin[src + d2], q2 = g_qlin[src + d2 + 32];
    float k1 = g_klin[src + d2], k2 = g_klin[src + d2 + 32];
    float qa = q1*c - q2*sn, qb = q2*c + q1*sn;
    float ka = k1*c - k2*sn, kb = k2*c + k1*sn;

    unsigned short* qh = reinterpret_cast<unsigned short*>(g_qthi);
    unsigned short* qlp = reinterpret_cast<unsigned short*>(g_qtlo);
    unsigned short* kh = reinterpret_cast<unsigned short*>(g_kthi);
    unsigned short* klp = reinterpret_cast<unsigned short*>(g_ktlo);

    unsigned short t;
    t = bfbits(qa); qh[dst+d2] = t;      qlp[dst+d2]    = bfbits(qa - bf2f(t));
    t = bfbits(qb); qh[dst+d2+32] = t;   qlp[dst+d2+32] = bfbits(qb - bf2f(t));
    t = bfbits(ka); kh[dst+d2] = t;      klp[dst+d2]    = bfbits(ka - bf2f(t));
    t = bfbits(kb); kh[dst+d2+32] = t;   klp[dst+d2+32] = bfbits(kb - bf2f(t));
}

// ---------------- Flash attention (causal): QK split-bf16, PV fp16 ----------
#define FROWP 72

__device__ __forceinline__ int SKI(int st, int hm, int r) {
    return ((st*2 + hm)*64 + r) * FROWP;
}
__device__ __forceinline__ int SVI(int st, int r) {
    return (st*64 + r) * FROWP;
}

__global__ __launch_bounds__(128)
void flash_attn_mma()
{
    const int iq = (int)gridDim.x - 1 - (int)blockIdx.x;   // heavy tiles first
    const int h = blockIdx.y, b = blockIdx.z;
    const int q0 = iq * 64;
    const int tid = threadIdx.x, lane = tid & 31, warp = tid >> 5;
    const float LOG2E = 1.4426950408889634f;

    extern __shared__ __align__(16) __nv_bfloat16 fsm[];
    __nv_bfloat16* sK = fsm;                           // 2 st x 2 planes x 64 x 72
    __half*        sV = reinterpret_cast<__half*>(fsm + 2*2*64*FROWP);  // 2 st x 64 x 72

    const size_t bh = (size_t)(b*NH + h) * SEQ * HD;
    const __nv_bfloat16* Qh = g_qthi + bh + (size_t)q0*HD;
    const __nv_bfloat16* Ql = g_qtlo + bh + (size_t)q0*HD;
    const __nv_bfloat16* Kh = g_kthi + bh;
    const __nv_bfloat16* Kl = g_ktlo + bh;
    const __half*        Vv = g_v16  + bh;

    const int lrow = tid >> 1;
    const int lc0  = (tid & 1) * 4;

    // stage Q through sK stage0
#pragma unroll
    for (int cc = 0; cc < 4; cc++) {
        int col = (lc0 + cc) * 8;
        cp16(smem_u32(&sK[SKI(0,0,lrow) + col]), Qh + lrow*HD + col);
        cp16(smem_u32(&sK[SKI(0,1,lrow) + col]), Ql + lrow*HD + col);
    }
    cp_commit(); cp_wait0();
    __syncthreads();

    unsigned int qfh[4][4], qfl[4][4];
    {
        int r  = warp*16 + (lane & 15);
        int ch = (lane >> 4) * 8;
#pragma unroll
        for (int ks = 0; ks < 4; ks++) {
            ldmx4(smem_u32(&sK[SKI(0,0,r) + ch + ks*16]),
                  qfh[ks][0], qfh[ks][1], qfh[ks][2], qfh[ks][3]);
            ldmx4(smem_u32(&sK[SKI(0,1,r) + ch + ks*16]),
                  qfl[ks][0], qfl[ks][1], qfl[ks][2], qfl[ks][3]);
        }
    }
    __syncthreads();

    float oacc[8][4];
#pragma unroll
    for (int i = 0; i < 8; i++)
#pragma unroll
        for (int j = 0; j < 4; j++) oacc[i][j] = 0.0f;
    float m0 = -INFINITY, m1 = -INFINITY, l0 = 0.0f, l1 = 0.0f;

    const int nkv = iq + 1;

    // prologue: tile 0 -> stage 0
#pragma unroll
    for (int cc = 0; cc < 4; cc++) {
        int col = (lc0 + cc) * 8;
        cp16(smem_u32(&sK[SKI(0,0,lrow) + col]), Kh + lrow*HD + col);
        cp16(smem_u32(&sK[SKI(0,1,lrow) + col]), Kl + lrow*HD + col);
        cp16(smem_u32(&sV[SVI(0,lrow) + col]),   Vv + lrow*HD + col);
    }
    cp_commit();

    for (int t = 0; t < nkv; t++) {
        const int st = t & 1;
        if (t + 1 < nkv) {
            const int ns = (t + 1) & 1;
            const size_t go = (size_t)(t + 1) * 64 * HD;
#pragma unroll
            for (int cc = 0; cc < 4; cc++) {
                int col = (lc0 + cc) * 8;
                cp16(smem_u32(&sK[SKI(ns,0,lrow) + col]), Kh + go + lrow*HD + col);
                cp16(smem_u32(&sK[SKI(ns,1,lrow) + col]), Kl + go + lrow*HD + col);
                cp16(smem_u32(&sV[SVI(ns,lrow) + col]),   Vv + go + lrow*HD + col);
            }
        }
        cp_commit();
        cp_wait1();
        __syncthreads();

        // S = Q K^T (split bf16, 3 terms)
        float sacc[8][4];
#pragma unroll
        for (int i = 0; i < 8; i++)
#pragma unroll
            for (int j = 0; j < 4; j++) sacc[i][j] = 0.0f;

        {
            const int grp = lane >> 3;
            const int rb  = (grp >> 1) * 8 + (lane & 7);
            const int cb  = (grp & 1) * 8;
#pragma unroll
            for (int ks = 0; ks < 4; ks++) {
#pragma unroll
                for (int p = 0; p < 4; p++) {
                    unsigned int kfh[4], kfl[4];
                    ldmx4(smem_u32(&sK[SKI(st,0,p*16+rb) + cb + ks*16]),
                          kfh[0], kfh[1], kfh[2], kfh[3]);
                    ldmx4(smem_u32(&sK[SKI(st,1,p*16+rb) + cb + ks*16]),
                          kfl[0], kfl[1], kfl[2], kfl[3]);
#pragma unroll
                    for (int s = 0; s < 2; s++) {
                        int nt = 2*p + s;
                        mma16816(sacc[nt], qfh[ks], kfh[2*s], kfh[2*s+1]);
                        mma16816(sacc[nt], qfh[ks], kfl[2*s], kfl[2*s+1]);
                        mma16816(sacc[nt], qfl[ks], kfh[2*s], kfh[2*s+1]);
                    }
                }
            }
        }

        const int quad = lane >> 2;
        const int cpair = (lane & 3) * 2;
        if (t == nkv - 1) {
            const int r0 = q0 + warp*16 + quad;
            const int kvb = t*64 + cpair;
#pragma unroll
            for (int nt = 0; nt < 8; nt++) {
#pragma unroll
                for (int j = 0; j < 2; j++) {
                    int kg = kvb + nt*8 + j;
                    sacc[nt][j]   = (kg > r0)     ? -INFINITY : sacc[nt][j]   * 0.125f;
                    sacc[nt][2+j] = (kg > r0 + 8) ? -INFINITY : sacc[nt][2+j] * 0.125f;
                }
            }
        } else {
#pragma unroll
            for (int nt = 0; nt < 8; nt++)
#pragma unroll
                for (int j = 0; j < 4; j++) sacc[nt][j] *= 0.125f;
        }

        // online softmax
        float mx0 = -INFINITY, mx1 = -INFINITY;
#pragma unroll
        for (int nt = 0; nt < 8; nt++) {
            mx0 = fmaxf(mx0, fmaxf(sacc[nt][0], sacc[nt][1]));
            mx1 = fmaxf(mx1, fmaxf(sacc[nt][2], sacc[nt][3]));
        }
        mx0 = fmaxf(mx0, __shfl_xor_sync(0xffffffffu, mx0, 1));
        mx0 = fmaxf(mx0, __shfl_xor_sync(0xffffffffu, mx0, 2));
        mx1 = fmaxf(mx1, __shfl_xor_sync(0xffffffffu, mx1, 1));
        mx1 = fmaxf(mx1, __shfl_xor_sync(0xffffffffu, mx1, 2));

        float mn0 = fmaxf(m0, mx0), mn1 = fmaxf(m1, mx1);
        float a0 = exp2f((m0 - mn0) * LOG2E);
        float a1 = exp2f((m1 - mn1) * LOG2E);
        m0 = mn0; m1 = mn1;

        float s0 = 0.0f, s1 = 0.0f;
#pragma unroll
        for (int nt = 0; nt < 8; nt++) {
            float p0 = exp2f((sacc[nt][0] - mn0) * LOG2E);
            float p1 = exp2f((sacc[nt][1] - mn0) * LOG2E);
            float p2 = exp2f((sacc[nt][2] - mn1) * LOG2E);
            float p3 = exp2f((sacc[nt][3] - mn1) * LOG2E);
            sacc[nt][0] = p0; sacc[nt][1] = p1; sacc[nt][2] = p2; sacc[nt][3] = p3;
            s0 += p0 + p1; s1 += p2 + p3;
        }
        s0 += __shfl_xor_sync(0xffffffffu, s0, 1);
        s0 += __shfl_xor_sync(0xffffffffu, s0, 2);
        s1 += __shfl_xor_sync(0xffffffffu, s1, 1);
        s1 += __shfl_xor_sync(0xffffffffu, s1, 2);
        l0 = l0 * a0 + s0;
        l1 = l1 * a1 + s1;

#pragma unroll
        for (int nt = 0; nt < 8; nt++) {
            oacc[nt][0] *= a0; oacc[nt][1] *= a0;
            oacc[nt][2] *= a1; oacc[nt][3] *= a1;
        }

        // pack P fragments (single fp16)
        unsigned int pf[4][4];
#pragma unroll
        for (int ks = 0; ks < 4; ks++) {
#pragma unroll
            for (int half = 0; half < 2; half++) {
                pf[ks][half]   = pk2h(sacc[2*ks][2*half],   sacc[2*ks][2*half+1]);
                pf[ks][2+half] = pk2h(sacc[2*ks+1][2*half], sacc[2*ks+1][2*half+1]);
            }
        }

        // O += P V (single fp16 term)
        {
            const int g   = lane >> 3;
            const int kvr = (g & 1) * 8 + (lane & 7);
            const int dcb = (g >> 1) * 8;
#pragma unroll
            for (int dt = 0; dt < 4; dt++) {
#pragma unroll
                for (int ks = 0; ks < 4; ks++) {
                    unsigned int vf[4];
                    ldmx4t(smem_u32(&sV[SVI(st,ks*16+kvr) + dt*16 + dcb]),
                           vf[0], vf[1], vf[2], vf[3]);
#pragma unroll
                    for (int s = 0; s < 2; s++) {
                        int nt = 2*dt + s;
                        mma16816h(oacc[nt], pf[ks], vf[2*s], vf[2*s+1]);
                    }
                }
            }
        }
        __syncthreads();
    }

    // epilogue: O/l -> g_ohi/g_olo at [B,S,D]
    {
        const int quad = lane >> 2;
        const int cpair = (lane & 3) * 2;
        float il0 = 1.0f / l0, il1 = 1.0f / l1;
        int r0 = q0 + warp*16 + quad;
        unsigned short* OH = reinterpret_cast<unsigned short*>(g_ohi);
        unsigned short* OL = reinterpret_cast<unsigned short*>(g_olo);
#pragma unroll
        for (int nt = 0; nt < 8; nt++) {
            int d = nt*8 + cpair;
            size_t i0 = ((size_t)(b*SEQ) + r0)     * DIMN + h*HD + d;
            size_t i1 = ((size_t)(b*SEQ) + r0 + 8) * DIMN + h*HD + d;
            float v0 = oacc[nt][0]*il0, v1 = oacc[nt][1]*il0;
            float v2 = oacc[nt][2]*il1, v3 = oacc[nt][3]*il1;
            unsigned short h0 = bfbits(v0), h1 = bfbits(v1);
            unsigned short h2 = bfbits(v2), h3 = bfbits(v3);
            *reinterpret_cast<unsigned int*>(&OH[i0]) = (unsigned)h0 | ((unsigned)h1 << 16);
            *reinterpret_cast<unsigned int*>(&OH[i1]) = (unsigned)h2 | ((unsigned)h3 << 16);
            *reinterpret_cast<unsigned int*>(&OL[i0]) =
                (unsigned)bfbits(v0 - bf2f(h0)) | ((unsigned)bfbits(v1 - bf2f(h1)) << 16);
            *reinterpret_cast<unsigned int*>(&OL[i1]) =
                (unsigned)bfbits(v2 - bf2f(h2)) | ((unsigned)bfbits(v3 - bf2f(h3)) << 16);
        }
    }
}

// ---------------- launch ----------------------------------------------------
extern "C" void kernel_launch(void* const* d_in, const int* in_sizes, int n_in,
                              void* d_out, int out_size)
{
    const float* x  = (const float*)d_in[0];
    const float* Wq = (const float*)d_in[1];
    const float* Wk = (const float*)d_in[2];
    const float* Wv = (const float*)d_in[3];
    const float* Wo = (const float*)d_in[4];
    float* out = (float*)d_out;

    __nv_bfloat16 *xhi, *xlo, *whi, *wlo;
    cudaGetSymbolAddress((void**)&xhi, g_xhi);
    cudaGetSymbolAddress((void**)&xlo, g_xlo);
    cudaGetSymbolAddress((void**)&whi, g_whi);
    cudaGetSymbolAddress((void**)&wlo, g_wlo);

    const int NW = DIMN * DIMN;
    const int NX = MROWS * DIMN;

    f32_split<<<(NX/4 + 255)/256, 256>>>(x,  xhi, xlo, NX/4);
    f32_split<<<(NW/4 + 255)/256, 256>>>(Wq, whi + 0*(size_t)NW, wlo + 0*(size_t)NW, NW/4);
    f32_split<<<(NW/4 + 255)/256, 256>>>(Wk, whi + 1*(size_t)NW, wlo + 1*(size_t)NW, NW/4);
    f32_split<<<(NW/4 + 255)/256, 256>>>(Wv, whi + 2*(size_t)NW, wlo + 2*(size_t)NW, NW/4);
    f32_split<<<(NW/4 + 255)/256, 256>>>(Wo, whi + 3*(size_t)NW, wlo + 3*(size_t)NW, NW/4);

    dim3 gqkv(DIMN/128, MROWS/128, 3);
    qkv_gemm_mma<<<gqkv, 256>>>(xhi, xlo);

    int nrope = BATCH*SEQ*NH*(HD/2);
    rope_transpose<<<(nrope + 255)/256, 256>>>();

    // smem: K 2 stages x 2 planes x 64 x 72 bf16 + V 2 stages x 64 x 72 fp16
    const int FSM_BYTES = (2*2*64*FROWP + 2*64*FROWP) * 2;   // 55296
    cudaFuncSetAttribute(flash_attn_mma, cudaFuncAttributeMaxDynamicSharedMemorySize, FSM_BYTES);
    dim3 gfl(SEQ/64, NH, BATCH);
    flash_attn_mma<<<gfl, 128, FSM_BYTES>>>();

    dim3 gout(DIMN/128, MROWS/128);
    out_gemm_mma<<<gout, 256>>>(out);
}

// round 7
// speedup vs baseline: 1.4163x; 1.1946x over previous
#include <cuda_runtime.h>
#include <cuda_bf16.h>
#include <cuda_fp16.h>
#include <math.h>

#define DIMN  1024
#define NH    16
#define HD    64
#define BATCH 2
#define SEQ   2048
#define MROWS (BATCH*SEQ)   // 4096

// ---------------- scratch (device globals; no allocations allowed) ----------
__device__ float g_qlin[MROWS*DIMN];
__device__ float g_klin[MROWS*DIMN];

__device__ __nv_bfloat16 g_xhi[MROWS*DIMN];
__device__ __nv_bfloat16 g_xlo[MROWS*DIMN];
__device__ __half        g_x16[MROWS*DIMN];
__device__ __nv_bfloat16 g_whi[2][DIMN*DIMN];   // Wq, Wk
__device__ __nv_bfloat16 g_wlo[2][DIMN*DIMN];
__device__ __half        g_w16v[DIMN*DIMN];
__device__ __half        g_w16o[DIMN*DIMN];

// attention operands, [B,H,S,hd]
__device__ __nv_bfloat16 g_qthi[MROWS*DIMN];
__device__ __nv_bfloat16 g_qtlo[MROWS*DIMN];
__device__ __nv_bfloat16 g_kthi[MROWS*DIMN];
__device__ __nv_bfloat16 g_ktlo[MROWS*DIMN];
__device__ __half        g_v16 [MROWS*DIMN];   // V fp16 plane
__device__ __half        g_att16[MROWS*DIMN];  // attention out, [B,S,D], fp16

// ---------------- helpers ----------------------------------------------------
__device__ __forceinline__ unsigned int smem_u32(const void* p) {
    return (unsigned int)__cvta_generic_to_shared(p);
}
__device__ __forceinline__ void cp16(unsigned int s, const void* g) {
    asm volatile("cp.async.cg.shared.global [%0], [%1], 16;\n" :: "r"(s), "l"(g));
}
__device__ __forceinline__ void cp_commit() {
    asm volatile("cp.async.commit_group;\n");
}
__device__ __forceinline__ void cp_wait1() {
    asm volatile("cp.async.wait_group 1;\n");
}
__device__ __forceinline__ void cp_wait0() {
    asm volatile("cp.async.wait_group 0;\n");
}
__device__ __forceinline__ void ldmx4(unsigned int addr, unsigned int& r0, unsigned int& r1,
                                      unsigned int& r2, unsigned int& r3) {
    asm volatile("ldmatrix.sync.aligned.m8n8.x4.shared.b16 {%0,%1,%2,%3}, [%4];\n"
                 : "=r"(r0), "=r"(r1), "=r"(r2), "=r"(r3) : "r"(addr));
}
__device__ __forceinline__ void ldmx4t(unsigned int addr, unsigned int& r0, unsigned int& r1,
                                       unsigned int& r2, unsigned int& r3) {
    asm volatile("ldmatrix.sync.aligned.m8n8.x4.trans.shared.b16 {%0,%1,%2,%3}, [%4];\n"
                 : "=r"(r0), "=r"(r1), "=r"(r2), "=r"(r3) : "r"(addr));
}
__device__ __forceinline__ void mma16816(float* c, const unsigned int* a,
                                         unsigned int b0, unsigned int b1) {
    asm volatile("mma.sync.aligned.m16n8k16.row.col.f32.bf16.bf16.f32 "
                 "{%0,%1,%2,%3}, {%4,%5,%6,%7}, {%8,%9}, {%0,%1,%2,%3};\n"
                 : "+f"(c[0]), "+f"(c[1]), "+f"(c[2]), "+f"(c[3])
                 : "r"(a[0]), "r"(a[1]), "r"(a[2]), "r"(a[3]), "r"(b0), "r"(b1));
}
__device__ __forceinline__ void mma16816h(float* c, const unsigned int* a,
                                          unsigned int b0, unsigned int b1) {
    asm volatile("mma.sync.aligned.m16n8k16.row.col.f32.f16.f16.f32 "
                 "{%0,%1,%2,%3}, {%4,%5,%6,%7}, {%8,%9}, {%0,%1,%2,%3};\n"
                 : "+f"(c[0]), "+f"(c[1]), "+f"(c[2]), "+f"(c[3])
                 : "r"(a[0]), "r"(a[1]), "r"(a[2]), "r"(a[3]), "r"(b0), "r"(b1));
}
__device__ __forceinline__ unsigned short bfbits(float f) {
    __nv_bfloat16 h = __float2bfloat16(f);
    return *reinterpret_cast<unsigned short*>(&h);
}
__device__ __forceinline__ unsigned short hfbits(float f) {
    __half h = __float2half_rn(f);
    return *reinterpret_cast<unsigned short*>(&h);
}
__device__ __forceinline__ unsigned int pk2h(float a, float b) {
    return (unsigned int)hfbits(a) | ((unsigned int)hfbits(b) << 16);
}
__device__ __forceinline__ float bf2f(unsigned short u) {
    __nv_bfloat16 h = *reinterpret_cast<__nv_bfloat16*>(&u);
    return __bfloat162float(h);
}

// ---------------- conversion kernels -----------------------------------------
__global__ __launch_bounds__(256)
void f32_split(const float* __restrict__ src,
               __nv_bfloat16* __restrict__ hi,
               __nv_bfloat16* __restrict__ lo, int n4)
{
    int i = blockIdx.x * blockDim.x + threadIdx.x;
    if (i >= n4) return;
    float4 v = reinterpret_cast<const float4*>(src)[i];
    float f[4] = {v.x, v.y, v.z, v.w};
    unsigned short ph[4], pl[4];
#pragma unroll
    for (int j = 0; j < 4; j++) {
        ph[j] = bfbits(f[j]);
        pl[j] = bfbits(f[j] - bf2f(ph[j]));
    }
    reinterpret_cast<ushort4*>(hi)[i] = make_ushort4(ph[0], ph[1], ph[2], ph[3]);
    reinterpret_cast<ushort4*>(lo)[i] = make_ushort4(pl[0], pl[1], pl[2], pl[3]);
}

__global__ __launch_bounds__(256)
void f32_to_h(const float* __restrict__ src, __half* __restrict__ dst, int n4)
{
    int i = blockIdx.x * blockDim.x + threadIdx.x;
    if (i >= n4) return;
    float4 v = reinterpret_cast<const float4*>(src)[i];
    reinterpret_cast<ushort4*>(dst)[i] =
        make_ushort4(hfbits(v.x), hfbits(v.y), hfbits(v.z), hfbits(v.w));
}

// ---------------- 3-term bf16 GEMM (Q,K): C = A @ W^T ------------------------
__device__ __forceinline__ void gemm_mma_body(const __nv_bfloat16* __restrict__ Ah,
                                              const __nv_bfloat16* __restrict__ Al,
                                              const __nv_bfloat16* __restrict__ Bh,
                                              const __nv_bfloat16* __restrict__ Bl,
                                              float* __restrict__ C)
{
    __shared__ __align__(128) __nv_bfloat16 sA[2][2][128][16];
    __shared__ __align__(128) __nv_bfloat16 sB[2][2][128][16];

    const int tid   = threadIdx.x;
    const int lane  = tid & 31;
    const int warp  = tid >> 5;
    const int wm    = warp >> 2;
    const int wn    = warp & 3;
    const int row0  = blockIdx.y * 128;
    const int col0  = blockIdx.x * 128;

    const int lrow = tid >> 1;
    const int lch  = tid & 1;
    const int lpc  = lch ^ ((lrow >> 2) & 1);
    const size_t aoff = (size_t)(row0 + lrow) * DIMN + lch * 8;
    const size_t boff = (size_t)(col0 + lrow) * DIMN + lch * 8;

    float acc[4][4][4];
#pragma unroll
    for (int i = 0; i < 4; i++)
#pragma unroll
        for (int j = 0; j < 4; j++)
#pragma unroll
            for (int k = 0; k < 4; k++) acc[i][j][k] = 0.0f;

    const unsigned int stg = (unsigned int)(2 * 128 * 16 * sizeof(__nv_bfloat16));

    unsigned int aAddr[4][2], bAddr[2][2];
#pragma unroll
    for (int mt = 0; mt < 4; mt++) {
        int r  = wm * 64 + mt * 16 + (lane & 15);
        int ch = lane >> 4;
        int pc = ch ^ ((r >> 2) & 1);
        aAddr[mt][0] = smem_u32(&sA[0][0][r][pc * 8]);
        aAddr[mt][1] = smem_u32(&sA[0][1][r][pc * 8]);
    }
#pragma unroll
    for (int p = 0; p < 2; p++) {
        int grp = lane >> 3;
        int r   = wn * 32 + p * 16 + (grp >> 1) * 8 + (lane & 7);
        int ch  = grp & 1;
        int pc  = ch ^ ((r >> 2) & 1);
        bAddr[p][0] = smem_u32(&sB[0][0][r][pc * 8]);
        bAddr[p][1] = smem_u32(&sB[0][1][r][pc * 8]);
    }

    {
        cp16(smem_u32(&sA[0][0][lrow][lpc * 8]), Ah + aoff);
        cp16(smem_u32(&sA[0][1][lrow][lpc * 8]), Al + aoff);
        cp16(smem_u32(&sB[0][0][lrow][lpc * 8]), Bh + boff);
        cp16(smem_u32(&sB[0][1][lrow][lpc * 8]), Bl + boff);
        cp_commit();
    }

    const int KT = DIMN / 16;
    for (int kt = 0; kt < KT; kt++) {
        int cur = kt & 1;
        if (kt + 1 < KT) {
            int nxt = (kt + 1) & 1;
            size_t ko = (size_t)(kt + 1) * 16;
            cp16(smem_u32(&sA[nxt][0][lrow][lpc * 8]), Ah + aoff + ko);
            cp16(smem_u32(&sA[nxt][1][lrow][lpc * 8]), Al + aoff + ko);
            cp16(smem_u32(&sB[nxt][0][lrow][lpc * 8]), Bh + boff + ko);
            cp16(smem_u32(&sB[nxt][1][lrow][lpc * 8]), Bl + boff + ko);
        }
        cp_commit();
        cp_wait1();
        __syncthreads();

        unsigned int coff = cur * stg;
        unsigned int ah[4][4], al[4][4], bh[2][4], bl[2][4];
#pragma unroll
        for (int mt = 0; mt < 4; mt++) {
            ldmx4(aAddr[mt][0] + coff, ah[mt][0], ah[mt][1], ah[mt][2], ah[mt][3]);
            ldmx4(aAddr[mt][1] + coff, al[mt][0], al[mt][1], al[mt][2], al[mt][3]);
        }
#pragma unroll
        for (int p = 0; p < 2; p++) {
            ldmx4(bAddr[p][0] + coff, bh[p][0], bh[p][1], bh[p][2], bh[p][3]);
            ldmx4(bAddr[p][1] + coff, bl[p][0], bl[p][1], bl[p][2], bl[p][3]);
        }
#pragma unroll
        for (int mt = 0; mt < 4; mt++) {
#pragma unroll
            for (int nt = 0; nt < 4; nt++) {
                int p = nt >> 1, s = nt & 1;
                mma16816(acc[mt][nt], ah[mt], bh[p][2*s], bh[p][2*s+1]);
                mma16816(acc[mt][nt], ah[mt], bl[p][2*s], bl[p][2*s+1]);
                mma16816(acc[mt][nt], al[mt], bh[p][2*s], bh[p][2*s+1]);
            }
        }
        __syncthreads();
    }

#pragma unroll
    for (int mt = 0; mt < 4; mt++) {
        int r = row0 + wm * 64 + mt * 16 + (lane >> 2);
#pragma unroll
        for (int nt = 0; nt < 4; nt++) {
            int c = col0 + wn * 32 + nt * 8 + (lane & 3) * 2;
            *reinterpret_cast<float2*>(&C[(size_t)r * DIMN + c]) =
                make_float2(acc[mt][nt][0], acc[mt][nt][1]);
            *reinterpret_cast<float2*>(&C[(size_t)(r + 8) * DIMN + c]) =
                make_float2(acc[mt][nt][2], acc[mt][nt][3]);
        }
    }
}

__global__ __launch_bounds__(256)
void qk_gemm_mma(const __nv_bfloat16* __restrict__ xhi,
                 const __nv_bfloat16* __restrict__ xlo)
{
    if (blockIdx.z == 0) gemm_mma_body(xhi, xlo, g_whi[0], g_wlo[0], g_qlin);
    else                 gemm_mma_body(xhi, xlo, g_whi[1], g_wlo[1], g_klin);
}

// ---------------- single fp16 GEMM (V, O): C = A @ W^T -----------------------
__device__ __forceinline__ void gemm_f16_body(const __half* __restrict__ A,
                                              const __half* __restrict__ W,
                                              float* __restrict__ C, int vmode)
{
    __shared__ __align__(128) __half sA[2][128][16];
    __shared__ __align__(128) __half sB[2][128][16];

    const int tid   = threadIdx.x;
    const int lane  = tid & 31;
    const int warp  = tid >> 5;
    const int wm    = warp >> 2;
    const int wn    = warp & 3;
    const int row0  = blockIdx.y * 128;
    const int col0  = blockIdx.x * 128;

    const int lrow = tid >> 1;
    const int lch  = tid & 1;
    const int lpc  = lch ^ ((lrow >> 2) & 1);
    const size_t aoff = (size_t)(row0 + lrow) * DIMN + lch * 8;
    const size_t boff = (size_t)(col0 + lrow) * DIMN + lch * 8;

    float acc[4][4][4];
#pragma unroll
    for (int i = 0; i < 4; i++)
#pragma unroll
        for (int j = 0; j < 4; j++)
#pragma unroll
            for (int k = 0; k < 4; k++) acc[i][j][k] = 0.0f;

    const unsigned int stg = (unsigned int)(128 * 16 * sizeof(__half));  // 4KB

    unsigned int aAddr[4], bAddr[2];
#pragma unroll
    for (int mt = 0; mt < 4; mt++) {
        int r  = wm * 64 + mt * 16 + (lane & 15);
        int ch = lane >> 4;
        int pc = ch ^ ((r >> 2) & 1);
        aAddr[mt] = smem_u32(&sA[0][r][pc * 8]);
    }
#pragma unroll
    for (int p = 0; p < 2; p++) {
        int grp = lane >> 3;
        int r   = wn * 32 + p * 16 + (grp >> 1) * 8 + (lane & 7);
        int ch  = grp & 1;
        int pc  = ch ^ ((r >> 2) & 1);
        bAddr[p] = smem_u32(&sB[0][r][pc * 8]);
    }

    {
        cp16(smem_u32(&sA[0][lrow][lpc * 8]), A + aoff);
        cp16(smem_u32(&sB[0][lrow][lpc * 8]), W + boff);
        cp_commit();
    }

    const int KT = DIMN / 16;
    for (int kt = 0; kt < KT; kt++) {
        int cur = kt & 1;
        if (kt + 1 < KT) {
            int nxt = (kt + 1) & 1;
            size_t ko = (size_t)(kt + 1) * 16;
            cp16(smem_u32(&sA[nxt][lrow][lpc * 8]), A + aoff + ko);
            cp16(smem_u32(&sB[nxt][lrow][lpc * 8]), W + boff + ko);
        }
        cp_commit();
        cp_wait1();
        __syncthreads();

        unsigned int coff = cur * stg;
        unsigned int ah[4][4], bf[2][4];
#pragma unroll
        for (int mt = 0; mt < 4; mt++)
            ldmx4(aAddr[mt] + coff, ah[mt][0], ah[mt][1], ah[mt][2], ah[mt][3]);
#pragma unroll
        for (int p = 0; p < 2; p++)
            ldmx4(bAddr[p] + coff, bf[p][0], bf[p][1], bf[p][2], bf[p][3]);
#pragma unroll
        for (int mt = 0; mt < 4; mt++) {
#pragma unroll
            for (int nt = 0; nt < 4; nt++) {
                int p = nt >> 1, s = nt & 1;
                mma16816h(acc[mt][nt], ah[mt], bf[p][2*s], bf[p][2*s+1]);
            }
        }
        __syncthreads();
    }

    if (!vmode) {
#pragma unroll
        for (int mt = 0; mt < 4; mt++) {
            int r = row0 + wm * 64 + mt * 16 + (lane >> 2);
#pragma unroll
            for (int nt = 0; nt < 4; nt++) {
                int c = col0 + wn * 32 + nt * 8 + (lane & 3) * 2;
                *reinterpret_cast<float2*>(&C[(size_t)r * DIMN + c]) =
                    make_float2(acc[mt][nt][0], acc[mt][nt][1]);
                *reinterpret_cast<float2*>(&C[(size_t)(r + 8) * DIMN + c]) =
                    make_float2(acc[mt][nt][2], acc[mt][nt][3]);
            }
        }
    } else {
        // V: fp16, scatter transposed into [B,H,S,hd]
#pragma unroll
        for (int mt = 0; mt < 4; mt++) {
            int r = row0 + wm * 64 + mt * 16 + (lane >> 2);
#pragma unroll
            for (int nt = 0; nt < 4; nt++) {
                int c = col0 + wn * 32 + nt * 8 + (lane & 3) * 2;
#pragma unroll
                for (int e = 0; e < 4; e++) {
                    int rr = r + (e >> 1) * 8;
                    int cc = c + (e & 1);
                    int b = rr >> 11, s = rr & (SEQ-1);
                    int h = cc >> 6,  d = cc & (HD-1);
                    size_t di = (((size_t)(b*NH + h))*SEQ + s)*HD + d;
                    reinterpret_cast<unsigned short*>(g_v16)[di] = hfbits(acc[mt][nt][e]);
                }
            }
        }
    }
}

__global__ __launch_bounds__(256)
void v_gemm_f16(const __half* __restrict__ x16)
{
    gemm_f16_body(x16, g_w16v, nullptr, 1);
}

__global__ __launch_bounds__(256)
void out_gemm_f16(float* __restrict__ C)
{
    gemm_f16_body(g_att16, g_w16o, C, 0);
}

// ---------------- RoPE + transpose to [B,H,S,hd], emit bf16 hi/lo -----------
__global__ void rope_transpose()
{
    int idx = blockIdx.x * blockDim.x + threadIdx.x;
    if (idx >= BATCH*SEQ*NH*(HD/2)) return;
    int d2 = idx & 31;
    int h  = (idx >> 5) & (NH-1);
    int s  = (idx >> 9) & (SEQ-1);
    int b  = idx >> 20;

    float inv = exp2f(-(float)d2 * (13.287712379549449f / 32.0f));
    float ang = (float)s * inv;
    float c  = cosf(ang);
    float sn = sinf(ang);

    size_t src = ((size_t)(b*SEQ + s))*DIMN + h*HD;
    size_t dst = (((size_t)(b*NH + h))*SEQ + s)*HD;

    float q1 = g_qlin[src + d2], q2 = g_qlin[src + d2 + 32];
    float k1 = g_klin[src + d2], k2 = g_klin[src + d2 + 32];
    float qa = q1*c - q2*sn, qb = q2*c + q1*sn;
    float ka = k1*c - k2*sn, kb = k2*c + k1*sn;

    unsigned short* qh = reinterpret_cast<unsigned short*>(g_qthi);
    unsigned short* qlp = reinterpret_cast<unsigned short*>(g_qtlo);
    unsigned short* kh = reinterpret_cast<unsigned short*>(g_kthi);
    unsigned short* klp = reinterpret_cast<unsigned short*>(g_ktlo);

    unsigned short t;
    t = bfbits(qa); qh[dst+d2] = t;      qlp[dst+d2]    = bfbits(qa - bf2f(t));
    t = bfbits(qb); qh[dst+d2+32] = t;   qlp[dst+d2+32] = bfbits(qb - bf2f(t));
    t = bfbits(ka); kh[dst+d2] = t;      klp[dst+d2]    = bfbits(ka - bf2f(t));
    t = bfbits(kb); kh[dst+d2+32] = t;   klp[dst+d2+32] = bfbits(kb - bf2f(t));
}

// ---------------- Flash attention (causal): QK split-bf16, PV fp16 ----------
#define FROWP 72

__device__ __forceinline__ int SKI(int st, int hm, int r) {
    return ((st*2 + hm)*64 + r) * FROWP;
}
__device__ __forceinline__ int SVI(int st, int r) {
    return (st*64 + r) * FROWP;
}

__global__ __launch_bounds__(128)
void flash_attn_mma()
{
    const int iq = (int)gridDim.x - 1 - (int)blockIdx.x;   // heavy tiles first
    const int h = blockIdx.y, b = blockIdx.z;
    const int q0 = iq * 64;
    const int tid = threadIdx.x, lane = tid & 31, warp = tid >> 5;
    const float LOG2E = 1.4426950408889634f;

    extern __shared__ __align__(16) __nv_bfloat16 fsm[];
    __nv_bfloat16* sK = fsm;
    __half*        sV = reinterpret_cast<__half*>(fsm + 2*2*64*FROWP);

    const size_t bh = (size_t)(b*NH + h) * SEQ * HD;
    const __nv_bfloat16* Qh = g_qthi + bh + (size_t)q0*HD;
    const __nv_bfloat16* Ql = g_qtlo + bh + (size_t)q0*HD;
    const __nv_bfloat16* Kh = g_kthi + bh;
    const __nv_bfloat16* Kl = g_ktlo + bh;
    const __half*        Vv = g_v16  + bh;

    const int lrow = tid >> 1;
    const int lc0  = (tid & 1) * 4;

#pragma unroll
    for (int cc = 0; cc < 4; cc++) {
        int col = (lc0 + cc) * 8;
        cp16(smem_u32(&sK[SKI(0,0,lrow) + col]), Qh + lrow*HD + col);
        cp16(smem_u32(&sK[SKI(0,1,lrow) + col]), Ql + lrow*HD + col);
    }
    cp_commit(); cp_wait0();
    __syncthreads();

    unsigned int qfh[4][4], qfl[4][4];
    {
        int r  = warp*16 + (lane & 15);
        int ch = (lane >> 4) * 8;
#pragma unroll
        for (int ks = 0; ks < 4; ks++) {
            ldmx4(smem_u32(&sK[SKI(0,0,r) + ch + ks*16]),
                  qfh[ks][0], qfh[ks][1], qfh[ks][2], qfh[ks][3]);
            ldmx4(smem_u32(&sK[SKI(0,1,r) + ch + ks*16]),
                  qfl[ks][0], qfl[ks][1], qfl[ks][2], qfl[ks][3]);
        }
    }
    __syncthreads();

    float oacc[8][4];
#pragma unroll
    for (int i = 0; i < 8; i++)
#pragma unroll
        for (int j = 0; j < 4; j++) oacc[i][j] = 0.0f;
    float m0 = -INFINITY, m1 = -INFINITY, l0 = 0.0f, l1 = 0.0f;

    const int nkv = iq + 1;

#pragma unroll
    for (int cc = 0; cc < 4; cc++) {
        int col = (lc0 + cc) * 8;
        cp16(smem_u32(&sK[SKI(0,0,lrow) + col]), Kh + lrow*HD + col);
        cp16(smem_u32(&sK[SKI(0,1,lrow) + col]), Kl + lrow*HD + col);
        cp16(smem_u32(&sV[SVI(0,lrow) + col]),   Vv + lrow*HD + col);
    }
    cp_commit();

    for (int t = 0; t < nkv; t++) {
        const int st = t & 1;
        if (t + 1 < nkv) {
            const int ns = (t + 1) & 1;
            const size_t go = (size_t)(t + 1) * 64 * HD;
#pragma unroll
            for (int cc = 0; cc < 4; cc++) {
                int col = (lc0 + cc) * 8;
                cp16(smem_u32(&sK[SKI(ns,0,lrow) + col]), Kh + go + lrow*HD + col);
                cp16(smem_u32(&sK[SKI(ns,1,lrow) + col]), Kl + go + lrow*HD + col);
                cp16(smem_u32(&sV[SVI(ns,lrow) + col]),   Vv + go + lrow*HD + col);
            }
        }
        cp_commit();
        cp_wait1();
        __syncthreads();

        float sacc[8][4];
#pragma unroll
        for (int i = 0; i < 8; i++)
#pragma unroll
            for (int j = 0; j < 4; j++) sacc[i][j] = 0.0f;

        {
            const int grp = lane >> 3;
            const int rb  = (grp >> 1) * 8 + (lane & 7);
            const int cb  = (grp & 1) * 8;
#pragma unroll
            for (int ks = 0; ks < 4; ks++) {
#pragma unroll
                for (int p = 0; p < 4; p++) {
                    unsigned int kfh[4], kfl[4];
                    ldmx4(smem_u32(&sK[SKI(st,0,p*16+rb) + cb + ks*16]),
                          kfh[0], kfh[1], kfh[2], kfh[3]);
                    ldmx4(smem_u32(&sK[SKI(st,1,p*16+rb) + cb + ks*16]),
                          kfl[0], kfl[1], kfl[2], kfl[3]);
#pragma unroll
                    for (int s = 0; s < 2; s++) {
                        int nt = 2*p + s;
                        mma16816(sacc[nt], qfh[ks], kfh[2*s], kfh[2*s+1]);
                        mma16816(sacc[nt], qfh[ks], kfl[2*s], kfl[2*s+1]);
                        mma16816(sacc[nt], qfl[ks], kfh[2*s], kfh[2*s+1]);
                    }
                }
            }
        }

        const int quad = lane >> 2;
        const int cpair = (lane & 3) * 2;
        if (t == nkv - 1) {
            const int r0 = q0 + warp*16 + quad;
            const int kvb = t*64 + cpair;
#pragma unroll
            for (int nt = 0; nt < 8; nt++) {
#pragma unroll
                for (int j = 0; j < 2; j++) {
                    int kg = kvb + nt*8 + j;
                    sacc[nt][j]   = (kg > r0)     ? -INFINITY : sacc[nt][j]   * 0.125f;
                    sacc[nt][2+j] = (kg > r0 + 8) ? -INFINITY : sacc[nt][2+j] * 0.125f;
                }
            }
        } else {
#pragma unroll
            for (int nt = 0; nt < 8; nt++)
#pragma unroll
                for (int j = 0; j < 4; j++) sacc[nt][j] *= 0.125f;
        }

        float mx0 = -INFINITY, mx1 = -INFINITY;
#pragma unroll
        for (int nt = 0; nt < 8; nt++) {
            mx0 = fmaxf(mx0, fmaxf(sacc[nt][0], sacc[nt][1]));
            mx1 = fmaxf(mx1, fmaxf(sacc[nt][2], sacc[nt][3]));
        }
        mx0 = fmaxf(mx0, __shfl_xor_sync(0xffffffffu, mx0, 1));
        mx0 = fmaxf(mx0, __shfl_xor_sync(0xffffffffu, mx0, 2));
        mx1 = fmaxf(mx1, __shfl_xor_sync(0xffffffffu, mx1, 1));
        mx1 = fmaxf(mx1, __shfl_xor_sync(0xffffffffu, mx1, 2));

        float mn0 = fmaxf(m0, mx0), mn1 = fmaxf(m1, mx1);
        float a0 = exp2f((m0 - mn0) * LOG2E);
        float a1 = exp2f((m1 - mn1) * LOG2E);
        m0 = mn0; m1 = mn1;

        float s0 = 0.0f, s1 = 0.0f;
#pragma unroll
        for (int nt = 0; nt < 8; nt++) {
            float p0 = exp2f((sacc[nt][0] - mn0) * LOG2E);
            float p1 = exp2f((sacc[nt][1] - mn0) * LOG2E);
            float p2 = exp2f((sacc[nt][2] - mn1) * LOG2E);
            float p3 = exp2f((sacc[nt][3] - mn1) * LOG2E);
            sacc[nt][0] = p0; sacc[nt][1] = p1; sacc[nt][2] = p2; sacc[nt][3] = p3;
            s0 += p0 + p1; s1 += p2 + p3;
        }
        s0 += __shfl_xor_sync(0xffffffffu, s0, 1);
        s0 += __shfl_xor_sync(0xffffffffu, s0, 2);
        s1 += __shfl_xor_sync(0xffffffffu, s1, 1);
        s1 += __shfl_xor_sync(0xffffffffu, s1, 2);
        l0 = l0 * a0 + s0;
        l1 = l1 * a1 + s1;

#pragma unroll
        for (int nt = 0; nt < 8; nt++) {
            oacc[nt][0] *= a0; oacc[nt][1] *= a0;
            oacc[nt][2] *= a1; oacc[nt][3] *= a1;
        }

        unsigned int pf[4][4];
#pragma unroll
        for (int ks = 0; ks < 4; ks++) {
#pragma unroll
            for (int half = 0; half < 2; half++) {
                pf[ks][half]   = pk2h(sacc[2*ks][2*half],   sacc[2*ks][2*half+1]);
                pf[ks][2+half] = pk2h(sacc[2*ks+1][2*half], sacc[2*ks+1][2*half+1]);
            }
        }

        {
            const int g   = lane >> 3;
            const int kvr = (g & 1) * 8 + (lane & 7);
            const int dcb = (g >> 1) * 8;
#pragma unroll
            for (int dt = 0; dt < 4; dt++) {
#pragma unroll
                for (int ks = 0; ks < 4; ks++) {
                    unsigned int vf[4];
                    ldmx4t(smem_u32(&sV[SVI(st,ks*16+kvr) + dt*16 + dcb]),
                           vf[0], vf[1], vf[2], vf[3]);
#pragma unroll
                    for (int s = 0; s < 2; s++) {
                        int nt = 2*dt + s;
                        mma16816h(oacc[nt], pf[ks], vf[2*s], vf[2*s+1]);
                    }
                }
            }
        }
        __syncthreads();
    }

    // epilogue: O/l -> g_att16 (fp16) at [B,S,D]
    {
        const int quad = lane >> 2;
        const int cpair = (lane & 3) * 2;
        float il0 = 1.0f / l0, il1 = 1.0f / l1;
        int r0 = q0 + warp*16 + quad;
        unsigned short* AO = reinterpret_cast<unsigned short*>(g_att16);
#pragma unroll
        for (int nt = 0; nt < 8; nt++) {
            int d = nt*8 + cpair;
            size_t i0 = ((size_t)(b*SEQ) + r0)     * DIMN + h*HD + d;
            size_t i1 = ((size_t)(b*SEQ) + r0 + 8) * DIMN + h*HD + d;
            *reinterpret_cast<unsigned int*>(&AO[i0]) =
                pk2h(oacc[nt][0]*il0, oacc[nt][1]*il0);
            *reinterpret_cast<unsigned int*>(&AO[i1]) =
                pk2h(oacc[nt][2]*il1, oacc[nt][3]*il1);
        }
    }
}

// ---------------- launch ----------------------------------------------------
extern "C" void kernel_launch(void* const* d_in, const int* in_sizes, int n_in,
                              void* d_out, int out_size)
{
    const float* x  = (const float*)d_in[0];
    const float* Wq = (const float*)d_in[1];
    const float* Wk = (const float*)d_in[2];
    const float* Wv = (const float*)d_in[3];
    const float* Wo = (const float*)d_in[4];
    float* out = (float*)d_out;

    __nv_bfloat16 *xhi, *xlo, *whi, *wlo;
    __half *x16, *w16v, *w16o;
    cudaGetSymbolAddress((void**)&xhi, g_xhi);
    cudaGetSymbolAddress((void**)&xlo, g_xlo);
    cudaGetSymbolAddress((void**)&x16, g_x16);
    cudaGetSymbolAddress((void**)&whi, g_whi);
    cudaGetSymbolAddress((void**)&wlo, g_wlo);
    cudaGetSymbolAddress((void**)&w16v, g_w16v);
    cudaGetSymbolAddress((void**)&w16o, g_w16o);

    const int NW = DIMN * DIMN;
    const int NX = MROWS * DIMN;

    f32_split<<<(NX/4 + 255)/256, 256>>>(x,  xhi, xlo, NX/4);
    f32_to_h <<<(NX/4 + 255)/256, 256>>>(x,  x16, NX/4);
    f32_split<<<(NW/4 + 255)/256, 256>>>(Wq, whi + 0*(size_t)NW, wlo + 0*(size_t)NW, NW/4);
    f32_split<<<(NW/4 + 255)/256, 256>>>(Wk, whi + 1*(size_t)NW, wlo + 1*(size_t)NW, NW/4);
    f32_to_h <<<(NW/4 + 255)/256, 256>>>(Wv, w16v, NW/4);
    f32_to_h <<<(NW/4 + 255)/256, 256>>>(Wo, w16o, NW/4);

    dim3 gqk(DIMN/128, MROWS/128, 2);
    qk_gemm_mma<<<gqk, 256>>>(xhi, xlo);

    dim3 gv(DIMN/128, MROWS/128);
    v_gemm_f16<<<gv, 256>>>(x16);

    int nrope = BATCH*SEQ*NH*(HD/2);
    rope_transpose<<<(nrope + 255)/256, 256>>>();

    const int FSM_BYTES = (2*2*64*FROWP + 2*64*FROWP) * 2;   // 55296
    cudaFuncSetAttribute(flash_attn_mma, cudaFuncAttributeMaxDynamicSharedMemorySize, FSM_BYTES);
    dim3 gfl(SEQ/64, NH, BATCH);
    flash_attn_mma<<<gfl, 128, FSM_BYTES>>>();

    dim3 gout(DIMN/128, MROWS/128);
    out_gemm_f16<<<gout, 256>>>(out);
}

// round 8
// speedup vs baseline: 1.6682x; 1.1778x over previous
#include <cuda_runtime.h>
#include <cuda_bf16.h>
#include <cuda_fp16.h>
#include <math.h>

#define DIMN  1024
#define NH    16
#define HD    64
#define BATCH 2
#define SEQ   2048
#define MROWS (BATCH*SEQ)   // 4096

// ---------------- scratch (device globals; no allocations allowed) ----------
__device__ float g_qlin[MROWS*DIMN];
__device__ float g_klin[MROWS*DIMN];

__device__ __nv_bfloat16 g_xhi[MROWS*DIMN];
__device__ __nv_bfloat16 g_xlo[MROWS*DIMN];
__device__ __half        g_x16[MROWS*DIMN];
__device__ __nv_bfloat16 g_whi[2][DIMN*DIMN];   // Wq, Wk
__device__ __nv_bfloat16 g_wlo[2][DIMN*DIMN];
__device__ __half        g_w16v[DIMN*DIMN];
__device__ __half        g_w16o[DIMN*DIMN];

// attention operands, [B,H,S,hd], fp16
__device__ __half g_q16 [MROWS*DIMN];
__device__ __half g_k16 [MROWS*DIMN];
__device__ __half g_v16 [MROWS*DIMN];
__device__ __half g_att16[MROWS*DIMN];  // attention out, [B,S,D], fp16

// ---------------- helpers ----------------------------------------------------
__device__ __forceinline__ unsigned int smem_u32(const void* p) {
    return (unsigned int)__cvta_generic_to_shared(p);
}
__device__ __forceinline__ void cp16(unsigned int s, const void* g) {
    asm volatile("cp.async.cg.shared.global [%0], [%1], 16;\n" :: "r"(s), "l"(g));
}
__device__ __forceinline__ void cp_commit() {
    asm volatile("cp.async.commit_group;\n");
}
__device__ __forceinline__ void cp_wait1() {
    asm volatile("cp.async.wait_group 1;\n");
}
__device__ __forceinline__ void cp_wait0() {
    asm volatile("cp.async.wait_group 0;\n");
}
__device__ __forceinline__ void ldmx4(unsigned int addr, unsigned int& r0, unsigned int& r1,
                                      unsigned int& r2, unsigned int& r3) {
    asm volatile("ldmatrix.sync.aligned.m8n8.x4.shared.b16 {%0,%1,%2,%3}, [%4];\n"
                 : "=r"(r0), "=r"(r1), "=r"(r2), "=r"(r3) : "r"(addr));
}
__device__ __forceinline__ void ldmx4t(unsigned int addr, unsigned int& r0, unsigned int& r1,
                                       unsigned int& r2, unsigned int& r3) {
    asm volatile("ldmatrix.sync.aligned.m8n8.x4.trans.shared.b16 {%0,%1,%2,%3}, [%4];\n"
                 : "=r"(r0), "=r"(r1), "=r"(r2), "=r"(r3) : "r"(addr));
}
__device__ __forceinline__ void mma16816(float* c, const unsigned int* a,
                                         unsigned int b0, unsigned int b1) {
    asm volatile("mma.sync.aligned.m16n8k16.row.col.f32.bf16.bf16.f32 "
                 "{%0,%1,%2,%3}, {%4,%5,%6,%7}, {%8,%9}, {%0,%1,%2,%3};\n"
                 : "+f"(c[0]), "+f"(c[1]), "+f"(c[2]), "+f"(c[3])
                 : "r"(a[0]), "r"(a[1]), "r"(a[2]), "r"(a[3]), "r"(b0), "r"(b1));
}
__device__ __forceinline__ void mma16816h(float* c, const unsigned int* a,
                                          unsigned int b0, unsigned int b1) {
    asm volatile("mma.sync.aligned.m16n8k16.row.col.f32.f16.f16.f32 "
                 "{%0,%1,%2,%3}, {%4,%5,%6,%7}, {%8,%9}, {%0,%1,%2,%3};\n"
                 : "+f"(c[0]), "+f"(c[1]), "+f"(c[2]), "+f"(c[3])
                 : "r"(a[0]), "r"(a[1]), "r"(a[2]), "r"(a[3]), "r"(b0), "r"(b1));
}
__device__ __forceinline__ unsigned short bfbits(float f) {
    __nv_bfloat16 h = __float2bfloat16(f);
    return *reinterpret_cast<unsigned short*>(&h);
}
__device__ __forceinline__ unsigned short hfbits(float f) {
    __half h = __float2half_rn(f);
    return *reinterpret_cast<unsigned short*>(&h);
}
__device__ __forceinline__ unsigned int pk2h(float a, float b) {
    return (unsigned int)hfbits(a) | ((unsigned int)hfbits(b) << 16);
}
__device__ __forceinline__ float bf2f(unsigned short u) {
    __nv_bfloat16 h = *reinterpret_cast<__nv_bfloat16*>(&u);
    return __bfloat162float(h);
}

// ---------------- conversion kernels -----------------------------------------
__global__ __launch_bounds__(256)
void f32_split(const float* __restrict__ src,
               __nv_bfloat16* __restrict__ hi,
               __nv_bfloat16* __restrict__ lo, int n4)
{
    int i = blockIdx.x * blockDim.x + threadIdx.x;
    if (i >= n4) return;
    float4 v = reinterpret_cast<const float4*>(src)[i];
    float f[4] = {v.x, v.y, v.z, v.w};
    unsigned short ph[4], pl[4];
#pragma unroll
    for (int j = 0; j < 4; j++) {
        ph[j] = bfbits(f[j]);
        pl[j] = bfbits(f[j] - bf2f(ph[j]));
    }
    reinterpret_cast<ushort4*>(hi)[i] = make_ushort4(ph[0], ph[1], ph[2], ph[3]);
    reinterpret_cast<ushort4*>(lo)[i] = make_ushort4(pl[0], pl[1], pl[2], pl[3]);
}

// x: split to bf16 hi/lo AND fp16 copy in one pass
__global__ __launch_bounds__(256)
void f32_split_h(const float* __restrict__ src,
                 __nv_bfloat16* __restrict__ hi,
                 __nv_bfloat16* __restrict__ lo,
                 __half* __restrict__ h16, int n4)
{
    int i = blockIdx.x * blockDim.x + threadIdx.x;
    if (i >= n4) return;
    float4 v = reinterpret_cast<const float4*>(src)[i];
    float f[4] = {v.x, v.y, v.z, v.w};
    unsigned short ph[4], pl[4], hh[4];
#pragma unroll
    for (int j = 0; j < 4; j++) {
        ph[j] = bfbits(f[j]);
        pl[j] = bfbits(f[j] - bf2f(ph[j]));
        hh[j] = hfbits(f[j]);
    }
    reinterpret_cast<ushort4*>(hi)[i]  = make_ushort4(ph[0], ph[1], ph[2], ph[3]);
    reinterpret_cast<ushort4*>(lo)[i]  = make_ushort4(pl[0], pl[1], pl[2], pl[3]);
    reinterpret_cast<ushort4*>(h16)[i] = make_ushort4(hh[0], hh[1], hh[2], hh[3]);
}

__global__ __launch_bounds__(256)
void f32_to_h(const float* __restrict__ src, __half* __restrict__ dst, int n4)
{
    int i = blockIdx.x * blockDim.x + threadIdx.x;
    if (i >= n4) return;
    float4 v = reinterpret_cast<const float4*>(src)[i];
    reinterpret_cast<ushort4*>(dst)[i] =
        make_ushort4(hfbits(v.x), hfbits(v.y), hfbits(v.z), hfbits(v.w));
}

// ---------------- 3-term bf16 GEMM (Q,K): C = A @ W^T ------------------------
__device__ __forceinline__ void gemm_mma_body(const __nv_bfloat16* __restrict__ Ah,
                                              const __nv_bfloat16* __restrict__ Al,
                                              const __nv_bfloat16* __restrict__ Bh,
                                              const __nv_bfloat16* __restrict__ Bl,
                                              float* __restrict__ C)
{
    __shared__ __align__(128) __nv_bfloat16 sA[2][2][128][16];
    __shared__ __align__(128) __nv_bfloat16 sB[2][2][128][16];

    const int tid   = threadIdx.x;
    const int lane  = tid & 31;
    const int warp  = tid >> 5;
    const int wm    = warp >> 2;
    const int wn    = warp & 3;
    const int row0  = blockIdx.y * 128;
    const int col0  = blockIdx.x * 128;

    const int lrow = tid >> 1;
    const int lch  = tid & 1;
    const int lpc  = lch ^ ((lrow >> 2) & 1);
    const size_t aoff = (size_t)(row0 + lrow) * DIMN + lch * 8;
    const size_t boff = (size_t)(col0 + lrow) * DIMN + lch * 8;

    float acc[4][4][4];
#pragma unroll
    for (int i = 0; i < 4; i++)
#pragma unroll
        for (int j = 0; j < 4; j++)
#pragma unroll
            for (int k = 0; k < 4; k++) acc[i][j][k] = 0.0f;

    const unsigned int stg = (unsigned int)(2 * 128 * 16 * sizeof(__nv_bfloat16));

    unsigned int aAddr[4][2], bAddr[2][2];
#pragma unroll
    for (int mt = 0; mt < 4; mt++) {
        int r  = wm * 64 + mt * 16 + (lane & 15);
        int ch = lane >> 4;
        int pc = ch ^ ((r >> 2) & 1);
        aAddr[mt][0] = smem_u32(&sA[0][0][r][pc * 8]);
        aAddr[mt][1] = smem_u32(&sA[0][1][r][pc * 8]);
    }
#pragma unroll
    for (int p = 0; p < 2; p++) {
        int grp = lane >> 3;
        int r   = wn * 32 + p * 16 + (grp >> 1) * 8 + (lane & 7);
        int ch  = grp & 1;
        int pc  = ch ^ ((r >> 2) & 1);
        bAddr[p][0] = smem_u32(&sB[0][0][r][pc * 8]);
        bAddr[p][1] = smem_u32(&sB[0][1][r][pc * 8]);
    }

    {
        cp16(smem_u32(&sA[0][0][lrow][lpc * 8]), Ah + aoff);
        cp16(smem_u32(&sA[0][1][lrow][lpc * 8]), Al + aoff);
        cp16(smem_u32(&sB[0][0][lrow][lpc * 8]), Bh + boff);
        cp16(smem_u32(&sB[0][1][lrow][lpc * 8]), Bl + boff);
        cp_commit();
    }

    const int KT = DIMN / 16;
    for (int kt = 0; kt < KT; kt++) {
        int cur = kt & 1;
        if (kt + 1 < KT) {
            int nxt = (kt + 1) & 1;
            size_t ko = (size_t)(kt + 1) * 16;
            cp16(smem_u32(&sA[nxt][0][lrow][lpc * 8]), Ah + aoff + ko);
            cp16(smem_u32(&sA[nxt][1][lrow][lpc * 8]), Al + aoff + ko);
            cp16(smem_u32(&sB[nxt][0][lrow][lpc * 8]), Bh + boff + ko);
            cp16(smem_u32(&sB[nxt][1][lrow][lpc * 8]), Bl + boff + ko);
        }
        cp_commit();
        cp_wait1();
        __syncthreads();

        unsigned int coff = cur * stg;
        unsigned int ah[4][4], al[4][4], bh[2][4], bl[2][4];
#pragma unroll
        for (int mt = 0; mt < 4; mt++) {
            ldmx4(aAddr[mt][0] + coff, ah[mt][0], ah[mt][1], ah[mt][2], ah[mt][3]);
            ldmx4(aAddr[mt][1] + coff, al[mt][0], al[mt][1], al[mt][2], al[mt][3]);
        }
#pragma unroll
        for (int p = 0; p < 2; p++) {
            ldmx4(bAddr[p][0] + coff, bh[p][0], bh[p][1], bh[p][2], bh[p][3]);
            ldmx4(bAddr[p][1] + coff, bl[p][0], bl[p][1], bl[p][2], bl[p][3]);
        }
#pragma unroll
        for (int mt = 0; mt < 4; mt++) {
#pragma unroll
            for (int nt = 0; nt < 4; nt++) {
                int p = nt >> 1, s = nt & 1;
                mma16816(acc[mt][nt], ah[mt], bh[p][2*s], bh[p][2*s+1]);
                mma16816(acc[mt][nt], ah[mt], bl[p][2*s], bl[p][2*s+1]);
                mma16816(acc[mt][nt], al[mt], bh[p][2*s], bh[p][2*s+1]);
            }
        }
        __syncthreads();
    }

#pragma unroll
    for (int mt = 0; mt < 4; mt++) {
        int r = row0 + wm * 64 + mt * 16 + (lane >> 2);
#pragma unroll
        for (int nt = 0; nt < 4; nt++) {
            int c = col0 + wn * 32 + nt * 8 + (lane & 3) * 2;
            *reinterpret_cast<float2*>(&C[(size_t)r * DIMN + c]) =
                make_float2(acc[mt][nt][0], acc[mt][nt][1]);
            *reinterpret_cast<float2*>(&C[(size_t)(r + 8) * DIMN + c]) =
                make_float2(acc[mt][nt][2], acc[mt][nt][3]);
        }
    }
}

__global__ __launch_bounds__(256)
void qk_gemm_mma(const __nv_bfloat16* __restrict__ xhi,
                 const __nv_bfloat16* __restrict__ xlo)
{
    if (blockIdx.z == 0) gemm_mma_body(xhi, xlo, g_whi[0], g_wlo[0], g_qlin);
    else                 gemm_mma_body(xhi, xlo, g_whi[1], g_wlo[1], g_klin);
}

// ---------------- single fp16 GEMM (V, O): C = A @ W^T -----------------------
__device__ __forceinline__ void gemm_f16_body(const __half* __restrict__ A,
                                              const __half* __restrict__ W,
                                              float* __restrict__ C, int vmode)
{
    __shared__ __align__(128) __half sA[2][128][16];
    __shared__ __align__(128) __half sB[2][128][16];

    const int tid   = threadIdx.x;
    const int lane  = tid & 31;
    const int warp  = tid >> 5;
    const int wm    = warp >> 2;
    const int wn    = warp & 3;
    const int row0  = blockIdx.y * 128;
    const int col0  = blockIdx.x * 128;

    const int lrow = tid >> 1;
    const int lch  = tid & 1;
    const int lpc  = lch ^ ((lrow >> 2) & 1);
    const size_t aoff = (size_t)(row0 + lrow) * DIMN + lch * 8;
    const size_t boff = (size_t)(col0 + lrow) * DIMN + lch * 8;

    float acc[4][4][4];
#pragma unroll
    for (int i = 0; i < 4; i++)
#pragma unroll
        for (int j = 0; j < 4; j++)
#pragma unroll
            for (int k = 0; k < 4; k++) acc[i][j][k] = 0.0f;

    const unsigned int stg = (unsigned int)(128 * 16 * sizeof(__half));

    unsigned int aAddr[4], bAddr[2];
#pragma unroll
    for (int mt = 0; mt < 4; mt++) {
        int r  = wm * 64 + mt * 16 + (lane & 15);
        int ch = lane >> 4;
        int pc = ch ^ ((r >> 2) & 1);
        aAddr[mt] = smem_u32(&sA[0][r][pc * 8]);
    }
#pragma unroll
    for (int p = 0; p < 2; p++) {
        int grp = lane >> 3;
        int r   = wn * 32 + p * 16 + (grp >> 1) * 8 + (lane & 7);
        int ch  = grp & 1;
        int pc  = ch ^ ((r >> 2) & 1);
        bAddr[p] = smem_u32(&sB[0][r][pc * 8]);
    }

    {
        cp16(smem_u32(&sA[0][lrow][lpc * 8]), A + aoff);
        cp16(smem_u32(&sB[0][lrow][lpc * 8]), W + boff);
        cp_commit();
    }

    const int KT = DIMN / 16;
    for (int kt = 0; kt < KT; kt++) {
        int cur = kt & 1;
        if (kt + 1 < KT) {
            int nxt = (kt + 1) & 1;
            size_t ko = (size_t)(kt + 1) * 16;
            cp16(smem_u32(&sA[nxt][lrow][lpc * 8]), A + aoff + ko);
            cp16(smem_u32(&sB[nxt][lrow][lpc * 8]), W + boff + ko);
        }
        cp_commit();
        cp_wait1();
        __syncthreads();

        unsigned int coff = cur * stg;
        unsigned int ah[4][4], bf[2][4];
#pragma unroll
        for (int mt = 0; mt < 4; mt++)
            ldmx4(aAddr[mt] + coff, ah[mt][0], ah[mt][1], ah[mt][2], ah[mt][3]);
#pragma unroll
        for (int p = 0; p < 2; p++)
            ldmx4(bAddr[p] + coff, bf[p][0], bf[p][1], bf[p][2], bf[p][3]);
#pragma unroll
        for (int mt = 0; mt < 4; mt++) {
#pragma unroll
            for (int nt = 0; nt < 4; nt++) {
                int p = nt >> 1, s = nt & 1;
                mma16816h(acc[mt][nt], ah[mt], bf[p][2*s], bf[p][2*s+1]);
            }
        }
        __syncthreads();
    }

    if (!vmode) {
#pragma unroll
        for (int mt = 0; mt < 4; mt++) {
            int r = row0 + wm * 64 + mt * 16 + (lane >> 2);
#pragma unroll
            for (int nt = 0; nt < 4; nt++) {
                int c = col0 + wn * 32 + nt * 8 + (lane & 3) * 2;
                *reinterpret_cast<float2*>(&C[(size_t)r * DIMN + c]) =
                    make_float2(acc[mt][nt][0], acc[mt][nt][1]);
                *reinterpret_cast<float2*>(&C[(size_t)(r + 8) * DIMN + c]) =
                    make_float2(acc[mt][nt][2], acc[mt][nt][3]);
            }
        }
    } else {
        // V: fp16, scatter transposed into [B,H,S,hd]
#pragma unroll
        for (int mt = 0; mt < 4; mt++) {
            int r = row0 + wm * 64 + mt * 16 + (lane >> 2);
#pragma unroll
            for (int nt = 0; nt < 4; nt++) {
                int c = col0 + wn * 32 + nt * 8 + (lane & 3) * 2;
#pragma unroll
                for (int e = 0; e < 4; e++) {
                    int rr = r + (e >> 1) * 8;
                    int cc = c + (e & 1);
                    int b = rr >> 11, s = rr & (SEQ-1);
                    int h = cc >> 6,  d = cc & (HD-1);
                    size_t di = (((size_t)(b*NH + h))*SEQ + s)*HD + d;
                    reinterpret_cast<unsigned short*>(g_v16)[di] = hfbits(acc[mt][nt][e]);
                }
            }
        }
    }
}

__global__ __launch_bounds__(256)
void v_gemm_f16(const __half* __restrict__ x16)
{
    gemm_f16_body(x16, g_w16v, nullptr, 1);
}

__global__ __launch_bounds__(256)
void out_gemm_f16(float* __restrict__ C)
{
    gemm_f16_body(g_att16, g_w16o, C, 0);
}

// ---------------- RoPE + transpose to [B,H,S,hd], emit fp16 -----------------
__global__ void rope_transpose()
{
    int idx = blockIdx.x * blockDim.x + threadIdx.x;
    if (idx >= BATCH*SEQ*NH*(HD/2)) return;
    int d2 = idx & 31;
    int h  = (idx >> 5) & (NH-1);
    int s  = (idx >> 9) & (SEQ-1);
    int b  = idx >> 20;

    float inv = exp2f(-(float)d2 * (13.287712379549449f / 32.0f));
    float ang = (float)s * inv;
    float c  = cosf(ang);
    float sn = sinf(ang);

    size_t src = ((size_t)(b*SEQ + s))*DIMN + h*HD;
    size_t dst = (((size_t)(b*NH + h))*SEQ + s)*HD;

    float q1 = g_qlin[src + d2], q2 = g_qlin[src + d2 + 32];
    float k1 = g_klin[src + d2], k2 = g_klin[src + d2 + 32];

    unsigned short* qp = reinterpret_cast<unsigned short*>(g_q16);
    unsigned short* kp = reinterpret_cast<unsigned short*>(g_k16);
    qp[dst+d2]    = hfbits(q1*c - q2*sn);
    qp[dst+d2+32] = hfbits(q2*c + q1*sn);
    kp[dst+d2]    = hfbits(k1*c - k2*sn);
    kp[dst+d2+32] = hfbits(k2*c + k1*sn);
}

// ---------------- Flash attention (causal): all fp16 MMA --------------------
#define FROWP 72

__device__ __forceinline__ int STI(int st, int r) {
    return (st*64 + r) * FROWP;
}

__global__ __launch_bounds__(128)
void flash_attn_mma()
{
    const int iq = (int)gridDim.x - 1 - (int)blockIdx.x;   // heavy tiles first
    const int h = blockIdx.y, b = blockIdx.z;
    const int q0 = iq * 64;
    const int tid = threadIdx.x, lane = tid & 31, warp = tid >> 5;
    const float LOG2E = 1.4426950408889634f;

    extern __shared__ __align__(16) __half fsm[];
    __half* sK = fsm;                       // 2 stages x 64 x 72
    __half* sV = fsm + 2*64*FROWP;          // 2 stages x 64 x 72

    const size_t bh = (size_t)(b*NH + h) * SEQ * HD;
    const __half* Qv = g_q16 + bh + (size_t)q0*HD;
    const __half* Kv = g_k16 + bh;
    const __half* Vv = g_v16 + bh;

    const int lrow = tid >> 1;
    const int lc0  = (tid & 1) * 4;

    // stage Q through sK stage0
#pragma unroll
    for (int cc = 0; cc < 4; cc++) {
        int col = (lc0 + cc) * 8;
        cp16(smem_u32(&sK[STI(0,lrow) + col]), Qv + lrow*HD + col);
    }
    cp_commit(); cp_wait0();
    __syncthreads();

    unsigned int qf[4][4];
    {
        int r  = warp*16 + (lane & 15);
        int ch = (lane >> 4) * 8;
#pragma unroll
        for (int ks = 0; ks < 4; ks++)
            ldmx4(smem_u32(&sK[STI(0,r) + ch + ks*16]),
                  qf[ks][0], qf[ks][1], qf[ks][2], qf[ks][3]);
    }
    __syncthreads();

    float oacc[8][4];
#pragma unroll
    for (int i = 0; i < 8; i++)
#pragma unroll
        for (int j = 0; j < 4; j++) oacc[i][j] = 0.0f;
    float m0 = -INFINITY, m1 = -INFINITY, l0 = 0.0f, l1 = 0.0f;

    const int nkv = iq + 1;

    // prologue: tile 0 -> stage 0
#pragma unroll
    for (int cc = 0; cc < 4; cc++) {
        int col = (lc0 + cc) * 8;
        cp16(smem_u32(&sK[STI(0,lrow) + col]), Kv + lrow*HD + col);
        cp16(smem_u32(&sV[STI(0,lrow) + col]), Vv + lrow*HD + col);
    }
    cp_commit();

    for (int t = 0; t < nkv; t++) {
        const int st = t & 1;
        if (t + 1 < nkv) {
            const int ns = (t + 1) & 1;
            const size_t go = (size_t)(t + 1) * 64 * HD;
#pragma unroll
            for (int cc = 0; cc < 4; cc++) {
                int col = (lc0 + cc) * 8;
                cp16(smem_u32(&sK[STI(ns,lrow) + col]), Kv + go + lrow*HD + col);
                cp16(smem_u32(&sV[STI(ns,lrow) + col]), Vv + go + lrow*HD + col);
            }
        }
        cp_commit();
        cp_wait1();
        __syncthreads();

        // S = Q K^T (fp16 single term)
        float sacc[8][4];
#pragma unroll
        for (int i = 0; i < 8; i++)
#pragma unroll
            for (int j = 0; j < 4; j++) sacc[i][j] = 0.0f;

        {
            const int grp = lane >> 3;
            const int rb  = (grp >> 1) * 8 + (lane & 7);
            const int cb  = (grp & 1) * 8;
#pragma unroll
            for (int ks = 0; ks < 4; ks++) {
#pragma unroll
                for (int p = 0; p < 4; p++) {
                    unsigned int kf[4];
                    ldmx4(smem_u32(&sK[STI(st,p*16+rb) + cb + ks*16]),
                          kf[0], kf[1], kf[2], kf[3]);
#pragma unroll
                    for (int s = 0; s < 2; s++)
                        mma16816h(sacc[2*p+s], qf[ks], kf[2*s], kf[2*s+1]);
                }
            }
        }

        const int quad = lane >> 2;
        const int cpair = (lane & 3) * 2;
        if (t == nkv - 1) {
            const int r0 = q0 + warp*16 + quad;
            const int kvb = t*64 + cpair;
#pragma unroll
            for (int nt = 0; nt < 8; nt++) {
#pragma unroll
                for (int j = 0; j < 2; j++) {
                    int kg = kvb + nt*8 + j;
                    sacc[nt][j]   = (kg > r0)     ? -INFINITY : sacc[nt][j]   * 0.125f;
                    sacc[nt][2+j] = (kg > r0 + 8) ? -INFINITY : sacc[nt][2+j] * 0.125f;
                }
            }
        } else {
#pragma unroll
            for (int nt = 0; nt < 8; nt++)
#pragma unroll
                for (int j = 0; j < 4; j++) sacc[nt][j] *= 0.125f;
        }

        // online softmax
        float mx0 = -INFINITY, mx1 = -INFINITY;
#pragma unroll
        for (int nt = 0; nt < 8; nt++) {
            mx0 = fmaxf(mx0, fmaxf(sacc[nt][0], sacc[nt][1]));
            mx1 = fmaxf(mx1, fmaxf(sacc[nt][2], sacc[nt][3]));
        }
        mx0 = fmaxf(mx0, __shfl_xor_sync(0xffffffffu, mx0, 1));
        mx0 = fmaxf(mx0, __shfl_xor_sync(0xffffffffu, mx0, 2));
        mx1 = fmaxf(mx1, __shfl_xor_sync(0xffffffffu, mx1, 1));
        mx1 = fmaxf(mx1, __shfl_xor_sync(0xffffffffu, mx1, 2));

        float mn0 = fmaxf(m0, mx0), mn1 = fmaxf(m1, mx1);
        float a0 = exp2f((m0 - mn0) * LOG2E);
        float a1 = exp2f((m1 - mn1) * LOG2E);
        m0 = mn0; m1 = mn1;

        float s0 = 0.0f, s1 = 0.0f;
#pragma unroll
        for (int nt = 0; nt < 8; nt++) {
            float p0 = exp2f((sacc[nt][0] - mn0) * LOG2E);
            float p1 = exp2f((sacc[nt][1] - mn0) * LOG2E);
            float p2 = exp2f((sacc[nt][2] - mn1) * LOG2E);
            float p3 = exp2f((sacc[nt][3] - mn1) * LOG2E);
            sacc[nt][0] = p0; sacc[nt][1] = p1; sacc[nt][2] = p2; sacc[nt][3] = p3;
            s0 += p0 + p1; s1 += p2 + p3;
        }
        s0 += __shfl_xor_sync(0xffffffffu, s0, 1);
        s0 += __shfl_xor_sync(0xffffffffu, s0, 2);
        s1 += __shfl_xor_sync(0xffffffffu, s1, 1);
        s1 += __shfl_xor_sync(0xffffffffu, s1, 2);
        l0 = l0 * a0 + s0;
        l1 = l1 * a1 + s1;

#pragma unroll
        for (int nt = 0; nt < 8; nt++) {
            oacc[nt][0] *= a0; oacc[nt][1] *= a0;
            oacc[nt][2] *= a1; oacc[nt][3] *= a1;
        }

        // pack P fragments (fp16)
        unsigned int pf[4][4];
#pragma unroll
        for (int ks = 0; ks < 4; ks++) {
#pragma unroll
            for (int half = 0; half < 2; half++) {
                pf[ks][half]   = pk2h(sacc[2*ks][2*half],   sacc[2*ks][2*half+1]);
                pf[ks][2+half] = pk2h(sacc[2*ks+1][2*half], sacc[2*ks+1][2*half+1]);
            }
        }

        // O += P V (fp16)
        {
            const int g   = lane >> 3;
            const int kvr = (g & 1) * 8 + (lane & 7);
            const int dcb = (g >> 1) * 8;
#pragma unroll
            for (int dt = 0; dt < 4; dt++) {
#pragma unroll
                for (int ks = 0; ks < 4; ks++) {
                    unsigned int vf[4];
                    ldmx4t(smem_u32(&sV[STI(st,ks*16+kvr) + dt*16 + dcb]),
                           vf[0], vf[1], vf[2], vf[3]);
#pragma unroll
                    for (int s = 0; s < 2; s++)
                        mma16816h(oacc[2*dt+s], pf[ks], vf[2*s], vf[2*s+1]);
                }
            }
        }
        __syncthreads();
    }

    // epilogue: O/l -> g_att16 (fp16) at [B,S,D]
    {
        const int quad = lane >> 2;
        const int cpair = (lane & 3) * 2;
        float il0 = 1.0f / l0, il1 = 1.0f / l1;
        int r0 = q0 + warp*16 + quad;
        unsigned short* AO = reinterpret_cast<unsigned short*>(g_att16);
#pragma unroll
        for (int nt = 0; nt < 8; nt++) {
            int d = nt*8 + cpair;
            size_t i0 = ((size_t)(b*SEQ) + r0)     * DIMN + h*HD + d;
            size_t i1 = ((size_t)(b*SEQ) + r0 + 8) * DIMN + h*HD + d;
            *reinterpret_cast<unsigned int*>(&AO[i0]) =
                pk2h(oacc[nt][0]*il0, oacc[nt][1]*il0);
            *reinterpret_cast<unsigned int*>(&AO[i1]) =
                pk2h(oacc[nt][2]*il1, oacc[nt][3]*il1);
        }
    }
}

// ---------------- launch ----------------------------------------------------
extern "C" void kernel_launch(void* const* d_in, const int* in_sizes, int n_in,
                              void* d_out, int out_size)
{
    const float* x  = (const float*)d_in[0];
    const float* Wq = (const float*)d_in[1];
    const float* Wk = (const float*)d_in[2];
    const float* Wv = (const float*)d_in[3];
    const float* Wo = (const float*)d_in[4];
    float* out = (float*)d_out;

    __nv_bfloat16 *xhi, *xlo, *whi, *wlo;
    __half *x16, *w16v, *w16o;
    cudaGetSymbolAddress((void**)&xhi, g_xhi);
    cudaGetSymbolAddress((void**)&xlo, g_xlo);
    cudaGetSymbolAddress((void**)&x16, g_x16);
    cudaGetSymbolAddress((void**)&whi, g_whi);
    cudaGetSymbolAddress((void**)&wlo, g_wlo);
    cudaGetSymbolAddress((void**)&w16v, g_w16v);
    cudaGetSymbolAddress((void**)&w16o, g_w16o);

    const int NW = DIMN * DIMN;
    const int NX = MROWS * DIMN;

    f32_split_h<<<(NX/4 + 255)/256, 256>>>(x, xhi, xlo, x16, NX/4);
    f32_split<<<(NW/4 + 255)/256, 256>>>(Wq, whi + 0*(size_t)NW, wlo + 0*(size_t)NW, NW/4);
    f32_split<<<(NW/4 + 255)/256, 256>>>(Wk, whi + 1*(size_t)NW, wlo + 1*(size_t)NW, NW/4);
    f32_to_h <<<(NW/4 + 255)/256, 256>>>(Wv, w16v, NW/4);
    f32_to_h <<<(NW/4 + 255)/256, 256>>>(Wo, w16o, NW/4);

    dim3 gqk(DIMN/128, MROWS/128, 2);
    qk_gemm_mma<<<gqk, 256>>>(xhi, xlo);

    dim3 gv(DIMN/128, MROWS/128);
    v_gemm_f16<<<gv, 256>>>(x16);

    int nrope = BATCH*SEQ*NH*(HD/2);
    rope_transpose<<<(nrope + 255)/256, 256>>>();

    const int FSM_BYTES = (2*64*FROWP + 2*64*FROWP) * 2;   // 36864
    cudaFuncSetAttribute(flash_attn_mma, cudaFuncAttributeMaxDynamicSharedMemorySize, FSM_BYTES);
    dim3 gfl(SEQ/64, NH, BATCH);
    flash_attn_mma<<<gfl, 128, FSM_BYTES>>>();

    dim3 gout(DIMN/128, MROWS/128);
    out_gemm_f16<<<gout, 256>>>(out);
}

// round 9
// speedup vs baseline: 2.2835x; 1.3688x over previous
#include <cuda_runtime.h>
#include <cuda_fp16.h>
#include <math.h>

#define DIMN  1024
#define NH    16
#define HD    64
#define BATCH 2
#define SEQ   2048
#define MROWS (BATCH*SEQ)   // 4096

// ---------------- scratch (device globals; no allocations allowed) ----------
__device__ float g_qlin[MROWS*DIMN];
__device__ float g_klin[MROWS*DIMN];

__device__ __half g_x16[MROWS*DIMN];
__device__ __half g_w16[4][DIMN*DIMN];     // Wq, Wk, Wv, Wo

// attention operands, [B,H,S,hd], fp16
__device__ __half g_q16 [MROWS*DIMN];
__device__ __half g_k16 [MROWS*DIMN];
__device__ __half g_v16 [MROWS*DIMN];
__device__ __half g_att16[MROWS*DIMN];     // attention out, [B,S,D], fp16

// ---------------- helpers ----------------------------------------------------
__device__ __forceinline__ unsigned int smem_u32(const void* p) {
    return (unsigned int)__cvta_generic_to_shared(p);
}
__device__ __forceinline__ void cp16(unsigned int s, const void* g) {
    asm volatile("cp.async.cg.shared.global [%0], [%1], 16;\n" :: "r"(s), "l"(g));
}
__device__ __forceinline__ void cp_commit() {
    asm volatile("cp.async.commit_group;\n");
}
__device__ __forceinline__ void cp_wait1() {
    asm volatile("cp.async.wait_group 1;\n");
}
__device__ __forceinline__ void cp_wait0() {
    asm volatile("cp.async.wait_group 0;\n");
}
__device__ __forceinline__ void ldmx4(unsigned int addr, unsigned int& r0, unsigned int& r1,
                                      unsigned int& r2, unsigned int& r3) {
    asm volatile("ldmatrix.sync.aligned.m8n8.x4.shared.b16 {%0,%1,%2,%3}, [%4];\n"
                 : "=r"(r0), "=r"(r1), "=r"(r2), "=r"(r3) : "r"(addr));
}
__device__ __forceinline__ void ldmx4t(unsigned int addr, unsigned int& r0, unsigned int& r1,
                                       unsigned int& r2, unsigned int& r3) {
    asm volatile("ldmatrix.sync.aligned.m8n8.x4.trans.shared.b16 {%0,%1,%2,%3}, [%4];\n"
                 : "=r"(r0), "=r"(r1), "=r"(r2), "=r"(r3) : "r"(addr));
}
__device__ __forceinline__ void mma16816h(float* c, const unsigned int* a,
                                          unsigned int b0, unsigned int b1) {
    asm volatile("mma.sync.aligned.m16n8k16.row.col.f32.f16.f16.f32 "
                 "{%0,%1,%2,%3}, {%4,%5,%6,%7}, {%8,%9}, {%0,%1,%2,%3};\n"
                 : "+f"(c[0]), "+f"(c[1]), "+f"(c[2]), "+f"(c[3])
                 : "r"(a[0]), "r"(a[1]), "r"(a[2]), "r"(a[3]), "r"(b0), "r"(b1));
}
__device__ __forceinline__ unsigned short hfbits(float f) {
    __half h = __float2half_rn(f);
    return *reinterpret_cast<unsigned short*>(&h);
}
__device__ __forceinline__ unsigned int pk2h(float a, float b) {
    return (unsigned int)hfbits(a) | ((unsigned int)hfbits(b) << 16);
}

// ---------------- conversion kernel ------------------------------------------
__global__ __launch_bounds__(256)
void f32_to_h(const float* __restrict__ src, __half* __restrict__ dst, int n4)
{
    int i = blockIdx.x * blockDim.x + threadIdx.x;
    if (i >= n4) return;
    float4 v = reinterpret_cast<const float4*>(src)[i];
    reinterpret_cast<ushort4*>(dst)[i] =
        make_ushort4(hfbits(v.x), hfbits(v.y), hfbits(v.z), hfbits(v.w));
}

// ---------------- single fp16 GEMM: C = A @ W^T -------------------------------
// mode 0: write fp32 C[M,DIMN]; mode 1: V scatter to g_v16 [B,H,S,hd];
// mode 2: write fp16 C (unused slots keep symmetry)
__device__ __forceinline__ void gemm_f16_body(const __half* __restrict__ A,
                                              const __half* __restrict__ W,
                                              float* __restrict__ C, int vmode)
{
    __shared__ __align__(128) __half sA[2][128][16];
    __shared__ __align__(128) __half sB[2][128][16];

    const int tid   = threadIdx.x;
    const int lane  = tid & 31;
    const int warp  = tid >> 5;
    const int wm    = warp >> 2;
    const int wn    = warp & 3;
    const int row0  = blockIdx.y * 128;
    const int col0  = blockIdx.x * 128;

    const int lrow = tid >> 1;
    const int lch  = tid & 1;
    const int lpc  = lch ^ ((lrow >> 2) & 1);
    const size_t aoff = (size_t)(row0 + lrow) * DIMN + lch * 8;
    const size_t boff = (size_t)(col0 + lrow) * DIMN + lch * 8;

    float acc[4][4][4];
#pragma unroll
    for (int i = 0; i < 4; i++)
#pragma unroll
        for (int j = 0; j < 4; j++)
#pragma unroll
            for (int k = 0; k < 4; k++) acc[i][j][k] = 0.0f;

    const unsigned int stg = (unsigned int)(128 * 16 * sizeof(__half));

    unsigned int aAddr[4], bAddr[2];
#pragma unroll
    for (int mt = 0; mt < 4; mt++) {
        int r  = wm * 64 + mt * 16 + (lane & 15);
        int ch = lane >> 4;
        int pc = ch ^ ((r >> 2) & 1);
        aAddr[mt] = smem_u32(&sA[0][r][pc * 8]);
    }
#pragma unroll
    for (int p = 0; p < 2; p++) {
        int grp = lane >> 3;
        int r   = wn * 32 + p * 16 + (grp >> 1) * 8 + (lane & 7);
        int ch  = grp & 1;
        int pc  = ch ^ ((r >> 2) & 1);
        bAddr[p] = smem_u32(&sB[0][r][pc * 8]);
    }

    {
        cp16(smem_u32(&sA[0][lrow][lpc * 8]), A + aoff);
        cp16(smem_u32(&sB[0][lrow][lpc * 8]), W + boff);
        cp_commit();
    }

    const int KT = DIMN / 16;
    for (int kt = 0; kt < KT; kt++) {
        int cur = kt & 1;
        if (kt + 1 < KT) {
            int nxt = (kt + 1) & 1;
            size_t ko = (size_t)(kt + 1) * 16;
            cp16(smem_u32(&sA[nxt][lrow][lpc * 8]), A + aoff + ko);
            cp16(smem_u32(&sB[nxt][lrow][lpc * 8]), W + boff + ko);
        }
        cp_commit();
        cp_wait1();
        __syncthreads();

        unsigned int coff = cur * stg;
        unsigned int ah[4][4], bf[2][4];
#pragma unroll
        for (int mt = 0; mt < 4; mt++)
            ldmx4(aAddr[mt] + coff, ah[mt][0], ah[mt][1], ah[mt][2], ah[mt][3]);
#pragma unroll
        for (int p = 0; p < 2; p++)
            ldmx4(bAddr[p] + coff, bf[p][0], bf[p][1], bf[p][2], bf[p][3]);
#pragma unroll
        for (int mt = 0; mt < 4; mt++) {
#pragma unroll
            for (int nt = 0; nt < 4; nt++) {
                int p = nt >> 1, s = nt & 1;
                mma16816h(acc[mt][nt], ah[mt], bf[p][2*s], bf[p][2*s+1]);
            }
        }
        __syncthreads();
    }

    if (!vmode) {
#pragma unroll
        for (int mt = 0; mt < 4; mt++) {
            int r = row0 + wm * 64 + mt * 16 + (lane >> 2);
#pragma unroll
            for (int nt = 0; nt < 4; nt++) {
                int c = col0 + wn * 32 + nt * 8 + (lane & 3) * 2;
                *reinterpret_cast<float2*>(&C[(size_t)r * DIMN + c]) =
                    make_float2(acc[mt][nt][0], acc[mt][nt][1]);
                *reinterpret_cast<float2*>(&C[(size_t)(r + 8) * DIMN + c]) =
                    make_float2(acc[mt][nt][2], acc[mt][nt][3]);
            }
        }
    } else {
        // V: fp16, scatter transposed into [B,H,S,hd]
#pragma unroll
        for (int mt = 0; mt < 4; mt++) {
            int r = row0 + wm * 64 + mt * 16 + (lane >> 2);
#pragma unroll
            for (int nt = 0; nt < 4; nt++) {
                int c = col0 + wn * 32 + nt * 8 + (lane & 3) * 2;
#pragma unroll
                for (int e = 0; e < 4; e++) {
                    int rr = r + (e >> 1) * 8;
                    int cc = c + (e & 1);
                    int b = rr >> 11, s = rr & (SEQ-1);
                    int h = cc >> 6,  d = cc & (HD-1);
                    size_t di = (((size_t)(b*NH + h))*SEQ + s)*HD + d;
                    reinterpret_cast<unsigned short*>(g_v16)[di] = hfbits(acc[mt][nt][e]);
                }
            }
        }
    }
}

__global__ __launch_bounds__(256)
void qkv_gemm_f16(const __half* __restrict__ x16)
{
    int z = blockIdx.z;
    if (z == 0)      gemm_f16_body(x16, g_w16[0], g_qlin, 0);
    else if (z == 1) gemm_f16_body(x16, g_w16[1], g_klin, 0);
    else             gemm_f16_body(x16, g_w16[2], nullptr, 1);
}

__global__ __launch_bounds__(256)
void out_gemm_f16(float* __restrict__ C)
{
    gemm_f16_body(g_att16, g_w16[3], C, 0);
}

// ---------------- RoPE + transpose to [B,H,S,hd], emit fp16 -----------------
__global__ void rope_transpose()
{
    int idx = blockIdx.x * blockDim.x + threadIdx.x;
    if (idx >= BATCH*SEQ*NH*(HD/2)) return;
    int d2 = idx & 31;
    int h  = (idx >> 5) & (NH-1);
    int s  = (idx >> 9) & (SEQ-1);
    int b  = idx >> 20;

    float inv = exp2f(-(float)d2 * (13.287712379549449f / 32.0f));
    float ang = (float)s * inv;
    float c  = cosf(ang);
    float sn = sinf(ang);

    size_t src = ((size_t)(b*SEQ + s))*DIMN + h*HD;
    size_t dst = (((size_t)(b*NH + h))*SEQ + s)*HD;

    float q1 = g_qlin[src + d2], q2 = g_qlin[src + d2 + 32];
    float k1 = g_klin[src + d2], k2 = g_klin[src + d2 + 32];

    unsigned short* qp = reinterpret_cast<unsigned short*>(g_q16);
    unsigned short* kp = reinterpret_cast<unsigned short*>(g_k16);
    qp[dst+d2]    = hfbits(q1*c - q2*sn);
    qp[dst+d2+32] = hfbits(q2*c + q1*sn);
    kp[dst+d2]    = hfbits(k1*c - k2*sn);
    kp[dst+d2+32] = hfbits(k2*c + k1*sn);
}

// ---------------- Flash attention (causal): all fp16 MMA --------------------
#define FROWP 72

__device__ __forceinline__ int STI(int st, int r) {
    return (st*64 + r) * FROWP;
}

__global__ __launch_bounds__(128)
void flash_attn_mma()
{
    const int iq = (int)gridDim.x - 1 - (int)blockIdx.x;   // heavy tiles first
    const int h = blockIdx.y, b = blockIdx.z;
    const int q0 = iq * 64;
    const int tid = threadIdx.x, lane = tid & 31, warp = tid >> 5;
    const float LOG2E = 1.4426950408889634f;

    extern __shared__ __align__(16) __half fsm[];
    __half* sK = fsm;                       // 2 stages x 64 x 72
    __half* sV = fsm + 2*64*FROWP;          // 2 stages x 64 x 72

    const size_t bh = (size_t)(b*NH + h) * SEQ * HD;
    const __half* Qv = g_q16 + bh + (size_t)q0*HD;
    const __half* Kv = g_k16 + bh;
    const __half* Vv = g_v16 + bh;

    const int lrow = tid >> 1;
    const int lc0  = (tid & 1) * 4;

    // stage Q through sK stage0
#pragma unroll
    for (int cc = 0; cc < 4; cc++) {
        int col = (lc0 + cc) * 8;
        cp16(smem_u32(&sK[STI(0,lrow) + col]), Qv + lrow*HD + col);
    }
    cp_commit(); cp_wait0();
    __syncthreads();

    unsigned int qf[4][4];
    {
        int r  = warp*16 + (lane & 15);
        int ch = (lane >> 4) * 8;
#pragma unroll
        for (int ks = 0; ks < 4; ks++)
            ldmx4(smem_u32(&sK[STI(0,r) + ch + ks*16]),
                  qf[ks][0], qf[ks][1], qf[ks][2], qf[ks][3]);
    }
    __syncthreads();

    float oacc[8][4];
#pragma unroll
    for (int i = 0; i < 8; i++)
#pragma unroll
        for (int j = 0; j < 4; j++) oacc[i][j] = 0.0f;
    float m0 = -INFINITY, m1 = -INFINITY, l0 = 0.0f, l1 = 0.0f;

    const int nkv = iq + 1;

    // prologue: tile 0 -> stage 0
#pragma unroll
    for (int cc = 0; cc < 4; cc++) {
        int col = (lc0 + cc) * 8;
        cp16(smem_u32(&sK[STI(0,lrow) + col]), Kv + lrow*HD + col);
        cp16(smem_u32(&sV[STI(0,lrow) + col]), Vv + lrow*HD + col);
    }
    cp_commit();

    for (int t = 0; t < nkv; t++) {
        const int st = t & 1;
        if (t + 1 < nkv) {
            const int ns = (t + 1) & 1;
            const size_t go = (size_t)(t + 1) * 64 * HD;
#pragma unroll
            for (int cc = 0; cc < 4; cc++) {
                int col = (lc0 + cc) * 8;
                cp16(smem_u32(&sK[STI(ns,lrow) + col]), Kv + go + lrow*HD + col);
                cp16(smem_u32(&sV[STI(ns,lrow) + col]), Vv + go + lrow*HD + col);
            }
        }
        cp_commit();
        cp_wait1();
        __syncthreads();

        // S = Q K^T (fp16 single term)
        float sacc[8][4];
#pragma unroll
        for (int i = 0; i < 8; i++)
#pragma unroll
            for (int j = 0; j < 4; j++) sacc[i][j] = 0.0f;

        {
            const int grp = lane >> 3;
            const int rb  = (grp >> 1) * 8 + (lane & 7);
            const int cb  = (grp & 1) * 8;
#pragma unroll
            for (int ks = 0; ks < 4; ks++) {
#pragma unroll
                for (int p = 0; p < 4; p++) {
                    unsigned int kf[4];
                    ldmx4(smem_u32(&sK[STI(st,p*16+rb) + cb + ks*16]),
                          kf[0], kf[1], kf[2], kf[3]);
#pragma unroll
                    for (int s = 0; s < 2; s++)
                        mma16816h(sacc[2*p+s], qf[ks], kf[2*s], kf[2*s+1]);
                }
            }
        }

        const int quad = lane >> 2;
        const int cpair = (lane & 3) * 2;
        if (t == nkv - 1) {
            const int r0 = q0 + warp*16 + quad;
            const int kvb = t*64 + cpair;
#pragma unroll
            for (int nt = 0; nt < 8; nt++) {
#pragma unroll
                for (int j = 0; j < 2; j++) {
                    int kg = kvb + nt*8 + j;
                    sacc[nt][j]   = (kg > r0)     ? -INFINITY : sacc[nt][j]   * 0.125f;
                    sacc[nt][2+j] = (kg > r0 + 8) ? -INFINITY : sacc[nt][2+j] * 0.125f;
                }
            }
        } else {
#pragma unroll
            for (int nt = 0; nt < 8; nt++)
#pragma unroll
                for (int j = 0; j < 4; j++) sacc[nt][j] *= 0.125f;
        }

        // online softmax
        float mx0 = -INFINITY, mx1 = -INFINITY;
#pragma unroll
        for (int nt = 0; nt < 8; nt++) {
            mx0 = fmaxf(mx0, fmaxf(sacc[nt][0], sacc[nt][1]));
            mx1 = fmaxf(mx1, fmaxf(sacc[nt][2], sacc[nt][3]));
        }
        mx0 = fmaxf(mx0, __shfl_xor_sync(0xffffffffu, mx0, 1));
        mx0 = fmaxf(mx0, __shfl_xor_sync(0xffffffffu, mx0, 2));
        mx1 = fmaxf(mx1, __shfl_xor_sync(0xffffffffu, mx1, 1));
        mx1 = fmaxf(mx1, __shfl_xor_sync(0xffffffffu, mx1, 2));

        float mn0 = fmaxf(m0, mx0), mn1 = fmaxf(m1, mx1);
        float a0 = exp2f((m0 - mn0) * LOG2E);
        float a1 = exp2f((m1 - mn1) * LOG2E);
        m0 = mn0; m1 = mn1;

        float s0 = 0.0f, s1 = 0.0f;
#pragma unroll
        for (int nt = 0; nt < 8; nt++) {
            float p0 = exp2f((sacc[nt][0] - mn0) * LOG2E);
            float p1 = exp2f((sacc[nt][1] - mn0) * LOG2E);
            float p2 = exp2f((sacc[nt][2] - mn1) * LOG2E);
            float p3 = exp2f((sacc[nt][3] - mn1) * LOG2E);
            sacc[nt][0] = p0; sacc[nt][1] = p1; sacc[nt][2] = p2; sacc[nt][3] = p3;
            s0 += p0 + p1; s1 += p2 + p3;
        }
        s0 += __shfl_xor_sync(0xffffffffu, s0, 1);
        s0 += __shfl_xor_sync(0xffffffffu, s0, 2);
        s1 += __shfl_xor_sync(0xffffffffu, s1, 1);
        s1 += __shfl_xor_sync(0xffffffffu, s1, 2);
        l0 = l0 * a0 + s0;
        l1 = l1 * a1 + s1;

#pragma unroll
        for (int nt = 0; nt < 8; nt++) {
            oacc[nt][0] *= a0; oacc[nt][1] *= a0;
            oacc[nt][2] *= a1; oacc[nt][3] *= a1;
        }

        // pack P fragments (fp16)
        unsigned int pf[4][4];
#pragma unroll
        for (int ks = 0; ks < 4; ks++) {
#pragma unroll
            for (int half = 0; half < 2; half++) {
                pf[ks][half]   = pk2h(sacc[2*ks][2*half],   sacc[2*ks][2*half+1]);
                pf[ks][2+half] = pk2h(sacc[2*ks+1][2*half], sacc[2*ks+1][2*half+1]);
            }
        }

        // O += P V (fp16)
        {
            const int g   = lane >> 3;
            const int kvr = (g & 1) * 8 + (lane & 7);
            const int dcb = (g >> 1) * 8;
#pragma unroll
            for (int dt = 0; dt < 4; dt++) {
#pragma unroll
                for (int ks = 0; ks < 4; ks++) {
                    unsigned int vf[4];
                    ldmx4t(smem_u32(&sV[STI(st,ks*16+kvr) + dt*16 + dcb]),
                           vf[0], vf[1], vf[2], vf[3]);
#pragma unroll
                    for (int s = 0; s < 2; s++)
                        mma16816h(oacc[2*dt+s], pf[ks], vf[2*s], vf[2*s+1]);
                }
            }
        }
        __syncthreads();
    }

    // epilogue: O/l -> g_att16 (fp16) at [B,S,D]
    {
        const int quad = lane >> 2;
        const int cpair = (lane & 3) * 2;
        float il0 = 1.0f / l0, il1 = 1.0f / l1;
        int r0 = q0 + warp*16 + quad;
        unsigned short* AO = reinterpret_cast<unsigned short*>(g_att16);
#pragma unroll
        for (int nt = 0; nt < 8; nt++) {
            int d = nt*8 + cpair;
            size_t i0 = ((size_t)(b*SEQ) + r0)     * DIMN + h*HD + d;
            size_t i1 = ((size_t)(b*SEQ) + r0 + 8) * DIMN + h*HD + d;
            *reinterpret_cast<unsigned int*>(&AO[i0]) =
                pk2h(oacc[nt][0]*il0, oacc[nt][1]*il0);
            *reinterpret_cast<unsigned int*>(&AO[i1]) =
                pk2h(oacc[nt][2]*il1, oacc[nt][3]*il1);
        }
    }
}

// ---------------- launch ----------------------------------------------------
extern "C" void kernel_launch(void* const* d_in, const int* in_sizes, int n_in,
                              void* d_out, int out_size)
{
    const float* x  = (const float*)d_in[0];
    const float* Wq = (const float*)d_in[1];
    const float* Wk = (const float*)d_in[2];
    const float* Wv = (const float*)d_in[3];
    const float* Wo = (const float*)d_in[4];
    float* out = (float*)d_out;

    __half *x16, *w16;
    cudaGetSymbolAddress((void**)&x16, g_x16);
    cudaGetSymbolAddress((void**)&w16, g_w16);

    const int NW = DIMN * DIMN;
    const int NX = MROWS * DIMN;

    f32_to_h<<<(NX/4 + 255)/256, 256>>>(x,  x16, NX/4);
    f32_to_h<<<(NW/4 + 255)/256, 256>>>(Wq, w16 + 0*(size_t)NW, NW/4);
    f32_to_h<<<(NW/4 + 255)/256, 256>>>(Wk, w16 + 1*(size_t)NW, NW/4);
    f32_to_h<<<(NW/4 + 255)/256, 256>>>(Wv, w16 + 2*(size_t)NW, NW/4);
    f32_to_h<<<(NW/4 + 255)/256, 256>>>(Wo, w16 + 3*(size_t)NW, NW/4);

    dim3 gqkv(DIMN/128, MROWS/128, 3);
    qkv_gemm_f16<<<gqkv, 256>>>(x16);

    int nrope = BATCH*SEQ*NH*(HD/2);
    rope_transpose<<<(nrope + 255)/256, 256>>>();

    const int FSM_BYTES = (2*64*FROWP + 2*64*FROWP) * 2;   // 36864
    cudaFuncSetAttribute(flash_attn_mma, cudaFuncAttributeMaxDynamicSharedMemorySize, FSM_BYTES);
    dim3 gfl(SEQ/64, NH, BATCH);
    flash_attn_mma<<<gfl, 128, FSM_BYTES>>>();

    dim3 gout(DIMN/128, MROWS/128);
    out_gemm_f16<<<gout, 256>>>(out);
}

// round 10
// speedup vs baseline: 2.3043x; 1.0091x over previous
#include <cuda_runtime.h>
#include <cuda_fp16.h>
#include <math.h>

#define DIMN  1024
#define NH    16
#define HD    64
#define BATCH 2
#define SEQ   2048
#define MROWS (BATCH*SEQ)   // 4096

// ---------------- scratch (device globals; no allocations allowed) ----------
__device__ __half g_x16[MROWS*DIMN];
__device__ __half g_w16[4][DIMN*DIMN];     // Wq, Wk, Wv, Wo
__device__ float2 g_rope[SEQ*32];          // (cos, sin) per (s, d2)

// attention operands, [B,H,S,hd], fp16
__device__ __half g_q16 [MROWS*DIMN];      // pre-scaled by 0.125
__device__ __half g_k16 [MROWS*DIMN];
__device__ __half g_v16 [MROWS*DIMN];
__device__ __half g_att16[MROWS*DIMN];     // attention out, [B,S,D], fp16

// ---------------- helpers ----------------------------------------------------
__device__ __forceinline__ unsigned int smem_u32(const void* p) {
    return (unsigned int)__cvta_generic_to_shared(p);
}
__device__ __forceinline__ void cp16(unsigned int s, const void* g) {
    asm volatile("cp.async.cg.shared.global [%0], [%1], 16;\n" :: "r"(s), "l"(g));
}
__device__ __forceinline__ void cp_commit() {
    asm volatile("cp.async.commit_group;\n");
}
__device__ __forceinline__ void cp_wait1() {
    asm volatile("cp.async.wait_group 1;\n");
}
__device__ __forceinline__ void cp_wait0() {
    asm volatile("cp.async.wait_group 0;\n");
}
__device__ __forceinline__ void ldmx4(unsigned int addr, unsigned int& r0, unsigned int& r1,
                                      unsigned int& r2, unsigned int& r3) {
    asm volatile("ldmatrix.sync.aligned.m8n8.x4.shared.b16 {%0,%1,%2,%3}, [%4];\n"
                 : "=r"(r0), "=r"(r1), "=r"(r2), "=r"(r3) : "r"(addr));
}
__device__ __forceinline__ void ldmx4t(unsigned int addr, unsigned int& r0, unsigned int& r1,
                                       unsigned int& r2, unsigned int& r3) {
    asm volatile("ldmatrix.sync.aligned.m8n8.x4.trans.shared.b16 {%0,%1,%2,%3}, [%4];\n"
                 : "=r"(r0), "=r"(r1), "=r"(r2), "=r"(r3) : "r"(addr));
}
__device__ __forceinline__ void mma16816h(float* c, const unsigned int* a,
                                          unsigned int b0, unsigned int b1) {
    asm volatile("mma.sync.aligned.m16n8k16.row.col.f32.f16.f16.f32 "
                 "{%0,%1,%2,%3}, {%4,%5,%6,%7}, {%8,%9}, {%0,%1,%2,%3};\n"
                 : "+f"(c[0]), "+f"(c[1]), "+f"(c[2]), "+f"(c[3])
                 : "r"(a[0]), "r"(a[1]), "r"(a[2]), "r"(a[3]), "r"(b0), "r"(b1));
}
__device__ __forceinline__ unsigned short hfbits(float f) {
    __half h = __float2half_rn(f);
    return *reinterpret_cast<unsigned short*>(&h);
}
__device__ __forceinline__ unsigned int pk2h(float a, float b) {
    return (unsigned int)hfbits(a) | ((unsigned int)hfbits(b) << 16);
}

// ---------------- one-pass conversion: x + 4 weights -> fp16 -----------------
__global__ __launch_bounds__(256)
void conv_all(const float* __restrict__ x,  const float* __restrict__ wq,
              const float* __restrict__ wk, const float* __restrict__ wv,
              const float* __restrict__ wo)
{
    const int NX4 = MROWS*DIMN/4;       // 1<<20
    const int NW4 = DIMN*DIMN/4;        // 1<<18
    int i = blockIdx.x * blockDim.x + threadIdx.x;
    if (i >= NX4 + 4*NW4) return;
    const float* src; ushort4* dst; int off;
    if (i < NX4) {
        src = x; off = i;
        dst = reinterpret_cast<ushort4*>(g_x16);
    } else {
        int j = i - NX4;
        int w = j >> 18;
        off = j & (NW4 - 1);
        src = (w == 0) ? wq : (w == 1) ? wk : (w == 2) ? wv : wo;
        dst = reinterpret_cast<ushort4*>(&g_w16[w][0]);
    }
    float4 v = reinterpret_cast<const float4*>(src)[off];
    dst[off] = make_ushort4(hfbits(v.x), hfbits(v.y), hfbits(v.z), hfbits(v.w));
}

// ---------------- rope table --------------------------------------------------
__global__ __launch_bounds__(256)
void rope_tab()
{
    int idx = blockIdx.x * blockDim.x + threadIdx.x;
    if (idx >= SEQ*32) return;
    int d2 = idx & 31, s = idx >> 5;
    float inv = exp2f(-(float)d2 * 0.41524101186091403f);  // log2(10000)/32
    float ang = (float)s * inv;
    g_rope[idx] = make_float2(cosf(ang), sinf(ang));
}

// ---------------- fp16 GEMM: C = A @ W^T --------------------------------------
// mode 0: fp32 C[M,DIMN]; 1: V scatter -> g_v16 [B,H,S,hd];
// mode 2: Q rope (x0.125) -> g_q16;  3: K rope -> g_k16
#define SSTR 132

__device__ __forceinline__ void gemm_f16_body(const __half* __restrict__ A,
                                              const __half* __restrict__ W,
                                              float* __restrict__ C, int mode)
{
    extern __shared__ __align__(16) char gsm[];
    __half* sAb = reinterpret_cast<__half*>(gsm);          // [2][128][16]
    __half* sBb = reinterpret_cast<__half*>(gsm + 8192);   // [2][128][16]
    float*  stage = reinterpret_cast<float*>(gsm);         // reused post-pipeline

    const int tid   = threadIdx.x;
    const int lane  = tid & 31;
    const int warp  = tid >> 5;
    const int wm    = warp >> 2;
    const int wn    = warp & 3;
    const int row0  = blockIdx.y * 128;
    const int col0  = blockIdx.x * 128;

    const int lrow = tid >> 1;
    const int lch  = tid & 1;
    const int lpc  = lch ^ ((lrow >> 2) & 1);
    const size_t aoff = (size_t)(row0 + lrow) * DIMN + lch * 8;
    const size_t boff = (size_t)(col0 + lrow) * DIMN + lch * 8;

    float acc[4][4][4];
#pragma unroll
    for (int i = 0; i < 4; i++)
#pragma unroll
        for (int j = 0; j < 4; j++)
#pragma unroll
            for (int k = 0; k < 4; k++) acc[i][j][k] = 0.0f;

    const unsigned int stg = 4096;   // bytes per stage (128*16 halves)

    unsigned int aAddr[4], bAddr[2];
#pragma unroll
    for (int mt = 0; mt < 4; mt++) {
        int r  = wm * 64 + mt * 16 + (lane & 15);
        int ch = lane >> 4;
        int pc = ch ^ ((r >> 2) & 1);
        aAddr[mt] = smem_u32(sAb + r * 16 + pc * 8);
    }
#pragma unroll
    for (int p = 0; p < 2; p++) {
        int grp = lane >> 3;
        int r   = wn * 32 + p * 16 + (grp >> 1) * 8 + (lane & 7);
        int ch  = grp & 1;
        int pc  = ch ^ ((r >> 2) & 1);
        bAddr[p] = smem_u32(sBb + r * 16 + pc * 8);
    }

    {
        cp16(smem_u32(sAb + lrow * 16 + lpc * 8), A + aoff);
        cp16(smem_u32(sBb + lrow * 16 + lpc * 8), W + boff);
        cp_commit();
    }

    const int KT = DIMN / 16;
    for (int kt = 0; kt < KT; kt++) {
        int cur = kt & 1;
        if (kt + 1 < KT) {
            int nxt = (kt + 1) & 1;
            size_t ko = (size_t)(kt + 1) * 16;
            cp16(smem_u32(sAb + nxt * 2048 + lrow * 16 + lpc * 8), A + aoff + ko);
            cp16(smem_u32(sBb + nxt * 2048 + lrow * 16 + lpc * 8), W + boff + ko);
        }
        cp_commit();
        cp_wait1();
        __syncthreads();

        unsigned int coff = cur * stg;
        unsigned int ah[4][4], bf[2][4];
#pragma unroll
        for (int mt = 0; mt < 4; mt++)
            ldmx4(aAddr[mt] + coff, ah[mt][0], ah[mt][1], ah[mt][2], ah[mt][3]);
#pragma unroll
        for (int p = 0; p < 2; p++)
            ldmx4(bAddr[p] + coff, bf[p][0], bf[p][1], bf[p][2], bf[p][3]);
#pragma unroll
        for (int mt = 0; mt < 4; mt++) {
#pragma unroll
            for (int nt = 0; nt < 4; nt++) {
                int p = nt >> 1, s = nt & 1;
                mma16816h(acc[mt][nt], ah[mt], bf[p][2*s], bf[p][2*s+1]);
            }
        }
        __syncthreads();
    }

    if (mode == 0) {
#pragma unroll
        for (int mt = 0; mt < 4; mt++) {
            int r = row0 + wm * 64 + mt * 16 + (lane >> 2);
#pragma unroll
            for (int nt = 0; nt < 4; nt++) {
                int c = col0 + wn * 32 + nt * 8 + (lane & 3) * 2;
                *reinterpret_cast<float2*>(&C[(size_t)r * DIMN + c]) =
                    make_float2(acc[mt][nt][0], acc[mt][nt][1]);
                *reinterpret_cast<float2*>(&C[(size_t)(r + 8) * DIMN + c]) =
                    make_float2(acc[mt][nt][2], acc[mt][nt][3]);
            }
        }
    } else if (mode == 1) {
        // V: fp16, scatter transposed into [B,H,S,hd]
#pragma unroll
        for (int mt = 0; mt < 4; mt++) {
            int r = row0 + wm * 64 + mt * 16 + (lane >> 2);
#pragma unroll
            for (int nt = 0; nt < 4; nt++) {
                int c = col0 + wn * 32 + nt * 8 + (lane & 3) * 2;
#pragma unroll
                for (int e = 0; e < 4; e++) {
                    int rr = r + (e >> 1) * 8;
                    int cc = c + (e & 1);
                    int b = rr >> 11, s = rr & (SEQ-1);
                    int h = cc >> 6,  d = cc & (HD-1);
                    size_t di = (((size_t)(b*NH + h))*SEQ + s)*HD + d;
                    reinterpret_cast<unsigned short*>(g_v16)[di] = hfbits(acc[mt][nt][e]);
                }
            }
        }
    } else {
        // Q/K: stage fp32 tile, apply RoPE, write fp16 transposed
#pragma unroll
        for (int mt = 0; mt < 4; mt++) {
            int r = wm * 64 + mt * 16 + (lane >> 2);
#pragma unroll
            for (int nt = 0; nt < 4; nt++) {
                int c = wn * 32 + nt * 8 + (lane & 3) * 2;
                stage[r*SSTR + c]       = acc[mt][nt][0];
                stage[r*SSTR + c + 1]   = acc[mt][nt][1];
                stage[(r+8)*SSTR + c]   = acc[mt][nt][2];
                stage[(r+8)*SSTR + c+1] = acc[mt][nt][3];
            }
        }
        __syncthreads();

        const float qs = (mode == 2) ? 0.125f : 1.0f;
        __half* dstg = (mode == 2) ? g_q16 : g_k16;
        unsigned short* dp = reinterpret_cast<unsigned short*>(dstg);
#pragma unroll 4
        for (int i = 0; i < 64; i++) {
            int idx = i * 256 + tid;
            int r = idx >> 7, c = idx & 127;
            int sg = row0 + r;
            int b = sg >> 11, s = sg & (SEQ-1);
            int cg = col0 + c;
            int h = cg >> 6, d = cg & (HD-1);
            float2 cs = g_rope[s*32 + (d & 31)];
            float a = stage[r*SSTR + c];
            float p = stage[r*SSTR + (c ^ 32)];
            float out = (d < 32) ? (a*cs.x - p*cs.y) : (a*cs.x + p*cs.y);
            out *= qs;
            size_t di = (((size_t)(b*NH + h))*SEQ + s)*HD + d;
            dp[di] = hfbits(out);
        }
    }
}

__global__ __launch_bounds__(256)
void qkv_gemm_f16(const __half* __restrict__ x16)
{
    int z = blockIdx.z;
    if (z == 0)      gemm_f16_body(x16, g_w16[0], nullptr, 2);   // Q + rope
    else if (z == 1) gemm_f16_body(x16, g_w16[1], nullptr, 3);   // K + rope
    else             gemm_f16_body(x16, g_w16[2], nullptr, 1);   // V
}

__global__ __launch_bounds__(256)
void out_gemm_f16(float* __restrict__ C)
{
    gemm_f16_body(g_att16, g_w16[3], C, 0);
}

// ---------------- Flash attention (causal): all fp16 MMA --------------------
// Q pre-scaled by 0.125, so no score scaling here.
#define FROWP 72

__device__ __forceinline__ int STI(int st, int r) {
    return (st*64 + r) * FROWP;
}

__global__ __launch_bounds__(128)
void flash_attn_mma()
{
    const int iq = (int)gridDim.x - 1 - (int)blockIdx.x;   // heavy tiles first
    const int h = blockIdx.y, b = blockIdx.z;
    const int q0 = iq * 64;
    const int tid = threadIdx.x, lane = tid & 31, warp = tid >> 5;
    const float LOG2E = 1.4426950408889634f;

    extern __shared__ __align__(16) __half fsm[];
    __half* sK = fsm;                       // 2 stages x 64 x 72
    __half* sV = fsm + 2*64*FROWP;

    const size_t bh = (size_t)(b*NH + h) * SEQ * HD;
    const __half* Qv = g_q16 + bh + (size_t)q0*HD;
    const __half* Kv = g_k16 + bh;
    const __half* Vv = g_v16 + bh;

    const int lrow = tid >> 1;
    const int lc0  = (tid & 1) * 4;

#pragma unroll
    for (int cc = 0; cc < 4; cc++) {
        int col = (lc0 + cc) * 8;
        cp16(smem_u32(&sK[STI(0,lrow) + col]), Qv + lrow*HD + col);
    }
    cp_commit(); cp_wait0();
    __syncthreads();

    unsigned int qf[4][4];
    {
        int r  = warp*16 + (lane & 15);
        int ch = (lane >> 4) * 8;
#pragma unroll
        for (int ks = 0; ks < 4; ks++)
            ldmx4(smem_u32(&sK[STI(0,r) + ch + ks*16]),
                  qf[ks][0], qf[ks][1], qf[ks][2], qf[ks][3]);
    }
    __syncthreads();

    float oacc[8][4];
#pragma unroll
    for (int i = 0; i < 8; i++)
#pragma unroll
        for (int j = 0; j < 4; j++) oacc[i][j] = 0.0f;
    float m0 = -INFINITY, m1 = -INFINITY, l0 = 0.0f, l1 = 0.0f;

    const int nkv = iq + 1;

#pragma unroll
    for (int cc = 0; cc < 4; cc++) {
        int col = (lc0 + cc) * 8;
        cp16(smem_u32(&sK[STI(0,lrow) + col]), Kv + lrow*HD + col);
        cp16(smem_u32(&sV[STI(0,lrow) + col]), Vv + lrow*HD + col);
    }
    cp_commit();

    for (int t = 0; t < nkv; t++) {
        const int st = t & 1;
        if (t + 1 < nkv) {
            const int ns = (t + 1) & 1;
            const size_t go = (size_t)(t + 1) * 64 * HD;
#pragma unroll
            for (int cc = 0; cc < 4; cc++) {
                int col = (lc0 + cc) * 8;
                cp16(smem_u32(&sK[STI(ns,lrow) + col]), Kv + go + lrow*HD + col);
                cp16(smem_u32(&sV[STI(ns,lrow) + col]), Vv + go + lrow*HD + col);
            }
        }
        cp_commit();
        cp_wait1();
        __syncthreads();

        // S = Q K^T (fp16)
        float sacc[8][4];
#pragma unroll
        for (int i = 0; i < 8; i++)
#pragma unroll
            for (int j = 0; j < 4; j++) sacc[i][j] = 0.0f;

        {
            const int grp = lane >> 3;
            const int rb  = (grp >> 1) * 8 + (lane & 7);
            const int cb  = (grp & 1) * 8;
#pragma unroll
            for (int ks = 0; ks < 4; ks++) {
#pragma unroll
                for (int p = 0; p < 4; p++) {
                    unsigned int kf[4];
                    ldmx4(smem_u32(&sK[STI(st,p*16+rb) + cb + ks*16]),
                          kf[0], kf[1], kf[2], kf[3]);
#pragma unroll
                    for (int s = 0; s < 2; s++)
                        mma16816h(sacc[2*p+s], qf[ks], kf[2*s], kf[2*s+1]);
                }
            }
        }

        const int quad = lane >> 2;
        const int cpair = (lane & 3) * 2;
        if (t == nkv - 1) {
            const int r0 = q0 + warp*16 + quad;
            const int kvb = t*64 + cpair;
#pragma unroll
            for (int nt = 0; nt < 8; nt++) {
#pragma unroll
                for (int j = 0; j < 2; j++) {
                    int kg = kvb + nt*8 + j;
                    if (kg > r0)     sacc[nt][j]   = -INFINITY;
                    if (kg > r0 + 8) sacc[nt][2+j] = -INFINITY;
                }
            }
        }

        // online softmax
        float mx0 = -INFINITY, mx1 = -INFINITY;
#pragma unroll
        for (int nt = 0; nt < 8; nt++) {
            mx0 = fmaxf(mx0, fmaxf(sacc[nt][0], sacc[nt][1]));
            mx1 = fmaxf(mx1, fmaxf(sacc[nt][2], sacc[nt][3]));
        }
        mx0 = fmaxf(mx0, __shfl_xor_sync(0xffffffffu, mx0, 1));
        mx0 = fmaxf(mx0, __shfl_xor_sync(0xffffffffu, mx0, 2));
        mx1 = fmaxf(mx1, __shfl_xor_sync(0xffffffffu, mx1, 1));
        mx1 = fmaxf(mx1, __shfl_xor_sync(0xffffffffu, mx1, 2));

        float mn0 = fmaxf(m0, mx0), mn1 = fmaxf(m1, mx1);
        float a0 = exp2f((m0 - mn0) * LOG2E);
        float a1 = exp2f((m1 - mn1) * LOG2E);
        m0 = mn0; m1 = mn1;

        float s0 = 0.0f, s1 = 0.0f;
#pragma unroll
        for (int nt = 0; nt < 8; nt++) {
            float p0 = exp2f((sacc[nt][0] - mn0) * LOG2E);
            float p1 = exp2f((sacc[nt][1] - mn0) * LOG2E);
            float p2 = exp2f((sacc[nt][2] - mn1) * LOG2E);
            float p3 = exp2f((sacc[nt][3] - mn1) * LOG2E);
            sacc[nt][0] = p0; sacc[nt][1] = p1; sacc[nt][2] = p2; sacc[nt][3] = p3;
            s0 += p0 + p1; s1 += p2 + p3;
        }
        s0 += __shfl_xor_sync(0xffffffffu, s0, 1);
        s0 += __shfl_xor_sync(0xffffffffu, s0, 2);
        s1 += __shfl_xor_sync(0xffffffffu, s1, 1);
        s1 += __shfl_xor_sync(0xffffffffu, s1, 2);
        l0 = l0 * a0 + s0;
        l1 = l1 * a1 + s1;

#pragma unroll
        for (int nt = 0; nt < 8; nt++) {
            oacc[nt][0] *= a0; oacc[nt][1] *= a0;
            oacc[nt][2] *= a1; oacc[nt][3] *= a1;
        }

        unsigned int pf[4][4];
#pragma unroll
        for (int ks = 0; ks < 4; ks++) {
#pragma unroll
            for (int half = 0; half < 2; half++) {
                pf[ks][half]   = pk2h(sacc[2*ks][2*half],   sacc[2*ks][2*half+1]);
                pf[ks][2+half] = pk2h(sacc[2*ks+1][2*half], sacc[2*ks+1][2*half+1]);
            }
        }

        // O += P V (fp16)
        {
            const int g   = lane >> 3;
            const int kvr = (g & 1) * 8 + (lane & 7);
            const int dcb = (g >> 1) * 8;
#pragma unroll
            for (int dt = 0; dt < 4; dt++) {
#pragma unroll
                for (int ks = 0; ks < 4; ks++) {
                    unsigned int vf[4];
                    ldmx4t(smem_u32(&sV[STI(st,ks*16+kvr) + dt*16 + dcb]),
                           vf[0], vf[1], vf[2], vf[3]);
#pragma unroll
                    for (int s = 0; s < 2; s++)
                        mma16816h(oacc[2*dt+s], pf[ks], vf[2*s], vf[2*s+1]);
                }
            }
        }
        __syncthreads();
    }

    // epilogue: O/l -> g_att16 (fp16) at [B,S,D]
    {
        const int quad = lane >> 2;
        const int cpair = (lane & 3) * 2;
        float il0 = 1.0f / l0, il1 = 1.0f / l1;
        int r0 = q0 + warp*16 + quad;
        unsigned short* AO = reinterpret_cast<unsigned short*>(g_att16);
#pragma unroll
        for (int nt = 0; nt < 8; nt++) {
            int d = nt*8 + cpair;
            size_t i0 = ((size_t)(b*SEQ) + r0)     * DIMN + h*HD + d;
            size_t i1 = ((size_t)(b*SEQ) + r0 + 8) * DIMN + h*HD + d;
            *reinterpret_cast<unsigned int*>(&AO[i0]) =
                pk2h(oacc[nt][0]*il0, oacc[nt][1]*il0);
            *reinterpret_cast<unsigned int*>(&AO[i1]) =
                pk2h(oacc[nt][2]*il1, oacc[nt][3]*il1);
        }
    }
}

// ---------------- launch ----------------------------------------------------
extern "C" void kernel_launch(void* const* d_in, const int* in_sizes, int n_in,
                              void* d_out, int out_size)
{
    const float* x  = (const float*)d_in[0];
    const float* Wq = (const float*)d_in[1];
    const float* Wk = (const float*)d_in[2];
    const float* Wv = (const float*)d_in[3];
    const float* Wo = (const float*)d_in[4];
    float* out = (float*)d_out;

    __half* x16;
    cudaGetSymbolAddress((void**)&x16, g_x16);

    const int NTOT4 = (MROWS*DIMN + 4*DIMN*DIMN) / 4;   // 2M
    conv_all<<<(NTOT4 + 255)/256, 256>>>(x, Wq, Wk, Wv, Wo);
    rope_tab<<<(SEQ*32 + 255)/256, 256>>>();

    const int QKV_SMEM = 128 * SSTR * 4;   // 67584 (stage tile; > pipeline 16KB)
    cudaFuncSetAttribute(qkv_gemm_f16, cudaFuncAttributeMaxDynamicSharedMemorySize, QKV_SMEM);
    dim3 gqkv(DIMN/128, MROWS/128, 3);
    qkv_gemm_f16<<<gqkv, 256, QKV_SMEM>>>(x16);

    const int FSM_BYTES = (2*64*FROWP + 2*64*FROWP) * 2;   // 36864
    cudaFuncSetAttribute(flash_attn_mma, cudaFuncAttributeMaxDynamicSharedMemorySize, FSM_BYTES);
    dim3 gfl(SEQ/64, NH, BATCH);
    flash_attn_mma<<<gfl, 128, FSM_BYTES>>>();

    dim3 gout(DIMN/128, MROWS/128);
    out_gemm_f16<<<gout, 256, 16384>>>(out);
}

// round 11
// speedup vs baseline: 2.5887x; 1.1234x over previous
#include <cuda_runtime.h>
#include <cuda_fp16.h>
#include <math.h>

#define DIMN  1024
#define NH    16
#define HD    64
#define BATCH 2
#define SEQ   2048
#define MROWS (BATCH*SEQ)   // 4096

// ---------------- scratch (device globals; no allocations allowed) ----------
__device__ __half g_x16[MROWS*DIMN];
__device__ __half g_w16[4][DIMN*DIMN];     // Wq, Wk, Wv, Wo
__device__ float2 g_rope[SEQ*32];          // (cos, sin) per (s, d2)

// attention operands, [B,H,S,hd], fp16
__device__ __half g_q16 [MROWS*DIMN];      // pre-scaled by 0.125
__device__ __half g_k16 [MROWS*DIMN];
__device__ __half g_v16 [MROWS*DIMN];
__device__ __half g_att16[MROWS*DIMN];     // attention out, [B,S,D], fp16

// ---------------- helpers ----------------------------------------------------
__device__ __forceinline__ unsigned int smem_u32(const void* p) {
    return (unsigned int)__cvta_generic_to_shared(p);
}
__device__ __forceinline__ void cp16(unsigned int s, const void* g) {
    asm volatile("cp.async.cg.shared.global [%0], [%1], 16;\n" :: "r"(s), "l"(g));
}
__device__ __forceinline__ void cp_commit() {
    asm volatile("cp.async.commit_group;\n");
}
__device__ __forceinline__ void cp_wait1() {
    asm volatile("cp.async.wait_group 1;\n");
}
__device__ __forceinline__ void cp_wait0() {
    asm volatile("cp.async.wait_group 0;\n");
}
__device__ __forceinline__ void ldmx4(unsigned int addr, unsigned int& r0, unsigned int& r1,
                                      unsigned int& r2, unsigned int& r3) {
    asm volatile("ldmatrix.sync.aligned.m8n8.x4.shared.b16 {%0,%1,%2,%3}, [%4];\n"
                 : "=r"(r0), "=r"(r1), "=r"(r2), "=r"(r3) : "r"(addr));
}
__device__ __forceinline__ void ldmx4t(unsigned int addr, unsigned int& r0, unsigned int& r1,
                                       unsigned int& r2, unsigned int& r3) {
    asm volatile("ldmatrix.sync.aligned.m8n8.x4.trans.shared.b16 {%0,%1,%2,%3}, [%4];\n"
                 : "=r"(r0), "=r"(r1), "=r"(r2), "=r"(r3) : "r"(addr));
}
__device__ __forceinline__ void mma16816h(float* c, const unsigned int* a,
                                          unsigned int b0, unsigned int b1) {
    asm volatile("mma.sync.aligned.m16n8k16.row.col.f32.f16.f16.f32 "
                 "{%0,%1,%2,%3}, {%4,%5,%6,%7}, {%8,%9}, {%0,%1,%2,%3};\n"
                 : "+f"(c[0]), "+f"(c[1]), "+f"(c[2]), "+f"(c[3])
                 : "r"(a[0]), "r"(a[1]), "r"(a[2]), "r"(a[3]), "r"(b0), "r"(b1));
}
__device__ __forceinline__ unsigned short hfbits(float f) {
    __half h = __float2half_rn(f);
    return *reinterpret_cast<unsigned short*>(&h);
}
__device__ __forceinline__ unsigned int pk2h(float a, float b) {
    return (unsigned int)hfbits(a) | ((unsigned int)hfbits(b) << 16);
}

// ---------------- one-pass conversion + rope table ----------------------------
__global__ __launch_bounds__(256)
void conv_all(const float* __restrict__ x,  const float* __restrict__ wq,
              const float* __restrict__ wk, const float* __restrict__ wv,
              const float* __restrict__ wo)
{
    const int NX4 = MROWS*DIMN/4;       // 1<<20
    const int NW4 = DIMN*DIMN/4;        // 1<<18
    const int NCV = NX4 + 4*NW4;
    int i = blockIdx.x * blockDim.x + threadIdx.x;
    if (i < NCV) {
        const float* src; ushort4* dst; int off;
        if (i < NX4) {
            src = x; off = i;
            dst = reinterpret_cast<ushort4*>(g_x16);
        } else {
            int j = i - NX4;
            int w = j >> 18;
            off = j & (NW4 - 1);
            src = (w == 0) ? wq : (w == 1) ? wk : (w == 2) ? wv : wo;
            dst = reinterpret_cast<ushort4*>(&g_w16[w][0]);
        }
        float4 v = reinterpret_cast<const float4*>(src)[off];
        dst[off] = make_ushort4(hfbits(v.x), hfbits(v.y), hfbits(v.z), hfbits(v.w));
    } else {
        int idx = i - NCV;
        if (idx < SEQ*32) {
            int d2 = idx & 31, s = idx >> 5;
            float inv = exp2f(-(float)d2 * 0.41524101186091403f);  // log2(10000)/32
            float ang = (float)s * inv;
            g_rope[idx] = make_float2(cosf(ang), sinf(ang));
        }
    }
}

// ---------------- fp16 GEMM: C = A @ W^T --------------------------------------
// mode 0: fp32 C[M,DIMN]; 1: V scatter -> g_v16 [B,H,S,hd];
// mode 2: Q rope (x0.125) -> g_q16;  3: K rope -> g_k16
#define SSTR 132

__device__ __forceinline__ void gemm_f16_body(const __half* __restrict__ A,
                                              const __half* __restrict__ W,
                                              float* __restrict__ C, int mode)
{
    extern __shared__ __align__(16) char gsm[];
    __half* sAb = reinterpret_cast<__half*>(gsm);          // [2][128][16]
    __half* sBb = reinterpret_cast<__half*>(gsm + 8192);   // [2][128][16]
    float*  stage = reinterpret_cast<float*>(gsm);         // reused post-pipeline

    const int tid   = threadIdx.x;
    const int lane  = tid & 31;
    const int warp  = tid >> 5;
    const int wm    = warp >> 2;
    const int wn    = warp & 3;
    const int row0  = blockIdx.y * 128;
    const int col0  = blockIdx.x * 128;

    const int lrow = tid >> 1;
    const int lch  = tid & 1;
    const int lpc  = lch ^ ((lrow >> 2) & 1);
    const size_t aoff = (size_t)(row0 + lrow) * DIMN + lch * 8;
    const size_t boff = (size_t)(col0 + lrow) * DIMN + lch * 8;

    float acc[4][4][4];
#pragma unroll
    for (int i = 0; i < 4; i++)
#pragma unroll
        for (int j = 0; j < 4; j++)
#pragma unroll
            for (int k = 0; k < 4; k++) acc[i][j][k] = 0.0f;

    const unsigned int stg = 4096;

    unsigned int aAddr[4], bAddr[2];
#pragma unroll
    for (int mt = 0; mt < 4; mt++) {
        int r  = wm * 64 + mt * 16 + (lane & 15);
        int ch = lane >> 4;
        int pc = ch ^ ((r >> 2) & 1);
        aAddr[mt] = smem_u32(sAb + r * 16 + pc * 8);
    }
#pragma unroll
    for (int p = 0; p < 2; p++) {
        int grp = lane >> 3;
        int r   = wn * 32 + p * 16 + (grp >> 1) * 8 + (lane & 7);
        int ch  = grp & 1;
        int pc  = ch ^ ((r >> 2) & 1);
        bAddr[p] = smem_u32(sBb + r * 16 + pc * 8);
    }

    {
        cp16(smem_u32(sAb + lrow * 16 + lpc * 8), A + aoff);
        cp16(smem_u32(sBb + lrow * 16 + lpc * 8), W + boff);
        cp_commit();
    }

    const int KT = DIMN / 16;
    for (int kt = 0; kt < KT; kt++) {
        int cur = kt & 1;
        if (kt + 1 < KT) {
            int nxt = (kt + 1) & 1;
            size_t ko = (size_t)(kt + 1) * 16;
            cp16(smem_u32(sAb + nxt * 2048 + lrow * 16 + lpc * 8), A + aoff + ko);
            cp16(smem_u32(sBb + nxt * 2048 + lrow * 16 + lpc * 8), W + boff + ko);
        }
        cp_commit();
        cp_wait1();
        __syncthreads();

        unsigned int coff = cur * stg;
        unsigned int ah[4][4], bf[2][4];
#pragma unroll
        for (int mt = 0; mt < 4; mt++)
            ldmx4(aAddr[mt] + coff, ah[mt][0], ah[mt][1], ah[mt][2], ah[mt][3]);
#pragma unroll
        for (int p = 0; p < 2; p++)
            ldmx4(bAddr[p] + coff, bf[p][0], bf[p][1], bf[p][2], bf[p][3]);
#pragma unroll
        for (int mt = 0; mt < 4; mt++) {
#pragma unroll
            for (int nt = 0; nt < 4; nt++) {
                int p = nt >> 1, s = nt & 1;
                mma16816h(acc[mt][nt], ah[mt], bf[p][2*s], bf[p][2*s+1]);
            }
        }
        __syncthreads();
    }

    if (mode == 0) {
#pragma unroll
        for (int mt = 0; mt < 4; mt++) {
            int r = row0 + wm * 64 + mt * 16 + (lane >> 2);
#pragma unroll
            for (int nt = 0; nt < 4; nt++) {
                int c = col0 + wn * 32 + nt * 8 + (lane & 3) * 2;
                *reinterpret_cast<float2*>(&C[(size_t)r * DIMN + c]) =
                    make_float2(acc[mt][nt][0], acc[mt][nt][1]);
                *reinterpret_cast<float2*>(&C[(size_t)(r + 8) * DIMN + c]) =
                    make_float2(acc[mt][nt][2], acc[mt][nt][3]);
            }
        }
    } else if (mode == 1) {
#pragma unroll
        for (int mt = 0; mt < 4; mt++) {
            int r = row0 + wm * 64 + mt * 16 + (lane >> 2);
#pragma unroll
            for (int nt = 0; nt < 4; nt++) {
                int c = col0 + wn * 32 + nt * 8 + (lane & 3) * 2;
#pragma unroll
                for (int e = 0; e < 4; e++) {
                    int rr = r + (e >> 1) * 8;
                    int cc = c + (e & 1);
                    int b = rr >> 11, s = rr & (SEQ-1);
                    int h = cc >> 6,  d = cc & (HD-1);
                    size_t di = (((size_t)(b*NH + h))*SEQ + s)*HD + d;
                    reinterpret_cast<unsigned short*>(g_v16)[di] = hfbits(acc[mt][nt][e]);
                }
            }
        }
    } else {
        // Q/K: stage fp32 tile, apply RoPE, write fp16 transposed
#pragma unroll
        for (int mt = 0; mt < 4; mt++) {
            int r = wm * 64 + mt * 16 + (lane >> 2);
#pragma unroll
            for (int nt = 0; nt < 4; nt++) {
                int c = wn * 32 + nt * 8 + (lane & 3) * 2;
                stage[r*SSTR + c]       = acc[mt][nt][0];
                stage[r*SSTR + c + 1]   = acc[mt][nt][1];
                stage[(r+8)*SSTR + c]   = acc[mt][nt][2];
                stage[(r+8)*SSTR + c+1] = acc[mt][nt][3];
            }
        }
        __syncthreads();

        const float qs = (mode == 2) ? 0.125f : 1.0f;
        __half* dstg = (mode == 2) ? g_q16 : g_k16;
        unsigned short* dp = reinterpret_cast<unsigned short*>(dstg);
#pragma unroll 4
        for (int i = 0; i < 64; i++) {
            int idx = i * 256 + tid;
            int r = idx >> 7, c = idx & 127;
            int sg = row0 + r;
            int b = sg >> 11, s = sg & (SEQ-1);
            int cg = col0 + c;
            int h = cg >> 6, d = cg & (HD-1);
            float2 cs = g_rope[s*32 + (d & 31)];
            float a = stage[r*SSTR + c];
            float p = stage[r*SSTR + (c ^ 32)];
            float out = (d < 32) ? (a*cs.x - p*cs.y) : (a*cs.x + p*cs.y);
            out *= qs;
            size_t di = (((size_t)(b*NH + h))*SEQ + s)*HD + d;
            dp[di] = hfbits(out);
        }
    }
}

__global__ __launch_bounds__(256)
void qkv_gemm_f16(const __half* __restrict__ x16)
{
    int z = blockIdx.z;
    if (z == 0)      gemm_f16_body(x16, g_w16[0], nullptr, 2);   // Q + rope
    else if (z == 1) gemm_f16_body(x16, g_w16[1], nullptr, 3);   // K + rope
    else             gemm_f16_body(x16, g_w16[2], nullptr, 1);   // V
}

__global__ __launch_bounds__(256)
void out_gemm_f16(float* __restrict__ C)
{
    gemm_f16_body(g_att16, g_w16[3], C, 0);
}

// ---------------- Flash attention (causal): BQ=128, 8 warps, fp16 MMA -------
// Q pre-scaled by 0.125, so no score scaling here.
#define FROWP 72

__device__ __forceinline__ int STI(int st, int r) {
    return (st*64 + r) * FROWP;
}

__global__ __launch_bounds__(256)
void flash_attn_mma()
{
    const int iq = (int)gridDim.x - 1 - (int)blockIdx.x;   // heavy tiles first
    const int h = blockIdx.y, b = blockIdx.z;
    const int q0 = iq * 128;
    const int tid = threadIdx.x, lane = tid & 31, warp = tid >> 5;
    const float LOG2E = 1.4426950408889634f;

    extern __shared__ __align__(16) __half fsm[];
    __half* sK = fsm;                       // 2 stages x 64 x 72 (rows 0..127 contiguous)
    __half* sV = fsm + 2*64*FROWP;

    const size_t bh = (size_t)(b*NH + h) * SEQ * HD;
    const __half* Qv = g_q16 + bh + (size_t)q0*HD;
    const __half* Kv = g_k16 + bh;
    const __half* Vv = g_v16 + bh;

    // ---- stage full Q (128 rows) across sK rows 0..127 ----
#pragma unroll
    for (int i = 0; i < 4; i++) {
        int id = tid + i * 256;
        int row = id >> 3, ch = id & 7;
        cp16(smem_u32(&sK[row*FROWP + ch*8]), Qv + row*HD + ch*8);
    }
    cp_commit(); cp_wait0();
    __syncthreads();

    unsigned int qf[4][4];
    {
        int r  = warp*16 + (lane & 15);
        int ch = (lane >> 4) * 8;
#pragma unroll
        for (int ks = 0; ks < 4; ks++)
            ldmx4(smem_u32(&sK[r*FROWP + ch + ks*16]),
                  qf[ks][0], qf[ks][1], qf[ks][2], qf[ks][3]);
    }
    __syncthreads();

    float oacc[8][4];
#pragma unroll
    for (int i = 0; i < 8; i++)
#pragma unroll
        for (int j = 0; j < 4; j++) oacc[i][j] = 0.0f;
    float m0 = -INFINITY, m1 = -INFINITY, l0 = 0.0f, l1 = 0.0f;  // l: per-thread partial

    const int nkv = 2 * (iq + 1);
    const int wbase = q0 + warp * 16;

    // prologue: KV tile 0 -> stage 0 (2 K chunks + 2 V chunks per thread)
#pragma unroll
    for (int i = 0; i < 2; i++) {
        int id = tid + i * 256;
        int row = id >> 3, ch = id & 7;
        cp16(smem_u32(&sK[STI(0,row) + ch*8]), Kv + row*HD + ch*8);
        cp16(smem_u32(&sV[STI(0,row) + ch*8]), Vv + row*HD + ch*8);
    }
    cp_commit();

    for (int t = 0; t < nkv; t++) {
        const int st = t & 1;
        if (t + 1 < nkv) {
            const int ns = (t + 1) & 1;
            const size_t go = (size_t)(t + 1) * 64 * HD;
#pragma unroll
            for (int i = 0; i < 2; i++) {
                int id = tid + i * 256;
                int row = id >> 3, ch = id & 7;
                cp16(smem_u32(&sK[STI(ns,row) + ch*8]), Kv + go + row*HD + ch*8);
                cp16(smem_u32(&sV[STI(ns,row) + ch*8]), Vv + go + row*HD + ch*8);
            }
        }
        cp_commit();
        cp_wait1();
        __syncthreads();

        // warp-level causal skip: tile entirely above this warp's rows
        if (t * 64 <= wbase + 15) {
            // S = Q K^T (fp16)
            float sacc[8][4];
#pragma unroll
            for (int i = 0; i < 8; i++)
#pragma unroll
                for (int j = 0; j < 4; j++) sacc[i][j] = 0.0f;

            {
                const int grp = lane >> 3;
                const int rb  = (grp >> 1) * 8 + (lane & 7);
                const int cb  = (grp & 1) * 8;
#pragma unroll
                for (int ks = 0; ks < 4; ks++) {
#pragma unroll
                    for (int p = 0; p < 4; p++) {
                        unsigned int kf[4];
                        ldmx4(smem_u32(&sK[STI(st,p*16+rb) + cb + ks*16]),
                              kf[0], kf[1], kf[2], kf[3]);
#pragma unroll
                        for (int s = 0; s < 2; s++)
                            mma16816h(sacc[2*p+s], qf[ks], kf[2*s], kf[2*s+1]);
                    }
                }
            }

            const int quad = lane >> 2;
            const int cpair = (lane & 3) * 2;
            if (t * 64 + 63 > wbase) {     // diagonal-overlapping tile: mask
                const int r0 = wbase + quad;
                const int kvb = t*64 + cpair;
#pragma unroll
                for (int nt = 0; nt < 8; nt++) {
#pragma unroll
                    for (int j = 0; j < 2; j++) {
                        int kg = kvb + nt*8 + j;
                        if (kg > r0)     sacc[nt][j]   = -INFINITY;
                        if (kg > r0 + 8) sacc[nt][2+j] = -INFINITY;
                    }
                }
            }

            // online softmax (max shuffles only; l kept per-thread partial)
            float mx0 = -INFINITY, mx1 = -INFINITY;
#pragma unroll
            for (int nt = 0; nt < 8; nt++) {
                mx0 = fmaxf(mx0, fmaxf(sacc[nt][0], sacc[nt][1]));
                mx1 = fmaxf(mx1, fmaxf(sacc[nt][2], sacc[nt][3]));
            }
            mx0 = fmaxf(mx0, __shfl_xor_sync(0xffffffffu, mx0, 1));
            mx0 = fmaxf(mx0, __shfl_xor_sync(0xffffffffu, mx0, 2));
            mx1 = fmaxf(mx1, __shfl_xor_sync(0xffffffffu, mx1, 1));
            mx1 = fmaxf(mx1, __shfl_xor_sync(0xffffffffu, mx1, 2));

            float mn0 = fmaxf(m0, mx0), mn1 = fmaxf(m1, mx1);
            float a0 = exp2f((m0 - mn0) * LOG2E);
            float a1 = exp2f((m1 - mn1) * LOG2E);
            m0 = mn0; m1 = mn1;

            float s0 = 0.0f, s1 = 0.0f;
#pragma unroll
            for (int nt = 0; nt < 8; nt++) {
                float p0 = exp2f((sacc[nt][0] - mn0) * LOG2E);
                float p1 = exp2f((sacc[nt][1] - mn0) * LOG2E);
                float p2 = exp2f((sacc[nt][2] - mn1) * LOG2E);
                float p3 = exp2f((sacc[nt][3] - mn1) * LOG2E);
                sacc[nt][0] = p0; sacc[nt][1] = p1; sacc[nt][2] = p2; sacc[nt][3] = p3;
                s0 += p0 + p1; s1 += p2 + p3;
            }
            l0 = l0 * a0 + s0;
            l1 = l1 * a1 + s1;

#pragma unroll
            for (int nt = 0; nt < 8; nt++) {
                oacc[nt][0] *= a0; oacc[nt][1] *= a0;
                oacc[nt][2] *= a1; oacc[nt][3] *= a1;
            }

            unsigned int pf[4][4];
#pragma unroll
            for (int ks = 0; ks < 4; ks++) {
#pragma unroll
                for (int half = 0; half < 2; half++) {
                    pf[ks][half]   = pk2h(sacc[2*ks][2*half],   sacc[2*ks][2*half+1]);
                    pf[ks][2+half] = pk2h(sacc[2*ks+1][2*half], sacc[2*ks+1][2*half+1]);
                }
            }

            // O += P V (fp16)
            {
                const int g   = lane >> 3;
                const int kvr = (g & 1) * 8 + (lane & 7);
                const int dcb = (g >> 1) * 8;
#pragma unroll
                for (int dt = 0; dt < 4; dt++) {
#pragma unroll
                    for (int ks = 0; ks < 4; ks++) {
                        unsigned int vf[4];
                        ldmx4t(smem_u32(&sV[STI(st,ks*16+kvr) + dt*16 + dcb]),
                               vf[0], vf[1], vf[2], vf[3]);
#pragma unroll
                        for (int s = 0; s < 2; s++)
                            mma16816h(oacc[2*dt+s], pf[ks], vf[2*s], vf[2*s+1]);
                    }
                }
            }
        }
        __syncthreads();
    }

    // epilogue: reduce l across quad threads, then O/l -> g_att16 at [B,S,D]
    {
        l0 += __shfl_xor_sync(0xffffffffu, l0, 1);
        l0 += __shfl_xor_sync(0xffffffffu, l0, 2);
        l1 += __shfl_xor_sync(0xffffffffu, l1, 1);
        l1 += __shfl_xor_sync(0xffffffffu, l1, 2);

        const int quad = lane >> 2;
        const int cpair = (lane & 3) * 2;
        float il0 = 1.0f / l0, il1 = 1.0f / l1;
        int r0 = wbase + quad;
        unsigned short* AO = reinterpret_cast<unsigned short*>(g_att16);
#pragma unroll
        for (int nt = 0; nt < 8; nt++) {
            int d = nt*8 + cpair;
            size_t i0 = ((size_t)(b*SEQ) + r0)     * DIMN + h*HD + d;
            size_t i1 = ((size_t)(b*SEQ) + r0 + 8) * DIMN + h*HD + d;
            *reinterpret_cast<unsigned int*>(&AO[i0]) =
                pk2h(oacc[nt][0]*il0, oacc[nt][1]*il0);
            *reinterpret_cast<unsigned int*>(&AO[i1]) =
                pk2h(oacc[nt][2]*il1, oacc[nt][3]*il1);
        }
    }
}

// ---------------- launch ----------------------------------------------------
extern "C" void kernel_launch(void* const* d_in, const int* in_sizes, int n_in,
                              void* d_out, int out_size)
{
    const float* x  = (const float*)d_in[0];
    const float* Wq = (const float*)d_in[1];
    const float* Wk = (const float*)d_in[2];
    const float* Wv = (const float*)d_in[3];
    const float* Wo = (const float*)d_in[4];
    float* out = (float*)d_out;

    __half* x16;
    cudaGetSymbolAddress((void**)&x16, g_x16);

    const int NTOT4 = (MROWS*DIMN + 4*DIMN*DIMN) / 4 + SEQ*32;   // conv + rope
    conv_all<<<(NTOT4 + 255)/256, 256>>>(x, Wq, Wk, Wv, Wo);

    const int QKV_SMEM = 128 * SSTR * 4;   // 67584
    cudaFuncSetAttribute(qkv_gemm_f16, cudaFuncAttributeMaxDynamicSharedMemorySize, QKV_SMEM);
    dim3 gqkv(DIMN/128, MROWS/128, 3);
    qkv_gemm_f16<<<gqkv, 256, QKV_SMEM>>>(x16);

    const int FSM_BYTES = (2*64*FROWP + 2*64*FROWP) * 2;   // 36864
    cudaFuncSetAttribute(flash_attn_mma, cudaFuncAttributeMaxDynamicSharedMemorySize, FSM_BYTES);
    dim3 gfl(SEQ/128, NH, BATCH);
    flash_attn_mma<<<gfl, 256, FSM_BYTES>>>();

    dim3 gout(DIMN/128, MROWS/128);
    out_gemm_f16<<<gout, 256, 16384>>>(out);
}

// round 12
// speedup vs baseline: 2.6065x; 1.0069x over previous
#include <cuda_runtime.h>
#include <cuda_fp16.h>
#include <math.h>

#define DIMN  1024
#define NH    16
#define HD    64
#define BATCH 2
#define SEQ   2048
#define MROWS (BATCH*SEQ)   // 4096

// ---------------- scratch (device globals; no allocations allowed) ----------
__device__ __half g_x16[MROWS*DIMN];
__device__ __half g_w16[4][DIMN*DIMN];     // Wq, Wk, Wv, Wo
__device__ float2 g_rope[SEQ*32];          // (cos, sin) per (s, d2)

// attention operands, [B,H,S,hd], fp16
__device__ __half g_q16 [MROWS*DIMN];      // pre-scaled by 0.125
__device__ __half g_k16 [MROWS*DIMN];
__device__ __half g_v16 [MROWS*DIMN];
__device__ __half g_att16[MROWS*DIMN];     // attention out, [B,S,D], fp16

// ---------------- helpers ----------------------------------------------------
__device__ __forceinline__ unsigned int smem_u32(const void* p) {
    return (unsigned int)__cvta_generic_to_shared(p);
}
__device__ __forceinline__ void cp16(unsigned int s, const void* g) {
    asm volatile("cp.async.cg.shared.global [%0], [%1], 16;\n" :: "r"(s), "l"(g));
}
__device__ __forceinline__ void cp_commit() {
    asm volatile("cp.async.commit_group;\n");
}
__device__ __forceinline__ void cp_wait2() {
    asm volatile("cp.async.wait_group 2;\n");
}
__device__ __forceinline__ void cp_wait0() {
    asm volatile("cp.async.wait_group 0;\n");
}
__device__ __forceinline__ void ldmx4(unsigned int addr, unsigned int& r0, unsigned int& r1,
                                      unsigned int& r2, unsigned int& r3) {
    asm volatile("ldmatrix.sync.aligned.m8n8.x4.shared.b16 {%0,%1,%2,%3}, [%4];\n"
                 : "=r"(r0), "=r"(r1), "=r"(r2), "=r"(r3) : "r"(addr));
}
__device__ __forceinline__ void ldmx4t(unsigned int addr, unsigned int& r0, unsigned int& r1,
                                       unsigned int& r2, unsigned int& r3) {
    asm volatile("ldmatrix.sync.aligned.m8n8.x4.trans.shared.b16 {%0,%1,%2,%3}, [%4];\n"
                 : "=r"(r0), "=r"(r1), "=r"(r2), "=r"(r3) : "r"(addr));
}
__device__ __forceinline__ void mma16816h(float* c, const unsigned int* a,
                                          unsigned int b0, unsigned int b1) {
    asm volatile("mma.sync.aligned.m16n8k16.row.col.f32.f16.f16.f32 "
                 "{%0,%1,%2,%3}, {%4,%5,%6,%7}, {%8,%9}, {%0,%1,%2,%3};\n"
                 : "+f"(c[0]), "+f"(c[1]), "+f"(c[2]), "+f"(c[3])
                 : "r"(a[0]), "r"(a[1]), "r"(a[2]), "r"(a[3]), "r"(b0), "r"(b1));
}
__device__ __forceinline__ unsigned short hfbits(float f) {
    __half h = __float2half_rn(f);
    return *reinterpret_cast<unsigned short*>(&h);
}
__device__ __forceinline__ unsigned int pk2h(float a, float b) {
    return (unsigned int)hfbits(a) | ((unsigned int)hfbits(b) << 16);
}

// ---------------- one-pass conversion + rope table ----------------------------
__global__ __launch_bounds__(256)
void conv_all(const float* __restrict__ x,  const float* __restrict__ wq,
              const float* __restrict__ wk, const float* __restrict__ wv,
              const float* __restrict__ wo)
{
    const int NX4 = MROWS*DIMN/4;
    const int NW4 = DIMN*DIMN/4;
    const int NCV = NX4 + 4*NW4;
    int i = blockIdx.x * blockDim.x + threadIdx.x;
    if (i < NCV) {
        const float* src; ushort4* dst; int off;
        if (i < NX4) {
            src = x; off = i;
            dst = reinterpret_cast<ushort4*>(g_x16);
        } else {
            int j = i - NX4;
            int w = j >> 18;
            off = j & (NW4 - 1);
            src = (w == 0) ? wq : (w == 1) ? wk : (w == 2) ? wv : wo;
            dst = reinterpret_cast<ushort4*>(&g_w16[w][0]);
        }
        float4 v = reinterpret_cast<const float4*>(src)[off];
        dst[off] = make_ushort4(hfbits(v.x), hfbits(v.y), hfbits(v.z), hfbits(v.w));
    } else {
        int idx = i - NCV;
        if (idx < SEQ*32) {
            int d2 = idx & 31, s = idx >> 5;
            float inv = exp2f(-(float)d2 * 0.41524101186091403f);
            float ang = (float)s * inv;
            g_rope[idx] = make_float2(cosf(ang), sinf(ang));
        }
    }
}

// ---------------- fp16 GEMM: C = A @ W^T --------------------------------------
// BK=32, 4-stage cp.async, ONE syncthreads per K-iteration.
// smem: A 4 stages x 8KB at +0; B 4 stages x 8KB at +32768. (64KB)
// mode 0: fp32 C; 1: V scatter -> g_v16; 2: Q rope (x0.125); 3: K rope
#define SSTR 132
#define GKT  32

__device__ __forceinline__ void gemm_f16_body(const __half* __restrict__ A,
                                              const __half* __restrict__ W,
                                              float* __restrict__ C, int mode)
{
    extern __shared__ __align__(16) char gsm[];
    __half* sA = reinterpret_cast<__half*>(gsm);
    __half* sB = reinterpret_cast<__half*>(gsm + 32768);
    float*  stage = reinterpret_cast<float*>(gsm);   // reused post-pipeline (modes 2/3)

    const int tid   = threadIdx.x;
    const int lane  = tid & 31;
    const int warp  = tid >> 5;
    const int wm    = warp >> 2;
    const int wn    = warp & 3;
    const int row0  = blockIdx.y * 128;
    const int col0  = blockIdx.x * 128;

    const int lrow = tid >> 1;
    const int lch  = tid & 1;
    const int lpc  = lch ^ ((lrow >> 2) & 1);
    const __half* Ap = A + (size_t)(row0 + lrow) * DIMN + lch * 8;
    const __half* Wp = W + (size_t)(col0 + lrow) * DIMN + lch * 8;
    const unsigned int aLd = smem_u32(sA + lrow * 16 + lpc * 8);
    const unsigned int bLd = smem_u32(sB + lrow * 16 + lpc * 8);

    float acc[4][4][4];
#pragma unroll
    for (int i = 0; i < 4; i++)
#pragma unroll
        for (int j = 0; j < 4; j++)
#pragma unroll
            for (int k = 0; k < 4; k++) acc[i][j][k] = 0.0f;

    unsigned int aAddr[4], bAddr[2];
#pragma unroll
    for (int mt = 0; mt < 4; mt++) {
        int r  = wm * 64 + mt * 16 + (lane & 15);
        int ch = lane >> 4;
        int pc = ch ^ ((r >> 2) & 1);
        aAddr[mt] = smem_u32(sA + r * 16 + pc * 8);
    }
#pragma unroll
    for (int p = 0; p < 2; p++) {
        int grp = lane >> 3;
        int r   = wn * 32 + p * 16 + (grp >> 1) * 8 + (lane & 7);
        int ch  = grp & 1;
        int pc  = ch ^ ((r >> 2) & 1);
        bAddr[p] = smem_u32(sB + r * 16 + pc * 8);
    }

    // stage load: chunk kb (BK=32) into stage s
    auto load_stage = [&](int kb, int s) {
        const __half* a = Ap + kb * 32;
        const __half* w = Wp + kb * 32;
#pragma unroll
        for (int sub = 0; sub < 2; sub++) {
            unsigned int so = s * 8192 + sub * 4096;
            cp16(aLd + so, a + sub * 16);
            cp16(bLd + so, w + sub * 16);
        }
    };

    load_stage(0, 0); cp_commit();
    load_stage(1, 1); cp_commit();

    for (int kt = 0; kt < GKT; kt++) {
        if (kt + 2 < GKT) load_stage(kt + 2, (kt + 2) & 3);
        cp_commit();
        cp_wait2();
        __syncthreads();

#pragma unroll
        for (int sub = 0; sub < 2; sub++) {
            unsigned int coff = (unsigned)((kt & 3) * 8192 + sub * 4096);
            unsigned int ah[4][4], bf[2][4];
#pragma unroll
            for (int mt = 0; mt < 4; mt++)
                ldmx4(aAddr[mt] + coff, ah[mt][0], ah[mt][1], ah[mt][2], ah[mt][3]);
#pragma unroll
            for (int p = 0; p < 2; p++)
                ldmx4(bAddr[p] + coff, bf[p][0], bf[p][1], bf[p][2], bf[p][3]);
#pragma unroll
            for (int mt = 0; mt < 4; mt++) {
#pragma unroll
                for (int nt = 0; nt < 4; nt++) {
                    int p = nt >> 1, s = nt & 1;
                    mma16816h(acc[mt][nt], ah[mt], bf[p][2*s], bf[p][2*s+1]);
                }
            }
        }
    }

    if (mode == 0) {
#pragma unroll
        for (int mt = 0; mt < 4; mt++) {
            int r = row0 + wm * 64 + mt * 16 + (lane >> 2);
#pragma unroll
            for (int nt = 0; nt < 4; nt++) {
                int c = col0 + wn * 32 + nt * 8 + (lane & 3) * 2;
                *reinterpret_cast<float2*>(&C[(size_t)r * DIMN + c]) =
                    make_float2(acc[mt][nt][0], acc[mt][nt][1]);
                *reinterpret_cast<float2*>(&C[(size_t)(r + 8) * DIMN + c]) =
                    make_float2(acc[mt][nt][2], acc[mt][nt][3]);
            }
        }
    } else if (mode == 1) {
#pragma unroll
        for (int mt = 0; mt < 4; mt++) {
            int r = row0 + wm * 64 + mt * 16 + (lane >> 2);
#pragma unroll
            for (int nt = 0; nt < 4; nt++) {
                int c = col0 + wn * 32 + nt * 8 + (lane & 3) * 2;
#pragma unroll
                for (int e = 0; e < 4; e++) {
                    int rr = r + (e >> 1) * 8;
                    int cc = c + (e & 1);
                    int b = rr >> 11, s = rr & (SEQ-1);
                    int h = cc >> 6,  d = cc & (HD-1);
                    size_t di = (((size_t)(b*NH + h))*SEQ + s)*HD + d;
                    reinterpret_cast<unsigned short*>(g_v16)[di] = hfbits(acc[mt][nt][e]);
                }
            }
        }
    } else {
        __syncthreads();   // all MMA smem reads complete before fp32 stage reuse
#pragma unroll
        for (int mt = 0; mt < 4; mt++) {
            int r = wm * 64 + mt * 16 + (lane >> 2);
#pragma unroll
            for (int nt = 0; nt < 4; nt++) {
                int c = wn * 32 + nt * 8 + (lane & 3) * 2;
                stage[r*SSTR + c]       = acc[mt][nt][0];
                stage[r*SSTR + c + 1]   = acc[mt][nt][1];
                stage[(r+8)*SSTR + c]   = acc[mt][nt][2];
                stage[(r+8)*SSTR + c+1] = acc[mt][nt][3];
            }
        }
        __syncthreads();

        const float qs = (mode == 2) ? 0.125f : 1.0f;
        __half* dstg = (mode == 2) ? g_q16 : g_k16;
        unsigned short* dp = reinterpret_cast<unsigned short*>(dstg);
#pragma unroll 4
        for (int i = 0; i < 64; i++) {
            int idx = i * 256 + tid;
            int r = idx >> 7, c = idx & 127;
            int sg = row0 + r;
            int b = sg >> 11, s = sg & (SEQ-1);
            int cg = col0 + c;
            int h = cg >> 6, d = cg & (HD-1);
            float2 cs = g_rope[s*32 + (d & 31)];
            float a = stage[r*SSTR + c];
            float p = stage[r*SSTR + (c ^ 32)];
            float out = (d < 32) ? (a*cs.x - p*cs.y) : (a*cs.x + p*cs.y);
            out *= qs;
            size_t di = (((size_t)(b*NH + h))*SEQ + s)*HD + d;
            dp[di] = hfbits(out);
        }
    }
}

__global__ __launch_bounds__(256)
void qkv_gemm_f16(const __half* __restrict__ x16)
{
    int z = blockIdx.z;
    if (z == 0)      gemm_f16_body(x16, g_w16[0], nullptr, 2);   // Q + rope
    else if (z == 1) gemm_f16_body(x16, g_w16[1], nullptr, 3);   // K + rope
    else             gemm_f16_body(x16, g_w16[2], nullptr, 1);   // V
}

__global__ __launch_bounds__(256)
void out_gemm_f16(float* __restrict__ C)
{
    gemm_f16_body(g_att16, g_w16[3], C, 0);
}

// ---------------- Flash attention (causal): BQ=128, 4-stage, 1 sync/tile ----
#define FROWP 72

__device__ __forceinline__ int STI(int st, int r) {
    return (st*64 + r) * FROWP;
}

__global__ __launch_bounds__(256)
void flash_attn_mma()
{
    const int iq = (int)gridDim.x - 1 - (int)blockIdx.x;   // heavy tiles first
    const int h = blockIdx.y, b = blockIdx.z;
    const int q0 = iq * 128;
    const int tid = threadIdx.x, lane = tid & 31, warp = tid >> 5;
    const float LOG2E = 1.4426950408889634f;

    extern __shared__ __align__(16) __half fsm[];
    __half* sK = fsm;                       // 4 stages x 64 x 72
    __half* sV = fsm + 4*64*FROWP;

    const size_t bh = (size_t)(b*NH + h) * SEQ * HD;
    const __half* Qv = g_q16 + bh + (size_t)q0*HD;
    const __half* Kv = g_k16 + bh;
    const __half* Vv = g_v16 + bh;

    // ---- stage full Q (128 rows) across sK stage0+1 region ----
#pragma unroll
    for (int i = 0; i < 4; i++) {
        int id = tid + i * 256;
        int row = id >> 3, ch = id & 7;
        cp16(smem_u32(&sK[row*FROWP + ch*8]), Qv + row*HD + ch*8);
    }
    cp_commit(); cp_wait0();
    __syncthreads();

    unsigned int qf[4][4];
    {
        int r  = warp*16 + (lane & 15);
        int ch = (lane >> 4) * 8;
#pragma unroll
        for (int ks = 0; ks < 4; ks++)
            ldmx4(smem_u32(&sK[r*FROWP + ch + ks*16]),
                  qf[ks][0], qf[ks][1], qf[ks][2], qf[ks][3]);
    }
    __syncthreads();

    float oacc[8][4];
#pragma unroll
    for (int i = 0; i < 8; i++)
#pragma unroll
        for (int j = 0; j < 4; j++) oacc[i][j] = 0.0f;
    float m0 = -INFINITY, m1 = -INFINITY, l0 = 0.0f, l1 = 0.0f;

    const int nkv = 2 * (iq + 1);
    const int wbase = q0 + warp * 16;

    auto load_tile = [&](int t, int s) {
        const size_t go = (size_t)t * 64 * HD;
#pragma unroll
        for (int i = 0; i < 2; i++) {
            int id = tid + i * 256;
            int row = id >> 3, ch = id & 7;
            cp16(smem_u32(&sK[STI(s,row) + ch*8]), Kv + go + row*HD + ch*8);
            cp16(smem_u32(&sV[STI(s,row) + ch*8]), Vv + go + row*HD + ch*8);
        }
    };

    load_tile(0, 0); cp_commit();
    load_tile(1, 1); cp_commit();   // nkv >= 2 always

    for (int t = 0; t < nkv; t++) {
        if (t + 2 < nkv) load_tile(t + 2, (t + 2) & 3);
        cp_commit();
        cp_wait2();
        __syncthreads();
        const int st = t & 3;

        if (t * 64 <= wbase + 15) {
            float sacc[8][4];
#pragma unroll
            for (int i = 0; i < 8; i++)
#pragma unroll
                for (int j = 0; j < 4; j++) sacc[i][j] = 0.0f;

            {
                const int grp = lane >> 3;
                const int rb  = (grp >> 1) * 8 + (lane & 7);
                const int cb  = (grp & 1) * 8;
#pragma unroll
                for (int ks = 0; ks < 4; ks++) {
#pragma unroll
                    for (int p = 0; p < 4; p++) {
                        unsigned int kf[4];
                        ldmx4(smem_u32(&sK[STI(st,p*16+rb) + cb + ks*16]),
                              kf[0], kf[1], kf[2], kf[3]);
#pragma unroll
                        for (int s = 0; s < 2; s++)
                            mma16816h(sacc[2*p+s], qf[ks], kf[2*s], kf[2*s+1]);
                    }
                }
            }

            const int quad = lane >> 2;
            const int cpair = (lane & 3) * 2;
            if (t * 64 + 63 > wbase) {
                const int r0 = wbase + quad;
                const int kvb = t*64 + cpair;
#pragma unroll
                for (int nt = 0; nt < 8; nt++) {
#pragma unroll
                    for (int j = 0; j < 2; j++) {
                        int kg = kvb + nt*8 + j;
                        if (kg > r0)     sacc[nt][j]   = -INFINITY;
                        if (kg > r0 + 8) sacc[nt][2+j] = -INFINITY;
                    }
                }
            }

            float mx0 = -INFINITY, mx1 = -INFINITY;
#pragma unroll
            for (int nt = 0; nt < 8; nt++) {
                mx0 = fmaxf(mx0, fmaxf(sacc[nt][0], sacc[nt][1]));
                mx1 = fmaxf(mx1, fmaxf(sacc[nt][2], sacc[nt][3]));
            }
            mx0 = fmaxf(mx0, __shfl_xor_sync(0xffffffffu, mx0, 1));
            mx0 = fmaxf(mx0, __shfl_xor_sync(0xffffffffu, mx0, 2));
            mx1 = fmaxf(mx1, __shfl_xor_sync(0xffffffffu, mx1, 1));
            mx1 = fmaxf(mx1, __shfl_xor_sync(0xffffffffu, mx1, 2));

            float mn0 = fmaxf(m0, mx0), mn1 = fmaxf(m1, mx1);
            float a0 = exp2f((m0 - mn0) * LOG2E);
            float a1 = exp2f((m1 - mn1) * LOG2E);
            m0 = mn0; m1 = mn1;

            float s0 = 0.0f, s1 = 0.0f;
#pragma unroll
            for (int nt = 0; nt < 8; nt++) {
                float p0 = exp2f((sacc[nt][0] - mn0) * LOG2E);
                float p1 = exp2f((sacc[nt][1] - mn0) * LOG2E);
                float p2 = exp2f((sacc[nt][2] - mn1) * LOG2E);
                float p3 = exp2f((sacc[nt][3] - mn1) * LOG2E);
                sacc[nt][0] = p0; sacc[nt][1] = p1; sacc[nt][2] = p2; sacc[nt][3] = p3;
                s0 += p0 + p1; s1 += p2 + p3;
            }
            l0 = l0 * a0 + s0;
            l1 = l1 * a1 + s1;

#pragma unroll
            for (int nt = 0; nt < 8; nt++) {
                oacc[nt][0] *= a0; oacc[nt][1] *= a0;
                oacc[nt][2] *= a1; oacc[nt][3] *= a1;
            }

            unsigned int pf[4][4];
#pragma unroll
            for (int ks = 0; ks < 4; ks++) {
#pragma unroll
                for (int half = 0; half < 2; half++) {
                    pf[ks][half]   = pk2h(sacc[2*ks][2*half],   sacc[2*ks][2*half+1]);
                    pf[ks][2+half] = pk2h(sacc[2*ks+1][2*half], sacc[2*ks+1][2*half+1]);
                }
            }

            {
                const int g   = lane >> 3;
                const int kvr = (g & 1) * 8 + (lane & 7);
                const int dcb = (g >> 1) * 8;
#pragma unroll
                for (int dt = 0; dt < 4; dt++) {
#pragma unroll
                    for (int ks = 0; ks < 4; ks++) {
                        unsigned int vf[4];
                        ldmx4t(smem_u32(&sV[STI(st,ks*16+kvr) + dt*16 + dcb]),
                               vf[0], vf[1], vf[2], vf[3]);
#pragma unroll
                        for (int s = 0; s < 2; s++)
                            mma16816h(oacc[2*dt+s], pf[ks], vf[2*s], vf[2*s+1]);
                    }
                }
            }
        }
    }

    // epilogue: quad-reduce l, then O/l -> g_att16 at [B,S,D]
    {
        l0 += __shfl_xor_sync(0xffffffffu, l0, 1);
        l0 += __shfl_xor_sync(0xffffffffu, l0, 2);
        l1 += __shfl_xor_sync(0xffffffffu, l1, 1);
        l1 += __shfl_xor_sync(0xffffffffu, l1, 2);

        const int quad = lane >> 2;
        const int cpair = (lane & 3) * 2;
        float il0 = 1.0f / l0, il1 = 1.0f / l1;
        int r0 = wbase + quad;
        unsigned short* AO = reinterpret_cast<unsigned short*>(g_att16);
#pragma unroll
        for (int nt = 0; nt < 8; nt++) {
            int d = nt*8 + cpair;
            size_t i0 = ((size_t)(b*SEQ) + r0)     * DIMN + h*HD + d;
            size_t i1 = ((size_t)(b*SEQ) + r0 + 8) * DIMN + h*HD + d;
            *reinterpret_cast<unsigned int*>(&AO[i0]) =
                pk2h(oacc[nt][0]*il0, oacc[nt][1]*il0);
            *reinterpret_cast<unsigned int*>(&AO[i1]) =
                pk2h(oacc[nt][2]*il1, oacc[nt][3]*il1);
        }
    }
}

// ---------------- launch ----------------------------------------------------
extern "C" void kernel_launch(void* const* d_in, const int* in_sizes, int n_in,
                              void* d_out, int out_size)
{
    const float* x  = (const float*)d_in[0];
    const float* Wq = (const float*)d_in[1];
    const float* Wk = (const float*)d_in[2];
    const float* Wv = (const float*)d_in[3];
    const float* Wo = (const float*)d_in[4];
    float* out = (float*)d_out;

    __half* x16;
    cudaGetSymbolAddress((void**)&x16, g_x16);

    const int NTOT4 = (MROWS*DIMN + 4*DIMN*DIMN) / 4 + SEQ*32;
    conv_all<<<(NTOT4 + 255)/256, 256>>>(x, Wq, Wk, Wv, Wo);

    const int QKV_SMEM = 128 * SSTR * 4;   // 67584 >= 65536 pipeline
    cudaFuncSetAttribute(qkv_gemm_f16, cudaFuncAttributeMaxDynamicSharedMemorySize, QKV_SMEM);
    dim3 gqkv(DIMN/128, MROWS/128, 3);
    qkv_gemm_f16<<<gqkv, 256, QKV_SMEM>>>(x16);

    const int FSM_BYTES = (4*64*FROWP + 4*64*FROWP) * 2;   // 73728
    cudaFuncSetAttribute(flash_attn_mma, cudaFuncAttributeMaxDynamicSharedMemorySize, FSM_BYTES);
    dim3 gfl(SEQ/128, NH, BATCH);
    flash_attn_mma<<<gfl, 256, FSM_BYTES>>>();

    const int OUT_SMEM = 65536;
    cudaFuncSetAttribute(out_gemm_f16, cudaFuncAttributeMaxDynamicSharedMemorySize, OUT_SMEM);
    dim3 gout(DIMN/128, MROWS/128);
    out_gemm_f16<<<gout, 256, OUT_SMEM>>>(out);
}